// round 2
// baseline (speedup 1.0000x reference)
#include <cuda_runtime.h>
#include <cuda_bf16.h>
#include <math.h>
#include <float.h>

// Problem dims
#define BBs   128          // b * nw
#define Ls    343          // window length
#define Es    256          // embedding dim
#define Hs    8            // heads
#define HDs   32           // head dim
#define HIDs  512          // CPB hidden
#define LLs   (Ls * Ls)    // 117649
#define ROWSs (BBs * Ls)   // 43904

// -------- scratch (device globals; no allocation allowed) --------
__device__ float g_q[BBs * Hs * Ls * HDs];     // (bb, h, l, hd)
__device__ float g_k[BBs * Hs * Ls * HDs];
__device__ float g_v[BBs * Hs * Ls * HDs];
__device__ float g_bias[Hs * LLs];             // (h, i, j)
__device__ float g_att[ROWSs * Es];            // (bb*l, h*hd)
__device__ int   g_mask_mode;                  // 0=uint8, 1=int32, 2=float32

// ============================================================
// Kernel 0: detect the on-device dtype of the bool mask buffer.
// bool(1.0f) word == 0x3F800000 only in float mode; a nonzero byte
// above byte-0 only in byte-packed mode; else int32.
// ============================================================
__global__ void detect_mask_kernel(const unsigned int* __restrict__ m)
{
    __shared__ int s_float, s_multi;
    if (threadIdx.x == 0) { s_float = 0; s_multi = 0; }
    __syncthreads();
    for (int i = threadIdx.x; i < 4096; i += 256) {
        unsigned int w = m[i];
        if (w == 0x3F800000u) atomicOr(&s_float, 1);
        else if (w != 0u && (w & 0xFFFFFF00u) != 0u) atomicOr(&s_multi, 1);
    }
    __syncthreads();
    if (threadIdx.x == 0)
        g_mask_mode = s_float ? 2 : (s_multi ? 0 : 1);
}

// ============================================================
// Kernel 1: continuous-position-bias table (window invariant).
// ============================================================
__global__ __launch_bounds__(256) void bias_kernel(
    const float* __restrict__ indices,  // (L, L, 3)
    const float* __restrict__ W1,       // (3, 512)
    const float* __restrict__ b1,       // (512)
    const float* __restrict__ W2,       // (512, 8)
    const float* __restrict__ b2)       // (8)
{
    __shared__ float sW1[3 * HIDs];
    __shared__ float sb1[HIDs];
    __shared__ float sW2[HIDs * Hs];
    for (int i = threadIdx.x; i < 3 * HIDs; i += 256) sW1[i] = W1[i];
    for (int i = threadIdx.x; i < HIDs;     i += 256) sb1[i] = b1[i];
    for (int i = threadIdx.x; i < HIDs * Hs; i += 256) sW2[i] = W2[i];
    __syncthreads();

    const int p0 = blockIdx.x * 1024 + threadIdx.x;
    float x[4][3];
    bool valid[4];
#pragma unroll
    for (int k = 0; k < 4; k++) {
        int p = p0 + k * 256;
        valid[k] = (p < LLs);
        int pp = valid[k] ? p : 0;
#pragma unroll
        for (int c = 0; c < 3; c++) {
            float xv = indices[pp * 3 + c];
            x[k][c] = copysignf(log2f(1.0f + fabsf(xv)) * (1.0f / 3.0f), xv);
        }
    }

    float acc[4][8];
#pragma unroll
    for (int k = 0; k < 4; k++)
#pragma unroll
        for (int h = 0; h < 8; h++) acc[k][h] = 0.0f;

    for (int t = 0; t < HIDs; t++) {
        float w0 = sW1[t], w1 = sW1[HIDs + t], w2 = sW1[2 * HIDs + t];
        float bb1 = sb1[t];
        float hv[4];
#pragma unroll
        for (int k = 0; k < 4; k++)
            hv[k] = fmaxf(fmaf(x[k][0], w0, fmaf(x[k][1], w1, fmaf(x[k][2], w2, bb1))), 0.0f);
#pragma unroll
        for (int h = 0; h < 8; h++) {
            float w = sW2[t * 8 + h];
#pragma unroll
            for (int k = 0; k < 4; k++) acc[k][h] = fmaf(hv[k], w, acc[k][h]);
        }
    }

#pragma unroll
    for (int k = 0; k < 4; k++) {
        if (!valid[k]) continue;
        int p = p0 + k * 256;
#pragma unroll
        for (int h = 0; h < 8; h++) {
            float z = acc[k][h] + b2[h];
            g_bias[h * LLs + p] = 16.0f / (1.0f + expf(-z));
        }
    }
}

// ============================================================
// Kernel 2: fp32 GEMM  C = A(43904x256) @ W(256x256) (+ bias)
// ============================================================
__global__ __launch_bounds__(256) void gemm_kernel(
    const float* __restrict__ A, const float* __restrict__ W,
    const float* __restrict__ bias, float* __restrict__ C, int remap)
{
    __shared__ float As[8][128];
    __shared__ float Bs[8][128];
    const int tid = threadIdx.x;
    const int m0 = blockIdx.x * 128, n0 = blockIdx.y * 128;
    const int arow = tid >> 1, acol = (tid & 1) << 2;
    const int brow = tid >> 5, bcol = (tid & 31) << 2;
    const int ty = tid >> 4, tx = tid & 15;

    float acc[8][8];
#pragma unroll
    for (int i = 0; i < 8; i++)
#pragma unroll
        for (int j = 0; j < 8; j++) acc[i][j] = 0.0f;

    for (int k0 = 0; k0 < Es; k0 += 8) {
        float4 av = *(const float4*)(A + (size_t)(m0 + arow) * Es + k0 + acol);
        float4 bv = *(const float4*)(W + (size_t)(k0 + brow) * Es + n0 + bcol);
        As[acol + 0][arow] = av.x;
        As[acol + 1][arow] = av.y;
        As[acol + 2][arow] = av.z;
        As[acol + 3][arow] = av.w;
        *(float4*)&Bs[brow][bcol] = bv;
        __syncthreads();
#pragma unroll
        for (int kk = 0; kk < 8; kk++) {
            float a[8], b[8];
#pragma unroll
            for (int i = 0; i < 8; i++) a[i] = As[kk][ty * 8 + i];
#pragma unroll
            for (int j = 0; j < 8; j++) b[j] = Bs[kk][tx * 8 + j];
#pragma unroll
            for (int i = 0; i < 8; i++)
#pragma unroll
                for (int j = 0; j < 8; j++) acc[i][j] = fmaf(a[i], b[j], acc[i][j]);
        }
        __syncthreads();
    }

#pragma unroll
    for (int i = 0; i < 8; i++) {
        int r = m0 + ty * 8 + i;
        int bb = r / Ls;
        int l = r - bb * Ls;
#pragma unroll
        for (int j = 0; j < 8; j++) {
            int n = n0 + tx * 8 + j;
            float v = acc[i][j];
            if (bias) v += bias[n];
            if (remap) {
                int hh = n >> 5, hd = n & 31;
                C[((size_t)(bb * Hs + hh) * Ls + l) * HDs + hd] = v;
            } else {
                C[(size_t)r * Es + n] = v;
            }
        }
    }
}

// ============================================================
// Kernel 3: L2-normalize rows of g_q and g_k
// ============================================================
__global__ __launch_bounds__(256) void norm_kernel()
{
    const int R = BBs * Hs * Ls;
    int gw = (blockIdx.x * blockDim.x + threadIdx.x) >> 5;
    int lane = threadIdx.x & 31;
    if (gw >= 2 * R) return;
    float* p = (gw < R) ? g_q : g_k;
    int row = (gw < R) ? gw : gw - R;
    float v = p[(size_t)row * HDs + lane];
    float ss = v * v;
#pragma unroll
    for (int o = 16; o > 0; o >>= 1) ss += __shfl_xor_sync(0xffffffffu, ss, o);
    float d = fmaxf(sqrtf(ss), 1e-12f);
    p[(size_t)row * HDs + lane] = v / d;
}

// ============================================================
// Kernel 4: fused attention per (window bb, head h, 64-query tile).
// SMEM: K(343x33), V(343x33), Q(64x33), S(64x352) = 189112 B dynamic.
// ============================================================
#define ATTN_SMEM_FLOATS (Ls * 33 * 2 + 64 * 33 + 64 * 352)
#define ATTN_SMEM_BYTES  (ATTN_SMEM_FLOATS * 4)

__global__ __launch_bounds__(256) void attn_kernel(
    const void* __restrict__ maskp,   // (1, NW, 1, L, L) bool (dtype per g_mask_mode)
    const float* __restrict__ scalep) // (1,)
{
    extern __shared__ float sm[];
    float* Ksh = sm;                     // 343*33
    float* Vsh = Ksh + Ls * 33;          // 343*33
    float* Qsh = Vsh + Ls * 33;          // 64*33
    float* Ssh = Qsh + 64 * 33;          // 64*352

    const int tid = threadIdx.x;
    const int q0 = blockIdx.x * 64;
    const int h = blockIdx.y;
    const int bb = blockIdx.z;
    const int nq = min(64, Ls - q0);
    const size_t base = (size_t)(bb * Hs + h) * Ls * HDs;
    const int mmode = g_mask_mode;

    for (int idx = tid; idx < Ls * HDs; idx += 256) {
        int j = idx >> 5, c = idx & 31;
        Ksh[j * 33 + c] = g_k[base + idx];
        Vsh[j * 33 + c] = g_v[base + idx];
    }
    for (int idx = tid; idx < 64 * HDs; idx += 256) {
        int r = idx >> 5, c = idx & 31;
        Qsh[r * 33 + c] = (r < nq) ? g_q[base + (size_t)(q0 + r) * HDs + c] : 0.0f;
    }
    __syncthreads();

    const int ty = tid >> 5;   // 0..7  (query group)
    const int tx = tid & 31;   // 0..31

    // ---- phase 1: S = Q K^T ----
    float acc[8][11];
#pragma unroll
    for (int i = 0; i < 8; i++)
#pragma unroll
        for (int n = 0; n < 11; n++) acc[i][n] = 0.0f;

    const float* qb = Qsh + ty * 8 * 33;
    const float* kb = Ksh + tx * 33;
#pragma unroll 2
    for (int c = 0; c < 32; c++) {
        float qv[8], kv[11];
#pragma unroll
        for (int i = 0; i < 8; i++) qv[i] = qb[i * 33 + c];
#pragma unroll
        for (int n = 0; n < 11; n++) kv[n] = kb[n * (32 * 33) + c];
#pragma unroll
        for (int i = 0; i < 8; i++)
#pragma unroll
            for (int n = 0; n < 11; n++) acc[i][n] = fmaf(qv[i], kv[n], acc[i][n]);
    }

    const float invscale = 1.0f / fmaxf(scalep[0], 0.01f);
    const float* biasrow = g_bias + (size_t)h * LLs;
    const unsigned char* m8  = (const unsigned char*)maskp + (size_t)bb * LLs;
    const int*           m32 = (const int*)maskp           + (size_t)bb * LLs;
    const float*         mf  = (const float*)maskp         + (size_t)bb * LLs;
#pragma unroll
    for (int i = 0; i < 8; i++) {
        int qi = ty * 8 + i;
        if (qi >= nq) continue;
        int qrow = q0 + qi;
#pragma unroll
        for (int n = 0; n < 11; n++) {
            int kj = n * 32 + tx;
            if (kj < Ls) {
                size_t mi = (size_t)qrow * Ls + kj;
                float v = fmaf(acc[i][n], invscale, biasrow[mi]);
                bool masked = (mmode == 0) ? (m8[mi] != 0)
                            : (mmode == 1) ? (m32[mi] != 0)
                                           : (mf[mi] != 0.0f);
                if (masked) v = -100000.0f;
                Ssh[qi * 352 + kj] = v;
            }
        }
    }
    __syncthreads();

    // ---- phase 2: softmax ----
    for (int r = ty; r < nq; r += 8) {
        float* row = Ssh + r * 352;
        float m = -FLT_MAX;
        for (int j = tx; j < Ls; j += 32) m = fmaxf(m, row[j]);
#pragma unroll
        for (int o = 16; o > 0; o >>= 1) m = fmaxf(m, __shfl_xor_sync(0xffffffffu, m, o));
        float s = 0.0f;
        for (int j = tx; j < Ls; j += 32) {
            float e = __expf(row[j] - m);
            row[j] = e;
            s += e;
        }
#pragma unroll
        for (int o = 16; o > 0; o >>= 1) s += __shfl_xor_sync(0xffffffffu, s, o);
        float inv = 1.0f / s;
        for (int j = tx; j < Ls; j += 32) row[j] *= inv;
    }
    __syncthreads();

    // ---- phase 3: O = P V ----
    float o8[8];
#pragma unroll
    for (int i = 0; i < 8; i++) o8[i] = 0.0f;
#pragma unroll 2
    for (int j = 0; j < Ls; j++) {
        float v = Vsh[j * 33 + tx];
#pragma unroll
        for (int i = 0; i < 8; i++)
            o8[i] = fmaf(Ssh[(ty * 8 + i) * 352 + j], v, o8[i]);
    }
#pragma unroll
    for (int i = 0; i < 8; i++) {
        int qi = ty * 8 + i;
        if (qi < nq)
            g_att[(size_t)(bb * Ls + q0 + qi) * Es + h * HDs + tx] = o8[i];
    }
}

// ============================================================
// launch
// ============================================================
extern "C" void kernel_launch(void* const* d_in, const int* in_sizes, int n_in,
                              void* d_out, int out_size)
{
    (void)in_sizes; (void)n_in; (void)out_size;
    const float*         query   = (const float*)d_in[0];
    const float*         key     = (const float*)d_in[1];
    const float*         value   = (const float*)d_in[2];
    const float*         indices = (const float*)d_in[3];
    const void*          mask    = d_in[4];
    const float*         Wq      = (const float*)d_in[5];
    const float*         bq      = (const float*)d_in[6];
    const float*         Wk      = (const float*)d_in[7];
    const float*         bk      = (const float*)d_in[8];
    const float*         Wv      = (const float*)d_in[9];
    const float*         Ww      = (const float*)d_in[10];
    const float*         bw      = (const float*)d_in[11];
    const float*         scale   = (const float*)d_in[12];
    const float*         W1      = (const float*)d_in[13];
    const float*         b1      = (const float*)d_in[14];
    const float*         W2      = (const float*)d_in[15];
    const float*         b2      = (const float*)d_in[16];
    float* out = (float*)d_out;

    float *pq, *pk, *pv, *patt;
    cudaGetSymbolAddress((void**)&pq,   g_q);
    cudaGetSymbolAddress((void**)&pk,   g_k);
    cudaGetSymbolAddress((void**)&pv,   g_v);
    cudaGetSymbolAddress((void**)&patt, g_att);

    // 0) detect mask dtype (bool marshalling is undocumented)
    detect_mask_kernel<<<1, 256>>>((const unsigned int*)mask);

    // 1) CPB bias table
    bias_kernel<<<(LLs + 1023) / 1024, 256>>>(indices, W1, b1, W2, b2);

    // 2) Q/K/V projections into head-split layout
    dim3 gg(ROWSs / 128, Es / 128);
    gemm_kernel<<<gg, 256>>>(query, Wq, bq, pq, 1);
    gemm_kernel<<<gg, 256>>>(key,   Wk, bk, pk, 1);
    gemm_kernel<<<gg, 256>>>(value, Wv, nullptr, pv, 1);

    // 3) L2 normalize q and k heads
    {
        long long warps = 2LL * BBs * Hs * Ls;
        int blocks = (int)((warps * 32 + 255) / 256);
        norm_kernel<<<blocks, 256>>>();
    }

    // 4) fused attention
    cudaFuncSetAttribute(attn_kernel, cudaFuncAttributeMaxDynamicSharedMemorySize,
                         ATTN_SMEM_BYTES);
    attn_kernel<<<dim3((Ls + 63) / 64, Hs, BBs), 256, ATTN_SMEM_BYTES>>>(mask, scale);

    // 5) output projection straight into d_out
    gemm_kernel<<<gg, 256>>>(patt, Ww, bw, out, 0);
}

// round 4
// speedup vs baseline: 1.0988x; 1.0988x over previous
#include <cuda_runtime.h>
#include <cuda_bf16.h>
#include <math.h>
#include <float.h>
#include <stdint.h>

// Problem dims
#define BBs   128
#define Ls    343
#define Es    256
#define Hs    8
#define HDs   32
#define HIDs  512
#define LLs   (Ls * Ls)       // 117649
#define ROWSs (BBs * Ls)      // 43904

// -------- scratch (device globals; no allocation allowed) --------
__device__ float g_q[BBs * Hs * Ls * HDs];
__device__ float g_k[BBs * Hs * Ls * HDs];
__device__ float g_v[BBs * Hs * Ls * HDs];
__device__ float g_bias[Hs * LLs];
__device__ float g_att[ROWSs * Es];
__device__ int   g_mask_mode;
__device__ __nv_bfloat16 g_ah[ROWSs * Es];
__device__ __nv_bfloat16 g_al[ROWSs * Es];
__device__ __nv_bfloat16 g_wh[Es * Es];   // transposed [n][k]
__device__ __nv_bfloat16 g_wl[Es * Es];

// ============================================================
// PTX helpers (baseline sm_80+ ISA only — harness targets sm_103 w/o 'a')
// ============================================================
__device__ __forceinline__ uint32_t smem_u32(const void* p) {
    uint32_t a;
    asm("{ .reg .u64 t; cvta.to.shared.u64 t, %1; cvt.u32.u64 %0, t; }" : "=r"(a) : "l"(p));
    return a;
}
__device__ __forceinline__ void ldsm_x4(uint32_t& r0, uint32_t& r1, uint32_t& r2,
                                        uint32_t& r3, uint32_t addr) {
    asm volatile("ldmatrix.sync.aligned.m8n8.x4.shared.b16 {%0,%1,%2,%3}, [%4];"
                 : "=r"(r0), "=r"(r1), "=r"(r2), "=r"(r3) : "r"(addr));
}
__device__ __forceinline__ void mma16816(float* c, const uint32_t* a,
                                         uint32_t b0, uint32_t b1) {
    asm volatile(
        "mma.sync.aligned.m16n8k16.row.col.f32.bf16.bf16.f32 "
        "{%0,%1,%2,%3}, {%4,%5,%6,%7}, {%8,%9}, {%0,%1,%2,%3};"
        : "+f"(c[0]), "+f"(c[1]), "+f"(c[2]), "+f"(c[3])
        : "r"(a[0]), "r"(a[1]), "r"(a[2]), "r"(a[3]), "r"(b0), "r"(b1));
}
__device__ __forceinline__ void cp_async16(uint32_t dst, const void* src) {
    asm volatile("cp.async.cg.shared.global [%0], [%1], 16;" :: "r"(dst), "l"(src));
}
__device__ __forceinline__ void cp_commit() {
    asm volatile("cp.async.commit_group;");
}
__device__ __forceinline__ void cp_wait1() {
    asm volatile("cp.async.wait_group 1;");
}
__device__ __forceinline__ void cp_wait0() {
    asm volatile("cp.async.wait_group 0;");
}

// ============================================================
// Kernel 0: detect mask dtype
// ============================================================
__global__ void detect_mask_kernel(const unsigned int* __restrict__ m)
{
    __shared__ int s_float, s_multi;
    if (threadIdx.x == 0) { s_float = 0; s_multi = 0; }
    __syncthreads();
    for (int i = threadIdx.x; i < 4096; i += 256) {
        unsigned int w = m[i];
        if (w == 0x3F800000u) atomicOr(&s_float, 1);
        else if (w != 0u && (w & 0xFFFFFF00u) != 0u) atomicOr(&s_multi, 1);
    }
    __syncthreads();
    if (threadIdx.x == 0)
        g_mask_mode = s_float ? 2 : (s_multi ? 0 : 1);
}

// ============================================================
// Kernel 1: CPB bias table
// ============================================================
__global__ __launch_bounds__(256) void bias_kernel(
    const float* __restrict__ indices, const float* __restrict__ W1,
    const float* __restrict__ b1, const float* __restrict__ W2,
    const float* __restrict__ b2)
{
    __shared__ float sW1[3 * HIDs];
    __shared__ float sb1[HIDs];
    __shared__ float sW2[HIDs * Hs];
    for (int i = threadIdx.x; i < 3 * HIDs; i += 256) sW1[i] = W1[i];
    for (int i = threadIdx.x; i < HIDs;     i += 256) sb1[i] = b1[i];
    for (int i = threadIdx.x; i < HIDs * Hs; i += 256) sW2[i] = W2[i];
    __syncthreads();

    const int p0 = blockIdx.x * 1024 + threadIdx.x;
    float x[4][3];
    bool valid[4];
#pragma unroll
    for (int k = 0; k < 4; k++) {
        int p = p0 + k * 256;
        valid[k] = (p < LLs);
        int pp = valid[k] ? p : 0;
#pragma unroll
        for (int c = 0; c < 3; c++) {
            float xv = indices[pp * 3 + c];
            x[k][c] = copysignf(log2f(1.0f + fabsf(xv)) * (1.0f / 3.0f), xv);
        }
    }
    float acc[4][8];
#pragma unroll
    for (int k = 0; k < 4; k++)
#pragma unroll
        for (int h = 0; h < 8; h++) acc[k][h] = 0.0f;

    for (int t = 0; t < HIDs; t++) {
        float w0 = sW1[t], w1 = sW1[HIDs + t], w2 = sW1[2 * HIDs + t];
        float bb1 = sb1[t];
        float hv[4];
#pragma unroll
        for (int k = 0; k < 4; k++)
            hv[k] = fmaxf(fmaf(x[k][0], w0, fmaf(x[k][1], w1, fmaf(x[k][2], w2, bb1))), 0.0f);
#pragma unroll
        for (int h = 0; h < 8; h++) {
            float w = sW2[t * 8 + h];
#pragma unroll
            for (int k = 0; k < 4; k++) acc[k][h] = fmaf(hv[k], w, acc[k][h]);
        }
    }
#pragma unroll
    for (int k = 0; k < 4; k++) {
        if (!valid[k]) continue;
        int p = p0 + k * 256;
#pragma unroll
        for (int h = 0; h < 8; h++) {
            float z = acc[k][h] + b2[h];
            g_bias[h * LLs + p] = 16.0f / (1.0f + expf(-z));
        }
    }
}

// ============================================================
// Kernel 2a: split fp32 activations -> bf16 hi/lo
// ============================================================
__global__ __launch_bounds__(256) void split_kernel(
    const float4* __restrict__ in, ushort4* __restrict__ hi,
    ushort4* __restrict__ lo, int n4)
{
    int i = blockIdx.x * 256 + threadIdx.x;
    if (i >= n4) return;
    float4 v = in[i];
    __nv_bfloat16 h0 = __float2bfloat16(v.x), h1 = __float2bfloat16(v.y);
    __nv_bfloat16 h2 = __float2bfloat16(v.z), h3 = __float2bfloat16(v.w);
    __nv_bfloat16 l0 = __float2bfloat16(v.x - __bfloat162float(h0));
    __nv_bfloat16 l1 = __float2bfloat16(v.y - __bfloat162float(h1));
    __nv_bfloat16 l2 = __float2bfloat16(v.z - __bfloat162float(h2));
    __nv_bfloat16 l3 = __float2bfloat16(v.w - __bfloat162float(h3));
    ushort4 hv = { __bfloat16_as_ushort(h0), __bfloat16_as_ushort(h1),
                   __bfloat16_as_ushort(h2), __bfloat16_as_ushort(h3) };
    ushort4 lv = { __bfloat16_as_ushort(l0), __bfloat16_as_ushort(l1),
                   __bfloat16_as_ushort(l2), __bfloat16_as_ushort(l3) };
    hi[i] = hv; lo[i] = lv;
}

// ============================================================
// Kernel 2b: weight transpose + split: W[k][n] -> Wt_hi/lo[n][k]
// ============================================================
__global__ __launch_bounds__(256) void wsplit_kernel(
    const float* __restrict__ W, __nv_bfloat16* __restrict__ ht,
    __nv_bfloat16* __restrict__ lt)
{
    __shared__ float t[32][33];
    int bn = blockIdx.x * 32, bk = blockIdx.y * 32;
    int lx = threadIdx.x & 31, ly = threadIdx.x >> 5;
    for (int yy = ly; yy < 32; yy += 8)
        t[yy][lx] = W[(size_t)(bk + yy) * Es + bn + lx];
    __syncthreads();
    for (int yy = ly; yy < 32; yy += 8) {
        float v = t[lx][yy];
        __nv_bfloat16 h = __float2bfloat16(v);
        __nv_bfloat16 l = __float2bfloat16(v - __bfloat162float(h));
        size_t o = (size_t)(bn + yy) * Es + bk + lx;
        ht[o] = h; lt[o] = l;
    }
}

// ============================================================
// Kernel 3: mma.sync bf16 split-GEMM (tensor pipe via HMMA)
//   C = Ah@Wh + Al@Wh + Ah@Wl, fp32 accum in registers.
//   Block 128x128, 8 warps of 64x32; K in 12 chunks of 64,
//   2-stage cp.async double buffer. SMEM stride 72 bf16 -> conflict-free.
// ============================================================
#define TGS 72
#define STAGE_B (128 * TGS * 2)            // 18432 bytes per matrix per stage
#define TG_SMEM (4 * STAGE_B)              // 73728 bytes

__global__ __launch_bounds__(256) void tgemm_kernel(
    const __nv_bfloat16* __restrict__ Ah, const __nv_bfloat16* __restrict__ Al,
    const __nv_bfloat16* __restrict__ Wh, const __nv_bfloat16* __restrict__ Wl,
    const float* __restrict__ bias, float* __restrict__ C, int remap)
{
    extern __shared__ char dsm[];
    const int tid = threadIdx.x;
    const int wid = tid >> 5;
    const int lane = tid & 31;
    const int m0 = blockIdx.x * 128;
    const int n0 = blockIdx.y * 128;
    const int wm = wid & 1;        // 0..1
    const int wn = wid >> 1;       // 0..3
    const uint32_t smb = smem_u32(dsm);

    float c[4][4][4];
#pragma unroll
    for (int i = 0; i < 4; i++)
#pragma unroll
        for (int j = 0; j < 4; j++)
#pragma unroll
            for (int k = 0; k < 4; k++) c[i][j][k] = 0.0f;

    // prefetch chunk i into stage i&1
    auto prefetch = [&](int i) {
        const int t = i >> 2, kc = i & 3, s = i & 1;
        const __nv_bfloat16* As = (t == 1) ? Al : Ah;
        const __nv_bfloat16* Bs = (t == 2) ? Wl : Wh;
        const int k0 = kc * 64;
        const uint32_t bA = smb + s * 2 * STAGE_B;
        const uint32_t bB = bA + STAGE_B;
#pragma unroll
        for (int j = 0; j < 4; j++) {
            int x = tid + j * 256;
            int r = x >> 3, cc = x & 7;
            uint32_t off = (uint32_t)(r * TGS + cc * 8) * 2;
            cp_async16(bA + off, As + (size_t)(m0 + r) * Es + k0 + cc * 8);
            cp_async16(bB + off, Bs + (size_t)(n0 + r) * Es + k0 + cc * 8);
        }
    };

    prefetch(0);
    cp_commit();

    const int arow = (lane & 7) + ((lane >> 3) & 1) * 8;
    const int acolo = ((lane >> 4) & 1) * 8;
    const int brow = (lane & 7) + ((lane >> 4) & 1) * 8;
    const int bcolo = ((lane >> 3) & 1) * 8;

    for (int i = 0; i < 12; i++) {
        if (i < 11) { prefetch(i + 1); cp_commit(); }
        if (i < 11) cp_wait1(); else cp_wait0();
        __syncthreads();

        const uint32_t bA = smb + (i & 1) * 2 * STAGE_B;
        const uint32_t bB = bA + STAGE_B;
#pragma unroll
        for (int ks = 0; ks < 4; ks++) {
            const int k0 = ks * 16;
            uint32_t a[4][4], b[2][4];
#pragma unroll
            for (int mt = 0; mt < 4; mt++)
                ldsm_x4(a[mt][0], a[mt][1], a[mt][2], a[mt][3],
                        bA + (uint32_t)((wm * 64 + mt * 16 + arow) * TGS + k0 + acolo) * 2);
#pragma unroll
            for (int g = 0; g < 2; g++)
                ldsm_x4(b[g][0], b[g][1], b[g][2], b[g][3],
                        bB + (uint32_t)((wn * 32 + g * 16 + brow) * TGS + k0 + bcolo) * 2);
#pragma unroll
            for (int mt = 0; mt < 4; mt++)
#pragma unroll
                for (int nt = 0; nt < 4; nt++)
                    mma16816(c[mt][nt], a[mt], b[nt >> 1][(nt & 1) * 2],
                             b[nt >> 1][(nt & 1) * 2 + 1]);
        }
        __syncthreads();
    }

    // ---- epilogue: direct register -> GMEM (float2 per tile-row) ----
    const int tq = lane >> 2;      // 0..7
    const int tr = lane & 3;       // 0..3
#pragma unroll
    for (int mt = 0; mt < 4; mt++) {
        const int m = m0 + wm * 64 + mt * 16 + tq;
#pragma unroll
        for (int nt = 0; nt < 4; nt++) {
            const int n = n0 + wn * 32 + nt * 8 + tr * 2;
            float2 v0 = make_float2(c[mt][nt][0], c[mt][nt][1]);
            float2 v1 = make_float2(c[mt][nt][2], c[mt][nt][3]);
            if (bias) {
                float2 bv = *(const float2*)(bias + n);
                v0.x += bv.x; v0.y += bv.y;
                v1.x += bv.x; v1.y += bv.y;
            }
            if (remap) {
                const int h = n >> 5, hd = n & 31;
                int bbw = m / Ls, l = m - bbw * Ls;
                *(float2*)(C + ((size_t)(bbw * Hs + h) * Ls + l) * HDs + hd) = v0;
                int m2 = m + 8;
                int bbw2 = m2 / Ls, l2 = m2 - bbw2 * Ls;
                *(float2*)(C + ((size_t)(bbw2 * Hs + h) * Ls + l2) * HDs + hd) = v1;
            } else {
                *(float2*)(C + (size_t)m * Es + n) = v0;
                *(float2*)(C + (size_t)(m + 8) * Es + n) = v1;
            }
        }
    }
}

// ============================================================
// Kernel 4: L2-normalize rows of g_q and g_k
// ============================================================
__global__ __launch_bounds__(256) void norm_kernel()
{
    const int R = BBs * Hs * Ls;
    int gw = (blockIdx.x * blockDim.x + threadIdx.x) >> 5;
    int lane = threadIdx.x & 31;
    if (gw >= 2 * R) return;
    float* p = (gw < R) ? g_q : g_k;
    int row = (gw < R) ? gw : gw - R;
    float v = p[(size_t)row * HDs + lane];
    float ss = v * v;
#pragma unroll
    for (int o = 16; o > 0; o >>= 1) ss += __shfl_xor_sync(0xffffffffu, ss, o);
    float d = fmaxf(sqrtf(ss), 1e-12f);
    p[(size_t)row * HDs + lane] = v / d;
}

// ============================================================
// Kernel 5: fused attention per (window, head, 64-query tile)
// ============================================================
#define VOFF 11320
#define QOFF (VOFF + Ls * 36)
#define SOFF (QOFF + 64 * 33)
#define ATTN_SMEM_BYTES ((SOFF + 64 * 352) * 4)

__global__ __launch_bounds__(256) void attn_kernel(
    const void* __restrict__ maskp, const float* __restrict__ scalep)
{
    extern __shared__ float sm[];
    float* Ksh = sm;
    float* Vsh = sm + VOFF;
    float* Qsh = sm + QOFF;
    float* Ssh = sm + SOFF;

    const int tid = threadIdx.x;
    const int q0 = blockIdx.x * 64;
    const int h = blockIdx.y;
    const int bb = blockIdx.z;
    const int nq = min(64, Ls - q0);
    const size_t base = (size_t)(bb * Hs + h) * Ls * HDs;
    const int mmode = g_mask_mode;

    for (int idx = tid; idx < Ls * HDs; idx += 256) {
        int j = idx >> 5, c = idx & 31;
        Ksh[j * 33 + c] = g_k[base + idx];
        Vsh[j * 36 + c] = g_v[base + idx];
    }
    for (int idx = tid; idx < 64 * HDs; idx += 256) {
        int r = idx >> 5, c = idx & 31;
        Qsh[r * 33 + c] = (r < nq) ? g_q[base + (size_t)(q0 + r) * HDs + c] : 0.0f;
    }
    __syncthreads();

    const int ty = tid >> 5;
    const int tx = tid & 31;

    // ---- phase 1: S = Q K^T (8 q x 11 k per thread) ----
    float acc[8][11];
#pragma unroll
    for (int i = 0; i < 8; i++)
#pragma unroll
        for (int n = 0; n < 11; n++) acc[i][n] = 0.0f;

    const float* qb = Qsh + ty * 8 * 33;
    const float* kb = Ksh + tx * 33;
#pragma unroll 2
    for (int c = 0; c < 32; c++) {
        float qv[8], kv[11];
#pragma unroll
        for (int i = 0; i < 8; i++) qv[i] = qb[i * 33 + c];
#pragma unroll
        for (int n = 0; n < 11; n++) kv[n] = kb[n * (32 * 33) + c];
#pragma unroll
        for (int i = 0; i < 8; i++)
#pragma unroll
            for (int n = 0; n < 11; n++) acc[i][n] = fmaf(qv[i], kv[n], acc[i][n]);
    }

    const float invscale = 1.0f / fmaxf(scalep[0], 0.01f);
    const float* biasrow = g_bias + (size_t)h * LLs;
    const unsigned char* m8  = (const unsigned char*)maskp + (size_t)bb * LLs;
    const int*           m32 = (const int*)maskp           + (size_t)bb * LLs;
    const float*         mf  = (const float*)maskp         + (size_t)bb * LLs;
#pragma unroll
    for (int i = 0; i < 8; i++) {
        int qi = ty * 8 + i;
        if (qi >= nq) continue;
        int qrow = q0 + qi;
#pragma unroll
        for (int n = 0; n < 11; n++) {
            int kj = n * 32 + tx;
            if (kj < Ls) {
                size_t mi = (size_t)qrow * Ls + kj;
                float v = fmaf(acc[i][n], invscale, biasrow[mi]);
                bool masked = (mmode == 0) ? (m8[mi] != 0)
                            : (mmode == 1) ? (m32[mi] != 0)
                                           : (mf[mi] != 0.0f);
                if (masked) v = -100000.0f;
                Ssh[qi * 352 + kj] = v;
            }
        }
    }
    __syncthreads();

    // ---- phase 2: softmax per row ----
    for (int r = ty; r < nq; r += 8) {
        float* row = Ssh + r * 352;
        float m = -FLT_MAX;
        for (int j = tx; j < Ls; j += 32) m = fmaxf(m, row[j]);
#pragma unroll
        for (int o = 16; o > 0; o >>= 1) m = fmaxf(m, __shfl_xor_sync(0xffffffffu, m, o));
        float s = 0.0f;
        for (int j = tx; j < Ls; j += 32) {
            float e = __expf(row[j] - m);
            row[j] = e;
            s += e;
        }
#pragma unroll
        for (int o = 16; o > 0; o >>= 1) s += __shfl_xor_sync(0xffffffffu, s, o);
        float inv = 1.0f / s;
        for (int j = tx; j < Ls; j += 32) row[j] *= inv;
    }
    __syncthreads();

    // ---- phase 3: O = P V (1 q x 8 hd per thread, vectorized V) ----
    const int q = tid >> 2;
    const int hb = (tid & 3) * 8;
    float o8[8];
#pragma unroll
    for (int i = 0; i < 8; i++) o8[i] = 0.0f;
    const float* srow = Ssh + q * 352;
#pragma unroll 2
    for (int j = 0; j < Ls; j++) {
        float s = srow[j];
        float4 v0 = *(const float4*)(Vsh + j * 36 + hb);
        float4 v1 = *(const float4*)(Vsh + j * 36 + hb + 4);
        o8[0] = fmaf(s, v0.x, o8[0]); o8[1] = fmaf(s, v0.y, o8[1]);
        o8[2] = fmaf(s, v0.z, o8[2]); o8[3] = fmaf(s, v0.w, o8[3]);
        o8[4] = fmaf(s, v1.x, o8[4]); o8[5] = fmaf(s, v1.y, o8[5]);
        o8[6] = fmaf(s, v1.z, o8[6]); o8[7] = fmaf(s, v1.w, o8[7]);
    }
    if (q < nq) {
        float* dst = g_att + (size_t)(bb * Ls + q0 + q) * Es + h * HDs + hb;
        *(float4*)dst       = make_float4(o8[0], o8[1], o8[2], o8[3]);
        *(float4*)(dst + 4) = make_float4(o8[4], o8[5], o8[6], o8[7]);
    }
}

// ============================================================
// launch
// ============================================================
extern "C" void kernel_launch(void* const* d_in, const int* in_sizes, int n_in,
                              void* d_out, int out_size)
{
    (void)in_sizes; (void)n_in; (void)out_size;
    const float* query   = (const float*)d_in[0];
    const float* key     = (const float*)d_in[1];
    const float* value   = (const float*)d_in[2];
    const float* indices = (const float*)d_in[3];
    const void*  mask    = d_in[4];
    const float* Wq      = (const float*)d_in[5];
    const float* bq      = (const float*)d_in[6];
    const float* Wk      = (const float*)d_in[7];
    const float* bk      = (const float*)d_in[8];
    const float* Wv      = (const float*)d_in[9];
    const float* Ww      = (const float*)d_in[10];
    const float* bw      = (const float*)d_in[11];
    const float* scale   = (const float*)d_in[12];
    const float* W1      = (const float*)d_in[13];
    const float* b1      = (const float*)d_in[14];
    const float* W2      = (const float*)d_in[15];
    const float* b2      = (const float*)d_in[16];
    float* out = (float*)d_out;

    float *pq, *pk, *pv, *patt;
    __nv_bfloat16 *pah, *pal, *pwh, *pwl;
    cudaGetSymbolAddress((void**)&pq,   g_q);
    cudaGetSymbolAddress((void**)&pk,   g_k);
    cudaGetSymbolAddress((void**)&pv,   g_v);
    cudaGetSymbolAddress((void**)&patt, g_att);
    cudaGetSymbolAddress((void**)&pah,  g_ah);
    cudaGetSymbolAddress((void**)&pal,  g_al);
    cudaGetSymbolAddress((void**)&pwh,  g_wh);
    cudaGetSymbolAddress((void**)&pwl,  g_wl);

    cudaFuncSetAttribute(tgemm_kernel, cudaFuncAttributeMaxDynamicSharedMemorySize,
                         TG_SMEM);
    cudaFuncSetAttribute(attn_kernel, cudaFuncAttributeMaxDynamicSharedMemorySize,
                         ATTN_SMEM_BYTES);

    const int n4 = ROWSs * Es / 4;
    const int splitg = (n4 + 255) / 256;
    const dim3 wsg(8, 8);
    const dim3 gg(ROWSs / 128, Es / 128);

    detect_mask_kernel<<<1, 256>>>((const unsigned int*)mask);
    bias_kernel<<<(LLs + 1023) / 1024, 256>>>(indices, W1, b1, W2, b2);

    // Q projection
    wsplit_kernel<<<wsg, 256>>>(Wq, pwh, pwl);
    split_kernel<<<splitg, 256>>>((const float4*)query, (ushort4*)pah, (ushort4*)pal, n4);
    tgemm_kernel<<<gg, 256, TG_SMEM>>>(pah, pal, pwh, pwl, bq, pq, 1);
    // K projection
    wsplit_kernel<<<wsg, 256>>>(Wk, pwh, pwl);
    split_kernel<<<splitg, 256>>>((const float4*)key, (ushort4*)pah, (ushort4*)pal, n4);
    tgemm_kernel<<<gg, 256, TG_SMEM>>>(pah, pal, pwh, pwl, bk, pk, 1);
    // V projection
    wsplit_kernel<<<wsg, 256>>>(Wv, pwh, pwl);
    split_kernel<<<splitg, 256>>>((const float4*)value, (ushort4*)pah, (ushort4*)pal, n4);
    tgemm_kernel<<<gg, 256, TG_SMEM>>>(pah, pal, pwh, pwl, nullptr, pv, 1);

    // normalize + attention
    {
        long long warps = 2LL * BBs * Hs * Ls;
        int blocks = (int)((warps * 32 + 255) / 256);
        norm_kernel<<<blocks, 256>>>();
    }
    attn_kernel<<<dim3((Ls + 63) / 64, Hs, BBs), 256, ATTN_SMEM_BYTES>>>(mask, scale);

    // output projection
    wsplit_kernel<<<wsg, 256>>>(Ww, pwh, pwl);
    split_kernel<<<splitg, 256>>>((const float4*)patt, (ushort4*)pah, (ushort4*)pal, n4);
    tgemm_kernel<<<gg, 256, TG_SMEM>>>(pah, pal, pwh, pwl, bw, out, 0);
}

// round 5
// speedup vs baseline: 1.3060x; 1.1886x over previous
#include <cuda_runtime.h>
#include <cuda_bf16.h>
#include <math.h>
#include <float.h>
#include <stdint.h>

// Problem dims
#define BBs   128
#define Ls    343
#define Es    256
#define Hs    8
#define HDs   32
#define HIDs  512
#define LLs   (Ls * Ls)       // 117649
#define ROWSs (BBs * Ls)      // 43904

// -------- scratch (device globals; no allocation allowed) --------
__device__ float g_q[BBs * Hs * Ls * HDs];
__device__ float g_k[BBs * Hs * Ls * HDs];
__device__ float g_v[BBs * Hs * Ls * HDs];
__device__ float g_bias[Hs * LLs];
__device__ float g_att[ROWSs * Es];
__device__ int   g_mask_mode;
__device__ __nv_bfloat16 g_ah[ROWSs * Es];
__device__ __nv_bfloat16 g_al[ROWSs * Es];
__device__ __nv_bfloat16 g_wh[Es * Es];   // transposed [n][k]
__device__ __nv_bfloat16 g_wl[Es * Es];

// ============================================================
// PTX helpers (baseline sm_80+ ISA only — harness targets sm_103 w/o 'a')
// ============================================================
__device__ __forceinline__ uint32_t smem_u32(const void* p) {
    uint32_t a;
    asm("{ .reg .u64 t; cvta.to.shared.u64 t, %1; cvt.u32.u64 %0, t; }" : "=r"(a) : "l"(p));
    return a;
}
__device__ __forceinline__ void ldsm_x4(uint32_t& r0, uint32_t& r1, uint32_t& r2,
                                        uint32_t& r3, uint32_t addr) {
    asm volatile("ldmatrix.sync.aligned.m8n8.x4.shared.b16 {%0,%1,%2,%3}, [%4];"
                 : "=r"(r0), "=r"(r1), "=r"(r2), "=r"(r3) : "r"(addr));
}
__device__ __forceinline__ void mma16816(float* c, const uint32_t* a,
                                         uint32_t b0, uint32_t b1) {
    asm volatile(
        "mma.sync.aligned.m16n8k16.row.col.f32.bf16.bf16.f32 "
        "{%0,%1,%2,%3}, {%4,%5,%6,%7}, {%8,%9}, {%0,%1,%2,%3};"
        : "+f"(c[0]), "+f"(c[1]), "+f"(c[2]), "+f"(c[3])
        : "r"(a[0]), "r"(a[1]), "r"(a[2]), "r"(a[3]), "r"(b0), "r"(b1));
}
__device__ __forceinline__ void cp_async16(uint32_t dst, const void* src) {
    asm volatile("cp.async.cg.shared.global [%0], [%1], 16;" :: "r"(dst), "l"(src));
}
__device__ __forceinline__ void cp_commit() {
    asm volatile("cp.async.commit_group;");
}
__device__ __forceinline__ void cp_wait1() {
    asm volatile("cp.async.wait_group 1;");
}
__device__ __forceinline__ void cp_wait0() {
    asm volatile("cp.async.wait_group 0;");
}

// ------------------------------------------------------------
// Fast exp on FMA/ALU pipes only (no MUFU).
// exp(x) = 2^(x*log2e); magic-number round, deg-5 poly on [-0.5,0.5],
// exponent spliced with an integer add. Valid for x <= ~88; hard
// clamp below -126*ln2 (masked -1e5 scores -> ~0). rel err ~2.4e-6.
// ------------------------------------------------------------
__device__ __forceinline__ float fexp(float x) {
    float y = fmaxf(x * 1.4426950408889634f, -126.0f);
    float yr = __fadd_rn(y, 12582912.0f);      // round-to-nearest-int
    float n  = __fsub_rn(yr, 12582912.0f);
    float f  = __fsub_rn(y, n);                // f in [-0.5, 0.5]
    float p  = 1.3333558e-3f;
    p = fmaf(p, f, 9.6181291e-3f);
    p = fmaf(p, f, 5.5504109e-2f);
    p = fmaf(p, f, 2.4022651e-1f);
    p = fmaf(p, f, 6.9314718e-1f);
    p = fmaf(p, f, 1.0f);
    // bits(yr) = 0x4B400000 + n exactly; (0x4B400000<<23) mod 2^32 == 0,
    // so (bits(yr)<<23) == n<<23 (mod 2^32): a pure exponent offset.
    return __int_as_float(__float_as_int(p) + (__float_as_int(yr) << 23));
}

// ============================================================
// Kernel 0: detect mask dtype
// ============================================================
__global__ void detect_mask_kernel(const unsigned int* __restrict__ m)
{
    __shared__ int s_float, s_multi;
    if (threadIdx.x == 0) { s_float = 0; s_multi = 0; }
    __syncthreads();
    for (int i = threadIdx.x; i < 4096; i += 256) {
        unsigned int w = m[i];
        if (w == 0x3F800000u) atomicOr(&s_float, 1);
        else if (w != 0u && (w & 0xFFFFFF00u) != 0u) atomicOr(&s_multi, 1);
    }
    __syncthreads();
    if (threadIdx.x == 0)
        g_mask_mode = s_float ? 2 : (s_multi ? 0 : 1);
}

// ============================================================
// Kernel 1: CPB bias table
// ============================================================
__global__ __launch_bounds__(256) void bias_kernel(
    const float* __restrict__ indices, const float* __restrict__ W1,
    const float* __restrict__ b1, const float* __restrict__ W2,
    const float* __restrict__ b2)
{
    __shared__ float sW1[3 * HIDs];
    __shared__ float sb1[HIDs];
    __shared__ float sW2[HIDs * Hs];
    for (int i = threadIdx.x; i < 3 * HIDs; i += 256) sW1[i] = W1[i];
    for (int i = threadIdx.x; i < HIDs;     i += 256) sb1[i] = b1[i];
    for (int i = threadIdx.x; i < HIDs * Hs; i += 256) sW2[i] = W2[i];
    __syncthreads();

    const int p0 = blockIdx.x * 1024 + threadIdx.x;
    float x[4][3];
    bool valid[4];
#pragma unroll
    for (int k = 0; k < 4; k++) {
        int p = p0 + k * 256;
        valid[k] = (p < LLs);
        int pp = valid[k] ? p : 0;
#pragma unroll
        for (int c = 0; c < 3; c++) {
            float xv = indices[pp * 3 + c];
            x[k][c] = copysignf(log2f(1.0f + fabsf(xv)) * (1.0f / 3.0f), xv);
        }
    }
    float acc[4][8];
#pragma unroll
    for (int k = 0; k < 4; k++)
#pragma unroll
        for (int h = 0; h < 8; h++) acc[k][h] = 0.0f;

    for (int t = 0; t < HIDs; t++) {
        float w0 = sW1[t], w1 = sW1[HIDs + t], w2 = sW1[2 * HIDs + t];
        float bb1 = sb1[t];
        float hv[4];
#pragma unroll
        for (int k = 0; k < 4; k++)
            hv[k] = fmaxf(fmaf(x[k][0], w0, fmaf(x[k][1], w1, fmaf(x[k][2], w2, bb1))), 0.0f);
#pragma unroll
        for (int h = 0; h < 8; h++) {
            float w = sW2[t * 8 + h];
#pragma unroll
            for (int k = 0; k < 4; k++) acc[k][h] = fmaf(hv[k], w, acc[k][h]);
        }
    }
#pragma unroll
    for (int k = 0; k < 4; k++) {
        if (!valid[k]) continue;
        int p = p0 + k * 256;
#pragma unroll
        for (int h = 0; h < 8; h++) {
            float z = acc[k][h] + b2[h];
            g_bias[h * LLs + p] = 16.0f / (1.0f + fexp(-z));
        }
    }
}

// ============================================================
// Kernel 2a: split fp32 activations -> bf16 hi/lo
// ============================================================
__global__ __launch_bounds__(256) void split_kernel(
    const float4* __restrict__ in, ushort4* __restrict__ hi,
    ushort4* __restrict__ lo, int n4)
{
    int i = blockIdx.x * 256 + threadIdx.x;
    if (i >= n4) return;
    float4 v = in[i];
    __nv_bfloat16 h0 = __float2bfloat16(v.x), h1 = __float2bfloat16(v.y);
    __nv_bfloat16 h2 = __float2bfloat16(v.z), h3 = __float2bfloat16(v.w);
    __nv_bfloat16 l0 = __float2bfloat16(v.x - __bfloat162float(h0));
    __nv_bfloat16 l1 = __float2bfloat16(v.y - __bfloat162float(h1));
    __nv_bfloat16 l2 = __float2bfloat16(v.z - __bfloat162float(h2));
    __nv_bfloat16 l3 = __float2bfloat16(v.w - __bfloat162float(h3));
    ushort4 hv = { __bfloat16_as_ushort(h0), __bfloat16_as_ushort(h1),
                   __bfloat16_as_ushort(h2), __bfloat16_as_ushort(h3) };
    ushort4 lv = { __bfloat16_as_ushort(l0), __bfloat16_as_ushort(l1),
                   __bfloat16_as_ushort(l2), __bfloat16_as_ushort(l3) };
    hi[i] = hv; lo[i] = lv;
}

// ============================================================
// Kernel 2b: weight transpose + split: W[k][n] -> Wt_hi/lo[n][k]
// ============================================================
__global__ __launch_bounds__(256) void wsplit_kernel(
    const float* __restrict__ W, __nv_bfloat16* __restrict__ ht,
    __nv_bfloat16* __restrict__ lt)
{
    __shared__ float t[32][33];
    int bn = blockIdx.x * 32, bk = blockIdx.y * 32;
    int lx = threadIdx.x & 31, ly = threadIdx.x >> 5;
    for (int yy = ly; yy < 32; yy += 8)
        t[yy][lx] = W[(size_t)(bk + yy) * Es + bn + lx];
    __syncthreads();
    for (int yy = ly; yy < 32; yy += 8) {
        float v = t[lx][yy];
        __nv_bfloat16 h = __float2bfloat16(v);
        __nv_bfloat16 l = __float2bfloat16(v - __bfloat162float(h));
        size_t o = (size_t)(bn + yy) * Es + bk + lx;
        ht[o] = h; lt[o] = l;
    }
}

// ============================================================
// Kernel 3: mma.sync bf16 split-GEMM (tensor pipe via HMMA)
// ============================================================
#define TGS 72
#define STAGE_B (128 * TGS * 2)            // 18432 bytes per matrix per stage
#define TG_SMEM (4 * STAGE_B)              // 73728 bytes

__global__ __launch_bounds__(256) void tgemm_kernel(
    const __nv_bfloat16* __restrict__ Ah, const __nv_bfloat16* __restrict__ Al,
    const __nv_bfloat16* __restrict__ Wh, const __nv_bfloat16* __restrict__ Wl,
    const float* __restrict__ bias, float* __restrict__ C, int remap)
{
    extern __shared__ char dsm[];
    const int tid = threadIdx.x;
    const int wid = tid >> 5;
    const int lane = tid & 31;
    const int m0 = blockIdx.x * 128;
    const int n0 = blockIdx.y * 128;
    const int wm = wid & 1;
    const int wn = wid >> 1;
    const uint32_t smb = smem_u32(dsm);

    float c[4][4][4];
#pragma unroll
    for (int i = 0; i < 4; i++)
#pragma unroll
        for (int j = 0; j < 4; j++)
#pragma unroll
            for (int k = 0; k < 4; k++) c[i][j][k] = 0.0f;

    auto prefetch = [&](int i) {
        const int t = i >> 2, kc = i & 3, s = i & 1;
        const __nv_bfloat16* As = (t == 1) ? Al : Ah;
        const __nv_bfloat16* Bs = (t == 2) ? Wl : Wh;
        const int k0 = kc * 64;
        const uint32_t bA = smb + s * 2 * STAGE_B;
        const uint32_t bB = bA + STAGE_B;
#pragma unroll
        for (int j = 0; j < 4; j++) {
            int x = tid + j * 256;
            int r = x >> 3, cc = x & 7;
            uint32_t off = (uint32_t)(r * TGS + cc * 8) * 2;
            cp_async16(bA + off, As + (size_t)(m0 + r) * Es + k0 + cc * 8);
            cp_async16(bB + off, Bs + (size_t)(n0 + r) * Es + k0 + cc * 8);
        }
    };

    prefetch(0);
    cp_commit();

    const int arow = (lane & 7) + ((lane >> 3) & 1) * 8;
    const int acolo = ((lane >> 4) & 1) * 8;
    const int brow = (lane & 7) + ((lane >> 4) & 1) * 8;
    const int bcolo = ((lane >> 3) & 1) * 8;

    for (int i = 0; i < 12; i++) {
        if (i < 11) { prefetch(i + 1); cp_commit(); }
        if (i < 11) cp_wait1(); else cp_wait0();
        __syncthreads();

        const uint32_t bA = smb + (i & 1) * 2 * STAGE_B;
        const uint32_t bB = bA + STAGE_B;
#pragma unroll
        for (int ks = 0; ks < 4; ks++) {
            const int k0 = ks * 16;
            uint32_t a[4][4], b[2][4];
#pragma unroll
            for (int mt = 0; mt < 4; mt++)
                ldsm_x4(a[mt][0], a[mt][1], a[mt][2], a[mt][3],
                        bA + (uint32_t)((wm * 64 + mt * 16 + arow) * TGS + k0 + acolo) * 2);
#pragma unroll
            for (int g = 0; g < 2; g++)
                ldsm_x4(b[g][0], b[g][1], b[g][2], b[g][3],
                        bB + (uint32_t)((wn * 32 + g * 16 + brow) * TGS + k0 + bcolo) * 2);
#pragma unroll
            for (int mt = 0; mt < 4; mt++)
#pragma unroll
                for (int nt = 0; nt < 4; nt++)
                    mma16816(c[mt][nt], a[mt], b[nt >> 1][(nt & 1) * 2],
                             b[nt >> 1][(nt & 1) * 2 + 1]);
        }
        __syncthreads();
    }

    const int tq = lane >> 2;
    const int tr = lane & 3;
#pragma unroll
    for (int mt = 0; mt < 4; mt++) {
        const int m = m0 + wm * 64 + mt * 16 + tq;
#pragma unroll
        for (int nt = 0; nt < 4; nt++) {
            const int n = n0 + wn * 32 + nt * 8 + tr * 2;
            float2 v0 = make_float2(c[mt][nt][0], c[mt][nt][1]);
            float2 v1 = make_float2(c[mt][nt][2], c[mt][nt][3]);
            if (bias) {
                float2 bv = *(const float2*)(bias + n);
                v0.x += bv.x; v0.y += bv.y;
                v1.x += bv.x; v1.y += bv.y;
            }
            if (remap) {
                const int h = n >> 5, hd = n & 31;
                int bbw = m / Ls, l = m - bbw * Ls;
                *(float2*)(C + ((size_t)(bbw * Hs + h) * Ls + l) * HDs + hd) = v0;
                int m2 = m + 8;
                int bbw2 = m2 / Ls, l2 = m2 - bbw2 * Ls;
                *(float2*)(C + ((size_t)(bbw2 * Hs + h) * Ls + l2) * HDs + hd) = v1;
            } else {
                *(float2*)(C + (size_t)m * Es + n) = v0;
                *(float2*)(C + (size_t)(m + 8) * Es + n) = v1;
            }
        }
    }
}

// ============================================================
// Kernel 4: L2-normalize rows of g_q and g_k
// ============================================================
__global__ __launch_bounds__(256) void norm_kernel()
{
    const int R = BBs * Hs * Ls;
    int gw = (blockIdx.x * blockDim.x + threadIdx.x) >> 5;
    int lane = threadIdx.x & 31;
    if (gw >= 2 * R) return;
    float* p = (gw < R) ? g_q : g_k;
    int row = (gw < R) ? gw : gw - R;
    float v = p[(size_t)row * HDs + lane];
    float ss = v * v;
#pragma unroll
    for (int o = 16; o > 0; o >>= 1) ss += __shfl_xor_sync(0xffffffffu, ss, o);
    float d = fmaxf(sqrtf(ss), 1e-12f);
    p[(size_t)row * HDs + lane] = v / d;
}

// ============================================================
// Kernel 5: fused attention per (window, head, 64-query tile)
// S stride 356 (== 4 mod 32): phase-3 8-row reads hit distinct banks.
// ============================================================
#define SSTR 356
#define VOFF 11320
#define QOFF (VOFF + Ls * 36)
#define SOFF (QOFF + 64 * 33)
#define ATTN_SMEM_BYTES ((SOFF + 64 * SSTR) * 4)

__global__ __launch_bounds__(256) void attn_kernel(
    const void* __restrict__ maskp, const float* __restrict__ scalep)
{
    extern __shared__ float sm[];
    float* Ksh = sm;
    float* Vsh = sm + VOFF;
    float* Qsh = sm + QOFF;
    float* Ssh = sm + SOFF;

    const int tid = threadIdx.x;
    const int q0 = blockIdx.x * 64;
    const int h = blockIdx.y;
    const int bb = blockIdx.z;
    const int nq = min(64, Ls - q0);
    const size_t base = (size_t)(bb * Hs + h) * Ls * HDs;
    const int mmode = g_mask_mode;

    for (int idx = tid; idx < Ls * HDs; idx += 256) {
        int j = idx >> 5, c = idx & 31;
        Ksh[j * 33 + c] = g_k[base + idx];
        Vsh[j * 36 + c] = g_v[base + idx];
    }
    for (int idx = tid; idx < 64 * HDs; idx += 256) {
        int r = idx >> 5, c = idx & 31;
        Qsh[r * 33 + c] = (r < nq) ? g_q[base + (size_t)(q0 + r) * HDs + c] : 0.0f;
    }
    __syncthreads();

    const int ty = tid >> 5;
    const int tx = tid & 31;

    // ---- phase 1: S = Q K^T (8 q x 11 k per thread) ----
    float acc[8][11];
#pragma unroll
    for (int i = 0; i < 8; i++)
#pragma unroll
        for (int n = 0; n < 11; n++) acc[i][n] = 0.0f;

    const float* qb = Qsh + ty * 8 * 33;
    const float* kb = Ksh + tx * 33;
#pragma unroll 2
    for (int c = 0; c < 32; c++) {
        float qv[8], kv[11];
#pragma unroll
        for (int i = 0; i < 8; i++) qv[i] = qb[i * 33 + c];
#pragma unroll
        for (int n = 0; n < 11; n++) kv[n] = kb[n * (32 * 33) + c];
#pragma unroll
        for (int i = 0; i < 8; i++)
#pragma unroll
            for (int n = 0; n < 11; n++) acc[i][n] = fmaf(qv[i], kv[n], acc[i][n]);
    }

    const float invscale = 1.0f / fmaxf(scalep[0], 0.01f);
    const float* biasrow = g_bias + (size_t)h * LLs;
    const unsigned char* m8  = (const unsigned char*)maskp + (size_t)bb * LLs;
    const int*           m32 = (const int*)maskp           + (size_t)bb * LLs;
    const float*         mf  = (const float*)maskp         + (size_t)bb * LLs;
#pragma unroll
    for (int i = 0; i < 8; i++) {
        int qi = ty * 8 + i;
        if (qi >= nq) continue;
        int qrow = q0 + qi;
#pragma unroll
        for (int n = 0; n < 11; n++) {
            int kj = n * 32 + tx;
            if (kj < Ls) {
                size_t mi = (size_t)qrow * Ls + kj;
                float v = fmaf(acc[i][n], invscale, biasrow[mi]);
                bool masked = (mmode == 0) ? (m8[mi] != 0)
                            : (mmode == 1) ? (m32[mi] != 0)
                                           : (mf[mi] != 0.0f);
                if (masked) v = -100000.0f;
                Ssh[qi * SSTR + kj] = v;
            }
        }
    }
    __syncthreads();

    // ---- phase 2: softmax per row (poly exp, no MUFU) ----
    for (int r = ty; r < nq; r += 8) {
        float* row = Ssh + r * SSTR;
        float m = -FLT_MAX;
        for (int j = tx; j < Ls; j += 32) m = fmaxf(m, row[j]);
#pragma unroll
        for (int o = 16; o > 0; o >>= 1) m = fmaxf(m, __shfl_xor_sync(0xffffffffu, m, o));
        float s = 0.0f;
        for (int j = tx; j < Ls; j += 32) {
            float e = fexp(row[j] - m);
            row[j] = e;
            s += e;
        }
#pragma unroll
        for (int o = 16; o > 0; o >>= 1) s += __shfl_xor_sync(0xffffffffu, s, o);
        float inv = 1.0f / s;
        for (int j = tx; j < Ls; j += 32) row[j] *= inv;
    }
    __syncthreads();

    // ---- phase 3: O = P V (1 q x 8 hd per thread, vectorized V) ----
    const int q = tid >> 2;
    const int hb = (tid & 3) * 8;
    float o8[8];
#pragma unroll
    for (int i = 0; i < 8; i++) o8[i] = 0.0f;
    const float* srow = Ssh + q * SSTR;
#pragma unroll 2
    for (int j = 0; j < Ls; j++) {
        float s = srow[j];
        float4 v0 = *(const float4*)(Vsh + j * 36 + hb);
        float4 v1 = *(const float4*)(Vsh + j * 36 + hb + 4);
        o8[0] = fmaf(s, v0.x, o8[0]); o8[1] = fmaf(s, v0.y, o8[1]);
        o8[2] = fmaf(s, v0.z, o8[2]); o8[3] = fmaf(s, v0.w, o8[3]);
        o8[4] = fmaf(s, v1.x, o8[4]); o8[5] = fmaf(s, v1.y, o8[5]);
        o8[6] = fmaf(s, v1.z, o8[6]); o8[7] = fmaf(s, v1.w, o8[7]);
    }
    if (q < nq) {
        float* dst = g_att + (size_t)(bb * Ls + q0 + q) * Es + h * HDs + hb;
        *(float4*)dst       = make_float4(o8[0], o8[1], o8[2], o8[3]);
        *(float4*)(dst + 4) = make_float4(o8[4], o8[5], o8[6], o8[7]);
    }
}

// ============================================================
// launch
// ============================================================
extern "C" void kernel_launch(void* const* d_in, const int* in_sizes, int n_in,
                              void* d_out, int out_size)
{
    (void)in_sizes; (void)n_in; (void)out_size;
    const float* query   = (const float*)d_in[0];
    const float* key     = (const float*)d_in[1];
    const float* value   = (const float*)d_in[2];
    const float* indices = (const float*)d_in[3];
    const void*  mask    = d_in[4];
    const float* Wq      = (const float*)d_in[5];
    const float* bq      = (const float*)d_in[6];
    const float* Wk      = (const float*)d_in[7];
    const float* bk      = (const float*)d_in[8];
    const float* Wv      = (const float*)d_in[9];
    const float* Ww      = (const float*)d_in[10];
    const float* bw      = (const float*)d_in[11];
    const float* scale   = (const float*)d_in[12];
    const float* W1      = (const float*)d_in[13];
    const float* b1      = (const float*)d_in[14];
    const float* W2      = (const float*)d_in[15];
    const float* b2      = (const float*)d_in[16];
    float* out = (float*)d_out;

    float *pq, *pk, *pv, *patt;
    __nv_bfloat16 *pah, *pal, *pwh, *pwl;
    cudaGetSymbolAddress((void**)&pq,   g_q);
    cudaGetSymbolAddress((void**)&pk,   g_k);
    cudaGetSymbolAddress((void**)&pv,   g_v);
    cudaGetSymbolAddress((void**)&patt, g_att);
    cudaGetSymbolAddress((void**)&pah,  g_ah);
    cudaGetSymbolAddress((void**)&pal,  g_al);
    cudaGetSymbolAddress((void**)&pwh,  g_wh);
    cudaGetSymbolAddress((void**)&pwl,  g_wl);

    cudaFuncSetAttribute(tgemm_kernel, cudaFuncAttributeMaxDynamicSharedMemorySize,
                         TG_SMEM);
    cudaFuncSetAttribute(attn_kernel, cudaFuncAttributeMaxDynamicSharedMemorySize,
                         ATTN_SMEM_BYTES);

    const int n4 = ROWSs * Es / 4;
    const int splitg = (n4 + 255) / 256;
    const dim3 wsg(8, 8);
    const dim3 gg(ROWSs / 128, Es / 128);

    detect_mask_kernel<<<1, 256>>>((const unsigned int*)mask);
    bias_kernel<<<(LLs + 1023) / 1024, 256>>>(indices, W1, b1, W2, b2);

    // Q projection
    wsplit_kernel<<<wsg, 256>>>(Wq, pwh, pwl);
    split_kernel<<<splitg, 256>>>((const float4*)query, (ushort4*)pah, (ushort4*)pal, n4);
    tgemm_kernel<<<gg, 256, TG_SMEM>>>(pah, pal, pwh, pwl, bq, pq, 1);
    // K projection
    wsplit_kernel<<<wsg, 256>>>(Wk, pwh, pwl);
    split_kernel<<<splitg, 256>>>((const float4*)key, (ushort4*)pah, (ushort4*)pal, n4);
    tgemm_kernel<<<gg, 256, TG_SMEM>>>(pah, pal, pwh, pwl, bk, pk, 1);
    // V projection
    wsplit_kernel<<<wsg, 256>>>(Wv, pwh, pwl);
    split_kernel<<<splitg, 256>>>((const float4*)value, (ushort4*)pah, (ushort4*)pal, n4);
    tgemm_kernel<<<gg, 256, TG_SMEM>>>(pah, pal, pwh, pwl, nullptr, pv, 1);

    // normalize + attention
    {
        long long warps = 2LL * BBs * Hs * Ls;
        int blocks = (int)((warps * 32 + 255) / 256);
        norm_kernel<<<blocks, 256>>>();
    }
    attn_kernel<<<dim3((Ls + 63) / 64, Hs, BBs), 256, ATTN_SMEM_BYTES>>>(mask, scale);

    // output projection
    wsplit_kernel<<<wsg, 256>>>(Ww, pwh, pwl);
    split_kernel<<<splitg, 256>>>((const float4*)patt, (ushort4*)pah, (ushort4*)pal, n4);
    tgemm_kernel<<<gg, 256, TG_SMEM>>>(pah, pal, pwh, pwl, bw, out, 0);
}

// round 6
// speedup vs baseline: 2.4841x; 1.9020x over previous
#include <cuda_runtime.h>
#include <cuda_bf16.h>
#include <math.h>
#include <float.h>
#include <stdint.h>

// Problem dims
#define BBs   128
#define Ls    343
#define Es    256
#define Hs    8
#define HDs   32
#define HIDs  512
#define LLs   (Ls * Ls)       // 117649
#define ROWSs (BBs * Ls)      // 43904
#define LPAD  344             // padded row stride for bias/mask tables

// -------- scratch (device globals; no allocation allowed) --------
__device__ float g_q[BBs * Hs * Ls * HDs];
__device__ float g_k[BBs * Hs * Ls * HDs];
__device__ float g_v[BBs * Hs * Ls * HDs];
__device__ float g_bias[Hs * Ls * LPAD];
__device__ float g_att[ROWSs * Es];
__device__ int   g_mask_mode;
__device__ uint8_t g_mask8[BBs * Ls * LPAD];
__device__ __nv_bfloat16 g_ah[ROWSs * Es];
__device__ __nv_bfloat16 g_al[ROWSs * Es];
__device__ __nv_bfloat16 g_wh[Es * Es];
__device__ __nv_bfloat16 g_wl[Es * Es];
// bf16 hi/lo operands for tensorized attention
__device__ __nv_bfloat16 g_qh[BBs * Hs * Ls * HDs];
__device__ __nv_bfloat16 g_ql[BBs * Hs * Ls * HDs];
__device__ __nv_bfloat16 g_kh[BBs * Hs * Ls * HDs];
__device__ __nv_bfloat16 g_kl[BBs * Hs * Ls * HDs];
__device__ __nv_bfloat16 g_vh[BBs * Hs * Ls * HDs];
__device__ __nv_bfloat16 g_vl[BBs * Hs * Ls * HDs];

// ============================================================
// PTX helpers (baseline sm_80+ ISA; harness targets sm_103 w/o 'a')
// ============================================================
__device__ __forceinline__ uint32_t smem_u32(const void* p) {
    uint32_t a;
    asm("{ .reg .u64 t; cvta.to.shared.u64 t, %1; cvt.u32.u64 %0, t; }" : "=r"(a) : "l"(p));
    return a;
}
__device__ __forceinline__ void ldsm_x4(uint32_t& r0, uint32_t& r1, uint32_t& r2,
                                        uint32_t& r3, uint32_t addr) {
    asm volatile("ldmatrix.sync.aligned.m8n8.x4.shared.b16 {%0,%1,%2,%3}, [%4];"
                 : "=r"(r0), "=r"(r1), "=r"(r2), "=r"(r3) : "r"(addr));
}
__device__ __forceinline__ void ldsm_x4_t(uint32_t& r0, uint32_t& r1, uint32_t& r2,
                                          uint32_t& r3, uint32_t addr) {
    asm volatile("ldmatrix.sync.aligned.m8n8.x4.trans.shared.b16 {%0,%1,%2,%3}, [%4];"
                 : "=r"(r0), "=r"(r1), "=r"(r2), "=r"(r3) : "r"(addr));
}
__device__ __forceinline__ void mma16816(float* c, const uint32_t* a,
                                         uint32_t b0, uint32_t b1) {
    asm volatile(
        "mma.sync.aligned.m16n8k16.row.col.f32.bf16.bf16.f32 "
        "{%0,%1,%2,%3}, {%4,%5,%6,%7}, {%8,%9}, {%0,%1,%2,%3};"
        : "+f"(c[0]), "+f"(c[1]), "+f"(c[2]), "+f"(c[3])
        : "r"(a[0]), "r"(a[1]), "r"(a[2]), "r"(a[3]), "r"(b0), "r"(b1));
}
__device__ __forceinline__ void cp_async16(uint32_t dst, const void* src) {
    asm volatile("cp.async.cg.shared.global [%0], [%1], 16;" :: "r"(dst), "l"(src));
}
__device__ __forceinline__ void cp_commit() { asm volatile("cp.async.commit_group;"); }
__device__ __forceinline__ void cp_wait1() { asm volatile("cp.async.wait_group 1;"); }
__device__ __forceinline__ void cp_wait0() { asm volatile("cp.async.wait_group 0;"); }

__device__ __forceinline__ uint32_t packbf(float a, float b) {
    __nv_bfloat162 t = __floats2bfloat162_rn(a, b);
    return *(uint32_t*)&t;
}

// Fast exp on FMA/ALU pipes only (no MUFU). rel err ~2.4e-6.
__device__ __forceinline__ float fexp(float x) {
    float y = fmaxf(x * 1.4426950408889634f, -126.0f);
    float yr = __fadd_rn(y, 12582912.0f);
    float n  = __fsub_rn(yr, 12582912.0f);
    float f  = __fsub_rn(y, n);
    float p  = 1.3333558e-3f;
    p = fmaf(p, f, 9.6181291e-3f);
    p = fmaf(p, f, 5.5504109e-2f);
    p = fmaf(p, f, 2.4022651e-1f);
    p = fmaf(p, f, 6.9314718e-1f);
    p = fmaf(p, f, 1.0f);
    return __int_as_float(__float_as_int(p) + (__float_as_int(yr) << 23));
}

// ============================================================
// Kernel 0: detect mask dtype
// ============================================================
__global__ void detect_mask_kernel(const unsigned int* __restrict__ m)
{
    __shared__ int s_float, s_multi;
    if (threadIdx.x == 0) { s_float = 0; s_multi = 0; }
    __syncthreads();
    for (int i = threadIdx.x; i < 4096; i += 256) {
        unsigned int w = m[i];
        if (w == 0x3F800000u) atomicOr(&s_float, 1);
        else if (w != 0u && (w & 0xFFFFFF00u) != 0u) atomicOr(&s_multi, 1);
    }
    __syncthreads();
    if (threadIdx.x == 0)
        g_mask_mode = s_float ? 2 : (s_multi ? 0 : 1);
}

// ============================================================
// Kernel 0b: normalize mask to padded uint8 table
// ============================================================
__global__ __launch_bounds__(256) void mask_prep_kernel(const void* __restrict__ maskp)
{
    int idx = blockIdx.x * 256 + threadIdx.x;
    if (idx >= BBs * LLs) return;
    int bb = idx / LLs;
    int p = idx - bb * LLs;
    int i = p / Ls, j = p - i * Ls;
    int mode = g_mask_mode;
    bool m = (mode == 0) ? (((const uint8_t*)maskp)[idx] != 0)
           : (mode == 1) ? (((const int*)maskp)[idx] != 0)
                         : (((const float*)maskp)[idx] != 0.0f);
    g_mask8[(size_t)bb * (Ls * LPAD) + i * LPAD + j] = m ? 1 : 0;
}

// ============================================================
// Kernel 1: CPB bias table (padded stride LPAD)
// ============================================================
__global__ __launch_bounds__(256) void bias_kernel(
    const float* __restrict__ indices, const float* __restrict__ W1,
    const float* __restrict__ b1, const float* __restrict__ W2,
    const float* __restrict__ b2)
{
    __shared__ float sW1[3 * HIDs];
    __shared__ float sb1[HIDs];
    __shared__ float sW2[HIDs * Hs];
    for (int i = threadIdx.x; i < 3 * HIDs; i += 256) sW1[i] = W1[i];
    for (int i = threadIdx.x; i < HIDs;     i += 256) sb1[i] = b1[i];
    for (int i = threadIdx.x; i < HIDs * Hs; i += 256) sW2[i] = W2[i];
    __syncthreads();

    const int p0 = blockIdx.x * 1024 + threadIdx.x;
    float x[4][3];
    bool valid[4];
#pragma unroll
    for (int k = 0; k < 4; k++) {
        int p = p0 + k * 256;
        valid[k] = (p < LLs);
        int pp = valid[k] ? p : 0;
#pragma unroll
        for (int c = 0; c < 3; c++) {
            float xv = indices[pp * 3 + c];
            x[k][c] = copysignf(log2f(1.0f + fabsf(xv)) * (1.0f / 3.0f), xv);
        }
    }
    float acc[4][8];
#pragma unroll
    for (int k = 0; k < 4; k++)
#pragma unroll
        for (int h = 0; h < 8; h++) acc[k][h] = 0.0f;

    for (int t = 0; t < HIDs; t++) {
        float w0 = sW1[t], w1 = sW1[HIDs + t], w2 = sW1[2 * HIDs + t];
        float bb1 = sb1[t];
        float hv[4];
#pragma unroll
        for (int k = 0; k < 4; k++)
            hv[k] = fmaxf(fmaf(x[k][0], w0, fmaf(x[k][1], w1, fmaf(x[k][2], w2, bb1))), 0.0f);
#pragma unroll
        for (int h = 0; h < 8; h++) {
            float w = sW2[t * 8 + h];
#pragma unroll
            for (int k = 0; k < 4; k++) acc[k][h] = fmaf(hv[k], w, acc[k][h]);
        }
    }
#pragma unroll
    for (int k = 0; k < 4; k++) {
        if (!valid[k]) continue;
        int p = p0 + k * 256;
        int ii = p / Ls, jj = p - ii * Ls;
#pragma unroll
        for (int h = 0; h < 8; h++) {
            float z = acc[k][h] + b2[h];
            g_bias[(size_t)h * (Ls * LPAD) + ii * LPAD + jj] = 16.0f / (1.0f + fexp(-z));
        }
    }
}

// ============================================================
// Kernel 2a: split fp32 -> bf16 hi/lo (elementwise, any layout)
// ============================================================
__global__ __launch_bounds__(256) void split_kernel(
    const float4* __restrict__ in, ushort4* __restrict__ hi,
    ushort4* __restrict__ lo, int n4)
{
    int i = blockIdx.x * 256 + threadIdx.x;
    if (i >= n4) return;
    float4 v = in[i];
    __nv_bfloat16 h0 = __float2bfloat16(v.x), h1 = __float2bfloat16(v.y);
    __nv_bfloat16 h2 = __float2bfloat16(v.z), h3 = __float2bfloat16(v.w);
    __nv_bfloat16 l0 = __float2bfloat16(v.x - __bfloat162float(h0));
    __nv_bfloat16 l1 = __float2bfloat16(v.y - __bfloat162float(h1));
    __nv_bfloat16 l2 = __float2bfloat16(v.z - __bfloat162float(h2));
    __nv_bfloat16 l3 = __float2bfloat16(v.w - __bfloat162float(h3));
    ushort4 hv = { __bfloat16_as_ushort(h0), __bfloat16_as_ushort(h1),
                   __bfloat16_as_ushort(h2), __bfloat16_as_ushort(h3) };
    ushort4 lv = { __bfloat16_as_ushort(l0), __bfloat16_as_ushort(l1),
                   __bfloat16_as_ushort(l2), __bfloat16_as_ushort(l3) };
    hi[i] = hv; lo[i] = lv;
}

// ============================================================
// Kernel 2b: weight transpose + split
// ============================================================
__global__ __launch_bounds__(256) void wsplit_kernel(
    const float* __restrict__ W, __nv_bfloat16* __restrict__ ht,
    __nv_bfloat16* __restrict__ lt)
{
    __shared__ float t[32][33];
    int bn = blockIdx.x * 32, bk = blockIdx.y * 32;
    int lx = threadIdx.x & 31, ly = threadIdx.x >> 5;
    for (int yy = ly; yy < 32; yy += 8)
        t[yy][lx] = W[(size_t)(bk + yy) * Es + bn + lx];
    __syncthreads();
    for (int yy = ly; yy < 32; yy += 8) {
        float v = t[lx][yy];
        __nv_bfloat16 h = __float2bfloat16(v);
        __nv_bfloat16 l = __float2bfloat16(v - __bfloat162float(h));
        size_t o = (size_t)(bn + yy) * Es + bk + lx;
        ht[o] = h; lt[o] = l;
    }
}

// ============================================================
// Kernel 3: mma.sync bf16 split-GEMM (validated)
// ============================================================
#define TGS 72
#define STAGE_B (128 * TGS * 2)
#define TG_SMEM (4 * STAGE_B)

__global__ __launch_bounds__(256) void tgemm_kernel(
    const __nv_bfloat16* __restrict__ Ah, const __nv_bfloat16* __restrict__ Al,
    const __nv_bfloat16* __restrict__ Wh, const __nv_bfloat16* __restrict__ Wl,
    const float* __restrict__ bias, float* __restrict__ C, int remap)
{
    extern __shared__ char dsm[];
    const int tid = threadIdx.x;
    const int wid = tid >> 5;
    const int lane = tid & 31;
    const int m0 = blockIdx.x * 128;
    const int n0 = blockIdx.y * 128;
    const int wm = wid & 1;
    const int wn = wid >> 1;
    const uint32_t smb = smem_u32(dsm);

    float c[4][4][4];
#pragma unroll
    for (int i = 0; i < 4; i++)
#pragma unroll
        for (int j = 0; j < 4; j++)
#pragma unroll
            for (int k = 0; k < 4; k++) c[i][j][k] = 0.0f;

    auto prefetch = [&](int i) {
        const int t = i >> 2, kc = i & 3, s = i & 1;
        const __nv_bfloat16* As = (t == 1) ? Al : Ah;
        const __nv_bfloat16* Bs = (t == 2) ? Wl : Wh;
        const int k0 = kc * 64;
        const uint32_t bA = smb + s * 2 * STAGE_B;
        const uint32_t bB = bA + STAGE_B;
#pragma unroll
        for (int j = 0; j < 4; j++) {
            int x = tid + j * 256;
            int r = x >> 3, cc = x & 7;
            uint32_t off = (uint32_t)(r * TGS + cc * 8) * 2;
            cp_async16(bA + off, As + (size_t)(m0 + r) * Es + k0 + cc * 8);
            cp_async16(bB + off, Bs + (size_t)(n0 + r) * Es + k0 + cc * 8);
        }
    };

    prefetch(0);
    cp_commit();

    const int arow = (lane & 7) + ((lane >> 3) & 1) * 8;
    const int acolo = ((lane >> 4) & 1) * 8;
    const int brow = (lane & 7) + ((lane >> 4) & 1) * 8;
    const int bcolo = ((lane >> 3) & 1) * 8;

    for (int i = 0; i < 12; i++) {
        if (i < 11) { prefetch(i + 1); cp_commit(); }
        if (i < 11) cp_wait1(); else cp_wait0();
        __syncthreads();

        const uint32_t bA = smb + (i & 1) * 2 * STAGE_B;
        const uint32_t bB = bA + STAGE_B;
#pragma unroll
        for (int ks = 0; ks < 4; ks++) {
            const int k0 = ks * 16;
            uint32_t a[4][4], b[2][4];
#pragma unroll
            for (int mt = 0; mt < 4; mt++)
                ldsm_x4(a[mt][0], a[mt][1], a[mt][2], a[mt][3],
                        bA + (uint32_t)((wm * 64 + mt * 16 + arow) * TGS + k0 + acolo) * 2);
#pragma unroll
            for (int g = 0; g < 2; g++)
                ldsm_x4(b[g][0], b[g][1], b[g][2], b[g][3],
                        bB + (uint32_t)((wn * 32 + g * 16 + brow) * TGS + k0 + bcolo) * 2);
#pragma unroll
            for (int mt = 0; mt < 4; mt++)
#pragma unroll
                for (int nt = 0; nt < 4; nt++)
                    mma16816(c[mt][nt], a[mt], b[nt >> 1][(nt & 1) * 2],
                             b[nt >> 1][(nt & 1) * 2 + 1]);
        }
        __syncthreads();
    }

    const int tq = lane >> 2;
    const int tr = lane & 3;
#pragma unroll
    for (int mt = 0; mt < 4; mt++) {
        const int m = m0 + wm * 64 + mt * 16 + tq;
#pragma unroll
        for (int nt = 0; nt < 4; nt++) {
            const int n = n0 + wn * 32 + nt * 8 + tr * 2;
            float2 v0 = make_float2(c[mt][nt][0], c[mt][nt][1]);
            float2 v1 = make_float2(c[mt][nt][2], c[mt][nt][3]);
            if (bias) {
                float2 bv = *(const float2*)(bias + n);
                v0.x += bv.x; v0.y += bv.y;
                v1.x += bv.x; v1.y += bv.y;
            }
            if (remap) {
                const int h = n >> 5, hd = n & 31;
                int bbw = m / Ls, l = m - bbw * Ls;
                *(float2*)(C + ((size_t)(bbw * Hs + h) * Ls + l) * HDs + hd) = v0;
                int m2 = m + 8;
                int bbw2 = m2 / Ls, l2 = m2 - bbw2 * Ls;
                *(float2*)(C + ((size_t)(bbw2 * Hs + h) * Ls + l2) * HDs + hd) = v1;
            } else {
                *(float2*)(C + (size_t)m * Es + n) = v0;
                *(float2*)(C + (size_t)(m + 8) * Es + n) = v1;
            }
        }
    }
}

// ============================================================
// Kernel 4: L2-normalize q,k rows -> bf16 hi/lo operands
// ============================================================
__global__ __launch_bounds__(256) void norm_kernel()
{
    const int R = BBs * Hs * Ls;
    int gw = (blockIdx.x * blockDim.x + threadIdx.x) >> 5;
    int lane = threadIdx.x & 31;
    if (gw >= 2 * R) return;
    const float* src = (gw < R) ? g_q : g_k;
    __nv_bfloat16* dh = (gw < R) ? g_qh : g_kh;
    __nv_bfloat16* dl = (gw < R) ? g_ql : g_kl;
    int row = (gw < R) ? gw : gw - R;
    float v = src[(size_t)row * HDs + lane];
    float ss = v * v;
#pragma unroll
    for (int o = 16; o > 0; o >>= 1) ss += __shfl_xor_sync(0xffffffffu, ss, o);
    float vn = v / fmaxf(sqrtf(ss), 1e-12f);
    __nv_bfloat16 h = __float2bfloat16(vn);
    __nv_bfloat16 l = __float2bfloat16(vn - __bfloat162float(h));
    dh[(size_t)row * HDs + lane] = h;
    dl[(size_t)row * HDs + lane] = l;
}

// ============================================================
// Kernel 5: tensorized FA2-style attention.
// Block = (64 queries, head, window). 8 warps: wm=wid&3 (16 rows),
// wn=wid>>2 (176-key half, padded to 352 total).
// Phase1 S = QK^T via bf16-split mma (fragments), softmax on fragments,
// Phase3 O = PV via fragment-reuse + ldmatrix.trans V.
// ============================================================
#define ASTR 40                       // smem row stride (bf16) — conflict-free
#define OFF_KH 0
#define OFF_KL 28160
#define OFF_VH 56320
#define OFF_VL 84480
#define OFF_QH 112640
#define OFF_QL 117760
#define OFF_RMAX 122880
#define OFF_RSUM 123392
#define OFF_ORED 123904
#define ATT2_SMEM 132096

__global__ __launch_bounds__(256) void attn2_kernel(const float* __restrict__ scalep)
{
    extern __shared__ char sm2[];
    __nv_bfloat16* KhS = (__nv_bfloat16*)(sm2 + OFF_KH);
    __nv_bfloat16* KlS = (__nv_bfloat16*)(sm2 + OFF_KL);
    __nv_bfloat16* VhS = (__nv_bfloat16*)(sm2 + OFF_VH);
    __nv_bfloat16* VlS = (__nv_bfloat16*)(sm2 + OFF_VL);
    __nv_bfloat16* QhS = (__nv_bfloat16*)(sm2 + OFF_QH);
    __nv_bfloat16* QlS = (__nv_bfloat16*)(sm2 + OFF_QL);
    float* redmax = (float*)(sm2 + OFF_RMAX);   // [2][64]
    float* redsum = (float*)(sm2 + OFF_RSUM);   // [2][64]
    float* ored   = (float*)(sm2 + OFF_ORED);   // [64][32]
    const uint32_t smb = smem_u32(sm2);

    const int tid = threadIdx.x;
    const int wid = tid >> 5;
    const int lane = tid & 31;
    const int q0 = blockIdx.x * 64;
    const int h = blockIdx.y;
    const int bb = blockIdx.z;
    const size_t gbase = (size_t)(bb * Hs + h) * (Ls * HDs);

    // ---- cooperative smem fill ----
    for (int i = tid; i < 1372; i += 256) {         // 10976 bf16 / 8
        int row = i >> 2, c8 = (i & 3) * 8;
        int so = row * HDs + c8;
        int dof = row * ASTR + c8;
        *(uint4*)(KhS + dof) = *(const uint4*)(g_kh + gbase + so);
        *(uint4*)(KlS + dof) = *(const uint4*)(g_kl + gbase + so);
        *(uint4*)(VhS + dof) = *(const uint4*)(g_vh + gbase + so);
        *(uint4*)(VlS + dof) = *(const uint4*)(g_vl + gbase + so);
    }
    for (int i = tid; i < 9 * ASTR; i += 256) {     // zero pad rows 343..351
        int dof = (343 + i / ASTR) * ASTR + (i % ASTR);
        ((unsigned short*)KhS)[dof] = 0; ((unsigned short*)KlS)[dof] = 0;
        ((unsigned short*)VhS)[dof] = 0; ((unsigned short*)VlS)[dof] = 0;
    }
    {
        int row = tid >> 2, c8 = (tid & 3) * 8;
        int qr = q0 + row;
        uint4 zv = make_uint4(0, 0, 0, 0);
        uint4 vh = zv, vl = zv;
        if (qr < Ls) {
            vh = *(const uint4*)(g_qh + gbase + (size_t)qr * HDs + c8);
            vl = *(const uint4*)(g_ql + gbase + (size_t)qr * HDs + c8);
        }
        *(uint4*)(QhS + row * ASTR + c8) = vh;
        *(uint4*)(QlS + row * ASTR + c8) = vl;
    }
    __syncthreads();

    const int wm = wid & 3;
    const int wn = wid >> 2;
    const int nbase = wn * 176;

    // ---- phase 1: S fragments ----
    const int arow = (lane & 7) + ((lane >> 3) & 1) * 8;
    const int acolo = ((lane >> 4) & 1) * 8;
    const int brow = (lane & 7) + ((lane >> 4) & 1) * 8;
    const int bcolo = ((lane >> 3) & 1) * 8;

    uint32_t qh[2][4], ql[2][4];
#pragma unroll
    for (int kk = 0; kk < 2; kk++) {
        uint32_t ad = smb + OFF_QH + (uint32_t)((wm * 16 + arow) * ASTR + kk * 16 + acolo) * 2;
        ldsm_x4(qh[kk][0], qh[kk][1], qh[kk][2], qh[kk][3], ad);
        ad = smb + OFF_QL + (uint32_t)((wm * 16 + arow) * ASTR + kk * 16 + acolo) * 2;
        ldsm_x4(ql[kk][0], ql[kk][1], ql[kk][2], ql[kk][3], ad);
    }

    float c[22][4];
#pragma unroll
    for (int t = 0; t < 22; t++)
#pragma unroll
        for (int e = 0; e < 4; e++) c[t][e] = 0.0f;

#pragma unroll
    for (int np = 0; np < 11; np++) {
        uint32_t bh[2][4], bl[2][4];
#pragma unroll
        for (int kk = 0; kk < 2; kk++) {
            uint32_t rb = (uint32_t)((nbase + np * 16 + brow) * ASTR + kk * 16 + bcolo) * 2;
            ldsm_x4(bh[kk][0], bh[kk][1], bh[kk][2], bh[kk][3], smb + OFF_KH + rb);
            ldsm_x4(bl[kk][0], bl[kk][1], bl[kk][2], bl[kk][3], smb + OFF_KL + rb);
        }
#pragma unroll
        for (int kk = 0; kk < 2; kk++)
#pragma unroll
            for (int nt = 0; nt < 2; nt++) {
                float* cc = c[np * 2 + nt];
                mma16816(cc, qh[kk], bh[kk][nt * 2], bh[kk][nt * 2 + 1]);
                mma16816(cc, ql[kk], bh[kk][nt * 2], bh[kk][nt * 2 + 1]);
                mma16816(cc, qh[kk], bl[kk][nt * 2], bl[kk][nt * 2 + 1]);
            }
    }

    // ---- scale + bias + mask on fragments ----
    const float invscale = 1.0f / fmaxf(scalep[0], 0.01f);
    const float* bias0 = g_bias + (size_t)h * (Ls * LPAD);
    const uint8_t* mrow = g_mask8 + (size_t)bb * (Ls * LPAD);
    const int r0 = wm * 16 + (lane >> 2);
    const int r1 = r0 + 8;
    const int qrow0 = q0 + r0, qrow1 = q0 + r1;
    const bool rv0 = qrow0 < Ls, rv1 = qrow1 < Ls;

#pragma unroll
    for (int t = 0; t < 22; t++) {
        int col = nbase + t * 8 + (lane & 3) * 2;
        bool cv0 = col < Ls, cv1 = (col + 1) < Ls;
        float2 b0v = make_float2(0.f, 0.f), b1v = make_float2(0.f, 0.f);
        uchar2 m0v = make_uchar2(0, 0), m1v = make_uchar2(0, 0);
        if (rv0 && cv0) {
            b0v = *(const float2*)(bias0 + (size_t)qrow0 * LPAD + col);
            m0v = *(const uchar2*)(mrow + (size_t)qrow0 * LPAD + col);
        }
        if (rv1 && cv0) {
            b1v = *(const float2*)(bias0 + (size_t)qrow1 * LPAD + col);
            m1v = *(const uchar2*)(mrow + (size_t)qrow1 * LPAD + col);
        }
        c[t][0] = (rv0 && cv0) ? (m0v.x ? -100000.0f : fmaf(c[t][0], invscale, b0v.x)) : -1e9f;
        c[t][1] = (rv0 && cv1) ? (m0v.y ? -100000.0f : fmaf(c[t][1], invscale, b0v.y)) : -1e9f;
        c[t][2] = (rv1 && cv0) ? (m1v.x ? -100000.0f : fmaf(c[t][2], invscale, b1v.x)) : -1e9f;
        c[t][3] = (rv1 && cv1) ? (m1v.y ? -100000.0f : fmaf(c[t][3], invscale, b1v.y)) : -1e9f;
    }

    // ---- softmax on fragments ----
    float mx0 = -FLT_MAX, mx1 = -FLT_MAX;
#pragma unroll
    for (int t = 0; t < 22; t++) {
        mx0 = fmaxf(mx0, fmaxf(c[t][0], c[t][1]));
        mx1 = fmaxf(mx1, fmaxf(c[t][2], c[t][3]));
    }
    mx0 = fmaxf(mx0, __shfl_xor_sync(0xffffffffu, mx0, 1));
    mx0 = fmaxf(mx0, __shfl_xor_sync(0xffffffffu, mx0, 2));
    mx1 = fmaxf(mx1, __shfl_xor_sync(0xffffffffu, mx1, 1));
    mx1 = fmaxf(mx1, __shfl_xor_sync(0xffffffffu, mx1, 2));
    if ((lane & 3) == 0) {
        redmax[wn * 64 + r0] = mx0;
        redmax[wn * 64 + r1] = mx1;
    }
    __syncthreads();
    mx0 = fmaxf(redmax[r0], redmax[64 + r0]);
    mx1 = fmaxf(redmax[r1], redmax[64 + r1]);

    float s0 = 0.0f, s1 = 0.0f;
#pragma unroll
    for (int t = 0; t < 22; t++) {
        float e0 = fexp(c[t][0] - mx0); c[t][0] = e0; s0 += e0;
        float e1 = fexp(c[t][1] - mx0); c[t][1] = e1; s0 += e1;
        float e2 = fexp(c[t][2] - mx1); c[t][2] = e2; s1 += e2;
        float e3 = fexp(c[t][3] - mx1); c[t][3] = e3; s1 += e3;
    }
    s0 += __shfl_xor_sync(0xffffffffu, s0, 1);
    s0 += __shfl_xor_sync(0xffffffffu, s0, 2);
    s1 += __shfl_xor_sync(0xffffffffu, s1, 1);
    s1 += __shfl_xor_sync(0xffffffffu, s1, 2);
    if ((lane & 3) == 0) {
        redsum[wn * 64 + r0] = s0;
        redsum[wn * 64 + r1] = s1;
    }
    __syncthreads();
    const float inv0 = 1.0f / (redsum[r0] + redsum[64 + r0]);
    const float inv1 = 1.0f / (redsum[r1] + redsum[64 + r1]);
#pragma unroll
    for (int t = 0; t < 22; t++) {
        c[t][0] *= inv0; c[t][1] *= inv0;
        c[t][2] *= inv1; c[t][3] *= inv1;
    }

    // ---- phase 3: O = P V (fragment reuse + trans ldmatrix V) ----
    float oc[4][4];
#pragma unroll
    for (int nt = 0; nt < 4; nt++)
#pragma unroll
        for (int e = 0; e < 4; e++) oc[nt][e] = 0.0f;

    const int vrow = (lane & 7) + ((lane >> 3) & 1) * 8;
    const int vcolo = ((lane >> 4) & 1) * 8;

#pragma unroll
    for (int kt = 0; kt < 11; kt++) {
        // pack P hi/lo from S fragments (A-operand layout)
        uint32_t ph[4], pl[4];
#pragma unroll
        for (int half = 0; half < 2; half++) {
            const float* cc = c[2 * kt + half];
            __nv_bfloat16 h0 = __float2bfloat16(cc[0]);
            __nv_bfloat16 h1 = __float2bfloat16(cc[1]);
            __nv_bfloat16 h2 = __float2bfloat16(cc[2]);
            __nv_bfloat16 h3 = __float2bfloat16(cc[3]);
            ph[half * 2 + 0] = packbf(__bfloat162float(h0), __bfloat162float(h1));
            ph[half * 2 + 1] = packbf(__bfloat162float(h2), __bfloat162float(h3));
            pl[half * 2 + 0] = packbf(cc[0] - __bfloat162float(h0), cc[1] - __bfloat162float(h1));
            pl[half * 2 + 1] = packbf(cc[2] - __bfloat162float(h2), cc[3] - __bfloat162float(h3));
        }
        // Hmm: a-order must be {a0,a1,a2,a3} = {E(c0,c1), E(c2,c3), O(c0,c1), O(c2,c3)}
        // half0 -> indices 0,1 ; half1 -> 2,3  (as written)  ✓

        const int krow = nbase + kt * 16;
        uint32_t vh[2][4], vl[2][4];
#pragma unroll
        for (int g = 0; g < 2; g++) {
            uint32_t ad = (uint32_t)((krow + vrow) * ASTR + g * 16 + vcolo) * 2;
            ldsm_x4_t(vh[g][0], vh[g][1], vh[g][2], vh[g][3], smb + OFF_VH + ad);
            ldsm_x4_t(vl[g][0], vl[g][1], vl[g][2], vl[g][3], smb + OFF_VL + ad);
        }
#pragma unroll
        for (int nt = 0; nt < 4; nt++) {
            const int g = nt >> 1, i2 = (nt & 1) * 2;
            mma16816(oc[nt], ph, vh[g][i2], vh[g][i2 + 1]);
            mma16816(oc[nt], pl, vh[g][i2], vh[g][i2 + 1]);
            mma16816(oc[nt], ph, vl[g][i2], vl[g][i2 + 1]);
        }
    }

    // ---- cross-half O reduction + store ----
    __syncthreads();   // red buffers / V reads done before ored reuse region touched
    const int ncol = (lane & 3) * 2;
    if (wn == 1) {
#pragma unroll
        for (int nt = 0; nt < 4; nt++) {
            *(float2*)(ored + r0 * 32 + nt * 8 + ncol) = make_float2(oc[nt][0], oc[nt][1]);
            *(float2*)(ored + r1 * 32 + nt * 8 + ncol) = make_float2(oc[nt][2], oc[nt][3]);
        }
    }
    __syncthreads();
    if (wn == 0) {
#pragma unroll
        for (int nt = 0; nt < 4; nt++) {
            float2 t0 = *(float2*)(ored + r0 * 32 + nt * 8 + ncol);
            float2 t1 = *(float2*)(ored + r1 * 32 + nt * 8 + ncol);
            if (rv0)
                *(float2*)(g_att + (size_t)(bb * Ls + qrow0) * Es + h * HDs + nt * 8 + ncol) =
                    make_float2(oc[nt][0] + t0.x, oc[nt][1] + t0.y);
            if (rv1)
                *(float2*)(g_att + (size_t)(bb * Ls + qrow1) * Es + h * HDs + nt * 8 + ncol) =
                    make_float2(oc[nt][2] + t1.x, oc[nt][3] + t1.y);
        }
    }
}

// ============================================================
// launch
// ============================================================
extern "C" void kernel_launch(void* const* d_in, const int* in_sizes, int n_in,
                              void* d_out, int out_size)
{
    (void)in_sizes; (void)n_in; (void)out_size;
    const float* query   = (const float*)d_in[0];
    const float* key     = (const float*)d_in[1];
    const float* value   = (const float*)d_in[2];
    const float* indices = (const float*)d_in[3];
    const void*  mask    = d_in[4];
    const float* Wq      = (const float*)d_in[5];
    const float* bq      = (const float*)d_in[6];
    const float* Wk      = (const float*)d_in[7];
    const float* bk      = (const float*)d_in[8];
    const float* Wv      = (const float*)d_in[9];
    const float* Ww      = (const float*)d_in[10];
    const float* bw      = (const float*)d_in[11];
    const float* scale   = (const float*)d_in[12];
    const float* W1      = (const float*)d_in[13];
    const float* b1      = (const float*)d_in[14];
    const float* W2      = (const float*)d_in[15];
    const float* b2      = (const float*)d_in[16];
    float* out = (float*)d_out;

    float *pq, *pk, *pv, *patt;
    __nv_bfloat16 *pah, *pal, *pwh, *pwl, *pvh, *pvl;
    cudaGetSymbolAddress((void**)&pq,   g_q);
    cudaGetSymbolAddress((void**)&pk,   g_k);
    cudaGetSymbolAddress((void**)&pv,   g_v);
    cudaGetSymbolAddress((void**)&patt, g_att);
    cudaGetSymbolAddress((void**)&pah,  g_ah);
    cudaGetSymbolAddress((void**)&pal,  g_al);
    cudaGetSymbolAddress((void**)&pwh,  g_wh);
    cudaGetSymbolAddress((void**)&pwl,  g_wl);
    cudaGetSymbolAddress((void**)&pvh,  g_vh);
    cudaGetSymbolAddress((void**)&pvl,  g_vl);

    cudaFuncSetAttribute(tgemm_kernel, cudaFuncAttributeMaxDynamicSharedMemorySize,
                         TG_SMEM);
    cudaFuncSetAttribute(attn2_kernel, cudaFuncAttributeMaxDynamicSharedMemorySize,
                         ATT2_SMEM);

    const int n4 = ROWSs * Es / 4;
    const int splitg = (n4 + 255) / 256;
    const dim3 wsg(8, 8);
    const dim3 gg(ROWSs / 128, Es / 128);

    detect_mask_kernel<<<1, 256>>>((const unsigned int*)mask);
    mask_prep_kernel<<<(BBs * LLs + 255) / 256, 256>>>(mask);
    bias_kernel<<<(LLs + 1023) / 1024, 256>>>(indices, W1, b1, W2, b2);

    // Q projection
    wsplit_kernel<<<wsg, 256>>>(Wq, pwh, pwl);
    split_kernel<<<splitg, 256>>>((const float4*)query, (ushort4*)pah, (ushort4*)pal, n4);
    tgemm_kernel<<<gg, 256, TG_SMEM>>>(pah, pal, pwh, pwl, bq, pq, 1);
    // K projection
    wsplit_kernel<<<wsg, 256>>>(Wk, pwh, pwl);
    split_kernel<<<splitg, 256>>>((const float4*)key, (ushort4*)pah, (ushort4*)pal, n4);
    tgemm_kernel<<<gg, 256, TG_SMEM>>>(pah, pal, pwh, pwl, bk, pk, 1);
    // V projection
    wsplit_kernel<<<wsg, 256>>>(Wv, pwh, pwl);
    split_kernel<<<splitg, 256>>>((const float4*)value, (ushort4*)pah, (ushort4*)pal, n4);
    tgemm_kernel<<<gg, 256, TG_SMEM>>>(pah, pal, pwh, pwl, nullptr, pv, 1);

    // V -> bf16 hi/lo (head-split layout, elementwise)
    split_kernel<<<(ROWSs * Es / 4 + 255) / 256, 256>>>(
        (const float4*)pv, (ushort4*)pvh, (ushort4*)pvl, ROWSs * Es / 4);

    // normalize q,k -> bf16 hi/lo
    {
        long long warps = 2LL * BBs * Hs * Ls;
        int blocks = (int)((warps * 32 + 255) / 256);
        norm_kernel<<<blocks, 256>>>();
    }

    // tensorized attention
    attn2_kernel<<<dim3((Ls + 63) / 64, Hs, BBs), 256, ATT2_SMEM>>>(scale);

    // output projection
    wsplit_kernel<<<wsg, 256>>>(Ww, pwh, pwl);
    split_kernel<<<splitg, 256>>>((const float4*)patt, (ushort4*)pah, (ushort4*)pal, n4);
    tgemm_kernel<<<gg, 256, TG_SMEM>>>(pah, pal, pwh, pwl, bw, out, 0);
}

// round 7
// speedup vs baseline: 2.5769x; 1.0374x over previous
#include <cuda_runtime.h>
#include <cuda_bf16.h>
#include <math.h>
#include <float.h>
#include <stdint.h>

// Problem dims
#define BBs   128
#define Ls    343
#define Es    256
#define Hs    8
#define HDs   32
#define HIDs  512
#define LLs   (Ls * Ls)       // 117649
#define ROWSs (BBs * Ls)      // 43904
#define LPAD  344

// -------- scratch (device globals; no allocation allowed) --------
__device__ float g_q[BBs * Hs * Ls * HDs];
__device__ float g_k[BBs * Hs * Ls * HDs];
__device__ float g_bias[Hs * Ls * LPAD];
__device__ int   g_mask_mode;
__device__ uint8_t g_mask8[BBs * Ls * LPAD];
__device__ __nv_bfloat16 g_ah[ROWSs * Es];
__device__ __nv_bfloat16 g_al[ROWSs * Es];
__device__ __nv_bfloat16 g_wh[Es * Es];
__device__ __nv_bfloat16 g_wl[Es * Es];
__device__ __nv_bfloat16 g_qh[BBs * Hs * Ls * HDs];
__device__ __nv_bfloat16 g_ql[BBs * Hs * Ls * HDs];
__device__ __nv_bfloat16 g_kh[BBs * Hs * Ls * HDs];
__device__ __nv_bfloat16 g_kl[BBs * Hs * Ls * HDs];
__device__ __nv_bfloat16 g_vh[BBs * Hs * Ls * HDs];
__device__ __nv_bfloat16 g_vl[BBs * Hs * Ls * HDs];

// ============================================================
// PTX helpers (baseline sm_80+ ISA; harness targets sm_103 w/o 'a')
// ============================================================
__device__ __forceinline__ uint32_t smem_u32(const void* p) {
    uint32_t a;
    asm("{ .reg .u64 t; cvta.to.shared.u64 t, %1; cvt.u32.u64 %0, t; }" : "=r"(a) : "l"(p));
    return a;
}
__device__ __forceinline__ void ldsm_x4(uint32_t& r0, uint32_t& r1, uint32_t& r2,
                                        uint32_t& r3, uint32_t addr) {
    asm volatile("ldmatrix.sync.aligned.m8n8.x4.shared.b16 {%0,%1,%2,%3}, [%4];"
                 : "=r"(r0), "=r"(r1), "=r"(r2), "=r"(r3) : "r"(addr));
}
__device__ __forceinline__ void ldsm_x4_t(uint32_t& r0, uint32_t& r1, uint32_t& r2,
                                          uint32_t& r3, uint32_t addr) {
    asm volatile("ldmatrix.sync.aligned.m8n8.x4.trans.shared.b16 {%0,%1,%2,%3}, [%4];"
                 : "=r"(r0), "=r"(r1), "=r"(r2), "=r"(r3) : "r"(addr));
}
__device__ __forceinline__ void mma16816(float* c, const uint32_t* a,
                                         uint32_t b0, uint32_t b1) {
    asm volatile(
        "mma.sync.aligned.m16n8k16.row.col.f32.bf16.bf16.f32 "
        "{%0,%1,%2,%3}, {%4,%5,%6,%7}, {%8,%9}, {%0,%1,%2,%3};"
        : "+f"(c[0]), "+f"(c[1]), "+f"(c[2]), "+f"(c[3])
        : "r"(a[0]), "r"(a[1]), "r"(a[2]), "r"(a[3]), "r"(b0), "r"(b1));
}
__device__ __forceinline__ void cp_async16(uint32_t dst, const void* src) {
    asm volatile("cp.async.cg.shared.global [%0], [%1], 16;" :: "r"(dst), "l"(src));
}
__device__ __forceinline__ void cp_commit() { asm volatile("cp.async.commit_group;"); }
__device__ __forceinline__ void cp_wait1() { asm volatile("cp.async.wait_group 1;"); }
__device__ __forceinline__ void cp_wait0() { asm volatile("cp.async.wait_group 0;"); }

__device__ __forceinline__ uint32_t packbf(float a, float b) {
    __nv_bfloat162 t = __floats2bfloat162_rn(a, b);
    return *(uint32_t*)&t;
}

// Fast exp on FMA/ALU pipes only (no MUFU). rel err ~2.4e-6.
__device__ __forceinline__ float fexp(float x) {
    float y = fmaxf(x * 1.4426950408889634f, -126.0f);
    float yr = __fadd_rn(y, 12582912.0f);
    float n  = __fsub_rn(yr, 12582912.0f);
    float f  = __fsub_rn(y, n);
    float p  = 1.3333558e-3f;
    p = fmaf(p, f, 9.6181291e-3f);
    p = fmaf(p, f, 5.5504109e-2f);
    p = fmaf(p, f, 2.4022651e-1f);
    p = fmaf(p, f, 6.9314718e-1f);
    p = fmaf(p, f, 1.0f);
    return __int_as_float(__float_as_int(p) + (__float_as_int(yr) << 23));
}

// ============================================================
// Kernel 0: detect mask dtype
// ============================================================
__global__ void detect_mask_kernel(const unsigned int* __restrict__ m)
{
    __shared__ int s_float, s_multi;
    if (threadIdx.x == 0) { s_float = 0; s_multi = 0; }
    __syncthreads();
    for (int i = threadIdx.x; i < 4096; i += 256) {
        unsigned int w = m[i];
        if (w == 0x3F800000u) atomicOr(&s_float, 1);
        else if (w != 0u && (w & 0xFFFFFF00u) != 0u) atomicOr(&s_multi, 1);
    }
    __syncthreads();
    if (threadIdx.x == 0)
        g_mask_mode = s_float ? 2 : (s_multi ? 0 : 1);
}

// ============================================================
// Kernel 0b: normalize mask to padded uint8 table
// ============================================================
__global__ __launch_bounds__(256) void mask_prep_kernel(const void* __restrict__ maskp)
{
    int idx = blockIdx.x * 256 + threadIdx.x;
    if (idx >= BBs * LLs) return;
    int bb = idx / LLs;
    int p = idx - bb * LLs;
    int i = p / Ls, j = p - i * Ls;
    int mode = g_mask_mode;
    bool m = (mode == 0) ? (((const uint8_t*)maskp)[idx] != 0)
           : (mode == 1) ? (((const int*)maskp)[idx] != 0)
                         : (((const float*)maskp)[idx] != 0.0f);
    g_mask8[(size_t)bb * (Ls * LPAD) + i * LPAD + j] = m ? 1 : 0;
}

// ============================================================
// Kernel 1: CPB bias table (padded stride LPAD)
// ============================================================
__global__ __launch_bounds__(256) void bias_kernel(
    const float* __restrict__ indices, const float* __restrict__ W1,
    const float* __restrict__ b1, const float* __restrict__ W2,
    const float* __restrict__ b2)
{
    __shared__ float sW1[3 * HIDs];
    __shared__ float sb1[HIDs];
    __shared__ float sW2[HIDs * Hs];
    for (int i = threadIdx.x; i < 3 * HIDs; i += 256) sW1[i] = W1[i];
    for (int i = threadIdx.x; i < HIDs;     i += 256) sb1[i] = b1[i];
    for (int i = threadIdx.x; i < HIDs * Hs; i += 256) sW2[i] = W2[i];
    __syncthreads();

    const int p0 = blockIdx.x * 1024 + threadIdx.x;
    float x[4][3];
    bool valid[4];
#pragma unroll
    for (int k = 0; k < 4; k++) {
        int p = p0 + k * 256;
        valid[k] = (p < LLs);
        int pp = valid[k] ? p : 0;
#pragma unroll
        for (int c = 0; c < 3; c++) {
            float xv = indices[pp * 3 + c];
            x[k][c] = copysignf(log2f(1.0f + fabsf(xv)) * (1.0f / 3.0f), xv);
        }
    }
    float acc[4][8];
#pragma unroll
    for (int k = 0; k < 4; k++)
#pragma unroll
        for (int h = 0; h < 8; h++) acc[k][h] = 0.0f;

    for (int t = 0; t < HIDs; t++) {
        float w0 = sW1[t], w1 = sW1[HIDs + t], w2 = sW1[2 * HIDs + t];
        float bb1 = sb1[t];
        float hv[4];
#pragma unroll
        for (int k = 0; k < 4; k++)
            hv[k] = fmaxf(fmaf(x[k][0], w0, fmaf(x[k][1], w1, fmaf(x[k][2], w2, bb1))), 0.0f);
#pragma unroll
        for (int h = 0; h < 8; h++) {
            float w = sW2[t * 8 + h];
#pragma unroll
            for (int k = 0; k < 4; k++) acc[k][h] = fmaf(hv[k], w, acc[k][h]);
        }
    }
#pragma unroll
    for (int k = 0; k < 4; k++) {
        if (!valid[k]) continue;
        int p = p0 + k * 256;
        int ii = p / Ls, jj = p - ii * Ls;
#pragma unroll
        for (int h = 0; h < 8; h++) {
            float z = acc[k][h] + b2[h];
            g_bias[(size_t)h * (Ls * LPAD) + ii * LPAD + jj] = 16.0f / (1.0f + fexp(-z));
        }
    }
}

// ============================================================
// Kernel 2a: split fp32 -> bf16 hi/lo
// ============================================================
__global__ __launch_bounds__(256) void split_kernel(
    const float4* __restrict__ in, ushort4* __restrict__ hi,
    ushort4* __restrict__ lo, int n4)
{
    int i = blockIdx.x * 256 + threadIdx.x;
    if (i >= n4) return;
    float4 v = in[i];
    __nv_bfloat16 h0 = __float2bfloat16(v.x), h1 = __float2bfloat16(v.y);
    __nv_bfloat16 h2 = __float2bfloat16(v.z), h3 = __float2bfloat16(v.w);
    __nv_bfloat16 l0 = __float2bfloat16(v.x - __bfloat162float(h0));
    __nv_bfloat16 l1 = __float2bfloat16(v.y - __bfloat162float(h1));
    __nv_bfloat16 l2 = __float2bfloat16(v.z - __bfloat162float(h2));
    __nv_bfloat16 l3 = __float2bfloat16(v.w - __bfloat162float(h3));
    ushort4 hv = { __bfloat16_as_ushort(h0), __bfloat16_as_ushort(h1),
                   __bfloat16_as_ushort(h2), __bfloat16_as_ushort(h3) };
    ushort4 lv = { __bfloat16_as_ushort(l0), __bfloat16_as_ushort(l1),
                   __bfloat16_as_ushort(l2), __bfloat16_as_ushort(l3) };
    hi[i] = hv; lo[i] = lv;
}

// ============================================================
// Kernel 2b: weight transpose + split
// ============================================================
__global__ __launch_bounds__(256) void wsplit_kernel(
    const float* __restrict__ W, __nv_bfloat16* __restrict__ ht,
    __nv_bfloat16* __restrict__ lt)
{
    __shared__ float t[32][33];
    int bn = blockIdx.x * 32, bk = blockIdx.y * 32;
    int lx = threadIdx.x & 31, ly = threadIdx.x >> 5;
    for (int yy = ly; yy < 32; yy += 8)
        t[yy][lx] = W[(size_t)(bk + yy) * Es + bn + lx];
    __syncthreads();
    for (int yy = ly; yy < 32; yy += 8) {
        float v = t[lx][yy];
        __nv_bfloat16 h = __float2bfloat16(v);
        __nv_bfloat16 l = __float2bfloat16(v - __bfloat162float(h));
        size_t o = (size_t)(bn + yy) * Es + bk + lx;
        ht[o] = h; lt[o] = l;
    }
}

// ============================================================
// Kernel 3: mma.sync bf16 split-GEMM; optional bf16 split output
// ============================================================
#define TGS 72
#define STAGE_B (128 * TGS * 2)
#define TG_SMEM (4 * STAGE_B)

__global__ __launch_bounds__(256) void tgemm_kernel(
    const __nv_bfloat16* __restrict__ Ah, const __nv_bfloat16* __restrict__ Al,
    const __nv_bfloat16* __restrict__ Wh, const __nv_bfloat16* __restrict__ Wl,
    const float* __restrict__ bias, float* __restrict__ C, int remap,
    __nv_bfloat16* __restrict__ Oh, __nv_bfloat16* __restrict__ Ol)
{
    extern __shared__ char dsm[];
    const int tid = threadIdx.x;
    const int wid = tid >> 5;
    const int lane = tid & 31;
    const int m0 = blockIdx.x * 128;
    const int n0 = blockIdx.y * 128;
    const int wm = wid & 1;
    const int wn = wid >> 1;
    const uint32_t smb = smem_u32(dsm);

    float c[4][4][4];
#pragma unroll
    for (int i = 0; i < 4; i++)
#pragma unroll
        for (int j = 0; j < 4; j++)
#pragma unroll
            for (int k = 0; k < 4; k++) c[i][j][k] = 0.0f;

    auto prefetch = [&](int i) {
        const int t = i >> 2, kc = i & 3, s = i & 1;
        const __nv_bfloat16* As = (t == 1) ? Al : Ah;
        const __nv_bfloat16* Bs = (t == 2) ? Wl : Wh;
        const int k0 = kc * 64;
        const uint32_t bA = smb + s * 2 * STAGE_B;
        const uint32_t bB = bA + STAGE_B;
#pragma unroll
        for (int j = 0; j < 4; j++) {
            int x = tid + j * 256;
            int r = x >> 3, cc = x & 7;
            uint32_t off = (uint32_t)(r * TGS + cc * 8) * 2;
            cp_async16(bA + off, As + (size_t)(m0 + r) * Es + k0 + cc * 8);
            cp_async16(bB + off, Bs + (size_t)(n0 + r) * Es + k0 + cc * 8);
        }
    };

    prefetch(0);
    cp_commit();

    const int arow = (lane & 7) + ((lane >> 3) & 1) * 8;
    const int acolo = ((lane >> 4) & 1) * 8;
    const int brow = (lane & 7) + ((lane >> 4) & 1) * 8;
    const int bcolo = ((lane >> 3) & 1) * 8;

    for (int i = 0; i < 12; i++) {
        if (i < 11) { prefetch(i + 1); cp_commit(); }
        if (i < 11) cp_wait1(); else cp_wait0();
        __syncthreads();

        const uint32_t bA = smb + (i & 1) * 2 * STAGE_B;
        const uint32_t bB = bA + STAGE_B;
#pragma unroll
        for (int ks = 0; ks < 4; ks++) {
            const int k0 = ks * 16;
            uint32_t a[4][4], b[2][4];
#pragma unroll
            for (int mt = 0; mt < 4; mt++)
                ldsm_x4(a[mt][0], a[mt][1], a[mt][2], a[mt][3],
                        bA + (uint32_t)((wm * 64 + mt * 16 + arow) * TGS + k0 + acolo) * 2);
#pragma unroll
            for (int g = 0; g < 2; g++)
                ldsm_x4(b[g][0], b[g][1], b[g][2], b[g][3],
                        bB + (uint32_t)((wn * 32 + g * 16 + brow) * TGS + k0 + bcolo) * 2);
#pragma unroll
            for (int mt = 0; mt < 4; mt++)
#pragma unroll
                for (int nt = 0; nt < 4; nt++)
                    mma16816(c[mt][nt], a[mt], b[nt >> 1][(nt & 1) * 2],
                             b[nt >> 1][(nt & 1) * 2 + 1]);
        }
        __syncthreads();
    }

    const int tq = lane >> 2;
    const int tr = lane & 3;
#pragma unroll
    for (int mt = 0; mt < 4; mt++) {
        const int m = m0 + wm * 64 + mt * 16 + tq;
#pragma unroll
        for (int nt = 0; nt < 4; nt++) {
            const int n = n0 + wn * 32 + nt * 8 + tr * 2;
            float2 v0 = make_float2(c[mt][nt][0], c[mt][nt][1]);
            float2 v1 = make_float2(c[mt][nt][2], c[mt][nt][3]);
            if (bias) {
                float2 bv = *(const float2*)(bias + n);
                v0.x += bv.x; v0.y += bv.y;
                v1.x += bv.x; v1.y += bv.y;
            }
            size_t a0, a1;
            if (remap) {
                const int hh = n >> 5, hd = n & 31;
                int bbw = m / Ls, l = m - bbw * Ls;
                a0 = ((size_t)(bbw * Hs + hh) * Ls + l) * HDs + hd;
                int m2 = m + 8;
                int bbw2 = m2 / Ls, l2 = m2 - bbw2 * Ls;
                a1 = ((size_t)(bbw2 * Hs + hh) * Ls + l2) * HDs + hd;
            } else {
                a0 = (size_t)m * Es + n;
                a1 = (size_t)(m + 8) * Es + n;
            }
            if (Oh) {
                __nv_bfloat16 h0 = __float2bfloat16(v0.x), h1 = __float2bfloat16(v0.y);
                __nv_bfloat16 h2 = __float2bfloat16(v1.x), h3 = __float2bfloat16(v1.y);
                *(uint32_t*)(Oh + a0) = packbf(__bfloat162float(h0), __bfloat162float(h1));
                *(uint32_t*)(Oh + a1) = packbf(__bfloat162float(h2), __bfloat162float(h3));
                *(uint32_t*)(Ol + a0) = packbf(v0.x - __bfloat162float(h0),
                                               v0.y - __bfloat162float(h1));
                *(uint32_t*)(Ol + a1) = packbf(v1.x - __bfloat162float(h2),
                                               v1.y - __bfloat162float(h3));
            } else {
                *(float2*)(C + a0) = v0;
                *(float2*)(C + a1) = v1;
            }
        }
    }
}

// ============================================================
// Kernel 4: L2-normalize q,k rows -> bf16 hi/lo operands
// ============================================================
__global__ __launch_bounds__(256) void norm_kernel()
{
    const int R = BBs * Hs * Ls;
    int gw = (blockIdx.x * blockDim.x + threadIdx.x) >> 5;
    int lane = threadIdx.x & 31;
    if (gw >= 2 * R) return;
    const float* src = (gw < R) ? g_q : g_k;
    __nv_bfloat16* dh = (gw < R) ? g_qh : g_kh;
    __nv_bfloat16* dl = (gw < R) ? g_ql : g_kl;
    int row = (gw < R) ? gw : gw - R;
    float v = src[(size_t)row * HDs + lane];
    float ss = v * v;
#pragma unroll
    for (int o = 16; o > 0; o >>= 1) ss += __shfl_xor_sync(0xffffffffu, ss, o);
    float vn = v / fmaxf(sqrtf(ss), 1e-12f);
    __nv_bfloat16 h = __float2bfloat16(vn);
    __nv_bfloat16 l = __float2bfloat16(vn - __bfloat162float(h));
    dh[(size_t)row * HDs + lane] = h;
    dl[(size_t)row * HDs + lane] = l;
}

// ============================================================
// Kernel 5: persistent tensorized attention per (head, window).
// 512 threads / 16 warps: wm=wid&3 (16-row m-tile), wn=wid>>2
// (96-key quarter, keys padded to 384). Loops 6 q-tiles of 64.
// Writes O directly as bf16 hi/lo into g_ah/g_al.
// ============================================================
#define ASTR 40
#define OFF_KH 0
#define OFF_KL 30720
#define OFF_VH 61440
#define OFF_VL 92160
#define OFF_QH 122880
#define OFF_QL 128000
#define OFF_RMAX 133120
#define OFF_RSUM 134144
#define OFF_ORED 135168
#define ORSTR 34
#define ATT3_SMEM (OFF_ORED + 3 * 64 * ORSTR * 4)   // 161280

__global__ __launch_bounds__(512) void attn3_kernel(const float* __restrict__ scalep)
{
    extern __shared__ char sm2[];
    float* redmax = (float*)(sm2 + OFF_RMAX);   // [4][64]
    float* redsum = (float*)(sm2 + OFF_RSUM);   // [4][64]
    float* ored   = (float*)(sm2 + OFF_ORED);   // [3][64][ORSTR]
    const uint32_t smb = smem_u32(sm2);

    const int tid = threadIdx.x;
    const int wid = tid >> 5;
    const int lane = tid & 31;
    const int h = blockIdx.x;
    const int bb = blockIdx.y;
    const size_t gbase = (size_t)(bb * Hs + h) * (Ls * HDs);

    // ---- KV fill once (cp.async), rows padded/zeroed to 384 ----
    for (int i = tid; i < 1372; i += 512) {
        int row = i >> 2, ch = i & 3;
        cp_async16(smb + OFF_KH + row * 80 + ch * 16, g_kh + gbase + row * HDs + ch * 8);
    }
    for (int i = tid; i < 1372; i += 512) {
        int row = i >> 2, ch = i & 3;
        cp_async16(smb + OFF_KL + row * 80 + ch * 16, g_kl + gbase + row * HDs + ch * 8);
    }
    for (int i = tid; i < 1372; i += 512) {
        int row = i >> 2, ch = i & 3;
        cp_async16(smb + OFF_VH + row * 80 + ch * 16, g_vh + gbase + row * HDs + ch * 8);
    }
    for (int i = tid; i < 1372; i += 512) {
        int row = i >> 2, ch = i & 3;
        cp_async16(smb + OFF_VL + row * 80 + ch * 16, g_vl + gbase + row * HDs + ch * 8);
    }
    for (int i = tid; i < 164; i += 512) {      // 41 pad rows x 4 chunks of 16B
        int r = 343 + (i >> 2), ch = i & 3;
        uint4 z = make_uint4(0, 0, 0, 0);
        *(uint4*)(sm2 + OFF_KH + r * 80 + ch * 16) = z;
        *(uint4*)(sm2 + OFF_KL + r * 80 + ch * 16) = z;
        *(uint4*)(sm2 + OFF_VH + r * 80 + ch * 16) = z;
        *(uint4*)(sm2 + OFF_VL + r * 80 + ch * 16) = z;
    }
    cp_commit();

    const int wm = wid & 3;
    const int wn = wid >> 2;
    const int nbase = wn * 96;

    const int arow = (lane & 7) + ((lane >> 3) & 1) * 8;
    const int acolo = ((lane >> 4) & 1) * 8;
    const int brow = (lane & 7) + ((lane >> 4) & 1) * 8;
    const int bcolo = ((lane >> 3) & 1) * 8;
    const int vrow = arow;      // same formula
    const int vcolo = acolo;

    const float invscale = 1.0f / fmaxf(scalep[0], 0.01f);
    const float* bias0 = g_bias + (size_t)h * (Ls * LPAD);
    const uint8_t* mrow = g_mask8 + (size_t)bb * (Ls * LPAD);
    const int r0 = wm * 16 + (lane >> 2);
    const int r1 = r0 + 8;
    const int ncol = (lane & 3) * 2;

    for (int qt = 0; qt < 6; qt++) {
        const int q0 = qt * 64;

        // ---- Q tile fill: exactly 1 op/thread ----
        {
            int row = tid >> 3, arr = (tid >> 2) & 1, ch = tid & 3;
            int qr = q0 + row;
            int off = (arr ? OFF_QL : OFF_QH) + row * 80 + ch * 16;
            if (qr < Ls) {
                const __nv_bfloat16* s = (arr ? g_ql : g_qh) + gbase + (size_t)qr * HDs + ch * 8;
                cp_async16(smb + off, s);
            } else {
                *(uint4*)(sm2 + off) = make_uint4(0, 0, 0, 0);
            }
        }
        cp_commit();
        cp_wait0();
        __syncthreads();

        // ---- Q fragments ----
        uint32_t qh[2][4], ql[2][4];
#pragma unroll
        for (int kk = 0; kk < 2; kk++) {
            uint32_t ad = smb + OFF_QH + (uint32_t)((wm * 16 + arow) * ASTR + kk * 16 + acolo) * 2;
            ldsm_x4(qh[kk][0], qh[kk][1], qh[kk][2], qh[kk][3], ad);
            ad = smb + OFF_QL + (uint32_t)((wm * 16 + arow) * ASTR + kk * 16 + acolo) * 2;
            ldsm_x4(ql[kk][0], ql[kk][1], ql[kk][2], ql[kk][3], ad);
        }

        // ---- phase 1: S fragments (12 n-tiles of 8) ----
        float c[12][4];
#pragma unroll
        for (int t = 0; t < 12; t++)
#pragma unroll
            for (int e = 0; e < 4; e++) c[t][e] = 0.0f;

#pragma unroll
        for (int g = 0; g < 6; g++) {
            uint32_t bh[2][4], bl[2][4];
#pragma unroll
            for (int kk = 0; kk < 2; kk++) {
                uint32_t rb = (uint32_t)((nbase + g * 16 + brow) * ASTR + kk * 16 + bcolo) * 2;
                ldsm_x4(bh[kk][0], bh[kk][1], bh[kk][2], bh[kk][3], smb + OFF_KH + rb);
                ldsm_x4(bl[kk][0], bl[kk][1], bl[kk][2], bl[kk][3], smb + OFF_KL + rb);
            }
#pragma unroll
            for (int kk = 0; kk < 2; kk++)
#pragma unroll
                for (int nt = 0; nt < 2; nt++) {
                    float* cc = c[g * 2 + nt];
                    mma16816(cc, qh[kk], bh[kk][nt * 2], bh[kk][nt * 2 + 1]);
                    mma16816(cc, ql[kk], bh[kk][nt * 2], bh[kk][nt * 2 + 1]);
                    mma16816(cc, qh[kk], bl[kk][nt * 2], bl[kk][nt * 2 + 1]);
                }
        }

        // ---- scale + bias + mask ----
        const int qrow0 = q0 + r0, qrow1 = q0 + r1;
        const bool rv0 = qrow0 < Ls, rv1 = qrow1 < Ls;
#pragma unroll
        for (int t = 0; t < 12; t++) {
            int col = nbase + t * 8 + ncol;
            bool cv0 = col < Ls, cv1 = (col + 1) < Ls;
            float2 b0v = make_float2(0.f, 0.f), b1v = make_float2(0.f, 0.f);
            uchar2 m0v = make_uchar2(0, 0), m1v = make_uchar2(0, 0);
            if (rv0 && cv0) {
                b0v = *(const float2*)(bias0 + (size_t)qrow0 * LPAD + col);
                m0v = *(const uchar2*)(mrow + (size_t)qrow0 * LPAD + col);
            }
            if (rv1 && cv0) {
                b1v = *(const float2*)(bias0 + (size_t)qrow1 * LPAD + col);
                m1v = *(const uchar2*)(mrow + (size_t)qrow1 * LPAD + col);
            }
            c[t][0] = (rv0 && cv0) ? (m0v.x ? -100000.0f : fmaf(c[t][0], invscale, b0v.x)) : -1e9f;
            c[t][1] = (rv0 && cv1) ? (m0v.y ? -100000.0f : fmaf(c[t][1], invscale, b0v.y)) : -1e9f;
            c[t][2] = (rv1 && cv0) ? (m1v.x ? -100000.0f : fmaf(c[t][2], invscale, b1v.x)) : -1e9f;
            c[t][3] = (rv1 && cv1) ? (m1v.y ? -100000.0f : fmaf(c[t][3], invscale, b1v.y)) : -1e9f;
        }

        // ---- softmax on fragments (4-quarter reduction) ----
        float mx0 = -FLT_MAX, mx1 = -FLT_MAX;
#pragma unroll
        for (int t = 0; t < 12; t++) {
            mx0 = fmaxf(mx0, fmaxf(c[t][0], c[t][1]));
            mx1 = fmaxf(mx1, fmaxf(c[t][2], c[t][3]));
        }
        mx0 = fmaxf(mx0, __shfl_xor_sync(0xffffffffu, mx0, 1));
        mx0 = fmaxf(mx0, __shfl_xor_sync(0xffffffffu, mx0, 2));
        mx1 = fmaxf(mx1, __shfl_xor_sync(0xffffffffu, mx1, 1));
        mx1 = fmaxf(mx1, __shfl_xor_sync(0xffffffffu, mx1, 2));
        if ((lane & 3) == 0) {
            redmax[wn * 64 + r0] = mx0;
            redmax[wn * 64 + r1] = mx1;
        }
        __syncthreads();
        mx0 = fmaxf(fmaxf(redmax[r0], redmax[64 + r0]),
                    fmaxf(redmax[128 + r0], redmax[192 + r0]));
        mx1 = fmaxf(fmaxf(redmax[r1], redmax[64 + r1]),
                    fmaxf(redmax[128 + r1], redmax[192 + r1]));

        float s0 = 0.0f, s1 = 0.0f;
#pragma unroll
        for (int t = 0; t < 12; t++) {
            float e0 = fexp(c[t][0] - mx0); c[t][0] = e0; s0 += e0;
            float e1 = fexp(c[t][1] - mx0); c[t][1] = e1; s0 += e1;
            float e2 = fexp(c[t][2] - mx1); c[t][2] = e2; s1 += e2;
            float e3 = fexp(c[t][3] - mx1); c[t][3] = e3; s1 += e3;
        }
        s0 += __shfl_xor_sync(0xffffffffu, s0, 1);
        s0 += __shfl_xor_sync(0xffffffffu, s0, 2);
        s1 += __shfl_xor_sync(0xffffffffu, s1, 1);
        s1 += __shfl_xor_sync(0xffffffffu, s1, 2);
        if ((lane & 3) == 0) {
            redsum[wn * 64 + r0] = s0;
            redsum[wn * 64 + r1] = s1;
        }
        __syncthreads();
        const float inv0 = 1.0f / (redsum[r0] + redsum[64 + r0]
                                   + redsum[128 + r0] + redsum[192 + r0]);
        const float inv1 = 1.0f / (redsum[r1] + redsum[64 + r1]
                                   + redsum[128 + r1] + redsum[192 + r1]);
#pragma unroll
        for (int t = 0; t < 12; t++) {
            c[t][0] *= inv0; c[t][1] *= inv0;
            c[t][2] *= inv1; c[t][3] *= inv1;
        }

        // ---- phase 3: O = P V ----
        float oc[4][4];
#pragma unroll
        for (int nt = 0; nt < 4; nt++)
#pragma unroll
            for (int e = 0; e < 4; e++) oc[nt][e] = 0.0f;

#pragma unroll
        for (int kt = 0; kt < 6; kt++) {
            uint32_t ph[4], pl[4];
#pragma unroll
            for (int half = 0; half < 2; half++) {
                const float* cc = c[2 * kt + half];
                __nv_bfloat16 h0 = __float2bfloat16(cc[0]);
                __nv_bfloat16 h1 = __float2bfloat16(cc[1]);
                __nv_bfloat16 h2 = __float2bfloat16(cc[2]);
                __nv_bfloat16 h3 = __float2bfloat16(cc[3]);
                ph[half * 2 + 0] = packbf(__bfloat162float(h0), __bfloat162float(h1));
                ph[half * 2 + 1] = packbf(__bfloat162float(h2), __bfloat162float(h3));
                pl[half * 2 + 0] = packbf(cc[0] - __bfloat162float(h0),
                                          cc[1] - __bfloat162float(h1));
                pl[half * 2 + 1] = packbf(cc[2] - __bfloat162float(h2),
                                          cc[3] - __bfloat162float(h3));
            }
            const int krow = nbase + kt * 16;
            uint32_t vh[2][4], vl[2][4];
#pragma unroll
            for (int g = 0; g < 2; g++) {
                uint32_t ad = (uint32_t)((krow + vrow) * ASTR + g * 16 + vcolo) * 2;
                ldsm_x4_t(vh[g][0], vh[g][1], vh[g][2], vh[g][3], smb + OFF_VH + ad);
                ldsm_x4_t(vl[g][0], vl[g][1], vl[g][2], vl[g][3], smb + OFF_VL + ad);
            }
#pragma unroll
            for (int nt = 0; nt < 4; nt++) {
                const int g = nt >> 1, i2 = (nt & 1) * 2;
                mma16816(oc[nt], ph, vh[g][i2], vh[g][i2 + 1]);
                mma16816(oc[nt], pl, vh[g][i2], vh[g][i2 + 1]);
                mma16816(oc[nt], ph, vl[g][i2], vl[g][i2 + 1]);
            }
        }

        // ---- cross-quarter O reduction + split store ----
        __syncthreads();
        if (wn > 0) {
            float* dst = ored + (size_t)(wn - 1) * (64 * ORSTR);
#pragma unroll
            for (int nt = 0; nt < 4; nt++) {
                *(float2*)(dst + r0 * ORSTR + nt * 8 + ncol) = make_float2(oc[nt][0], oc[nt][1]);
                *(float2*)(dst + r1 * ORSTR + nt * 8 + ncol) = make_float2(oc[nt][2], oc[nt][3]);
            }
        }
        __syncthreads();
        if (wn == 0) {
#pragma unroll
            for (int nt = 0; nt < 4; nt++) {
                float2 a0 = *(float2*)(ored + r0 * ORSTR + nt * 8 + ncol);
                float2 a1 = *(float2*)(ored + (64 * ORSTR) + r0 * ORSTR + nt * 8 + ncol);
                float2 a2 = *(float2*)(ored + (128 * ORSTR) + r0 * ORSTR + nt * 8 + ncol);
                float2 b0 = *(float2*)(ored + r1 * ORSTR + nt * 8 + ncol);
                float2 b1 = *(float2*)(ored + (64 * ORSTR) + r1 * ORSTR + nt * 8 + ncol);
                float2 b2 = *(float2*)(ored + (128 * ORSTR) + r1 * ORSTR + nt * 8 + ncol);
                float o00 = oc[nt][0] + a0.x + a1.x + a2.x;
                float o01 = oc[nt][1] + a0.y + a1.y + a2.y;
                float o10 = oc[nt][2] + b0.x + b1.x + b2.x;
                float o11 = oc[nt][3] + b0.y + b1.y + b2.y;
                int colg = h * HDs + nt * 8 + ncol;
                if (rv0) {
                    size_t ad = (size_t)(bb * Ls + qrow0) * Es + colg;
                    __nv_bfloat16 h0 = __float2bfloat16(o00), h1 = __float2bfloat16(o01);
                    *(uint32_t*)(g_ah + ad) = packbf(__bfloat162float(h0), __bfloat162float(h1));
                    *(uint32_t*)(g_al + ad) = packbf(o00 - __bfloat162float(h0),
                                                     o01 - __bfloat162float(h1));
                }
                if (rv1) {
                    size_t ad = (size_t)(bb * Ls + qrow1) * Es + colg;
                    __nv_bfloat16 h0 = __float2bfloat16(o10), h1 = __float2bfloat16(o11);
                    *(uint32_t*)(g_ah + ad) = packbf(__bfloat162float(h0), __bfloat162float(h1));
                    *(uint32_t*)(g_al + ad) = packbf(o10 - __bfloat162float(h0),
                                                     o11 - __bfloat162float(h1));
                }
            }
        }
        __syncthreads();
    }
}

// ============================================================
// launch
// ============================================================
extern "C" void kernel_launch(void* const* d_in, const int* in_sizes, int n_in,
                              void* d_out, int out_size)
{
    (void)in_sizes; (void)n_in; (void)out_size;
    const float* query   = (const float*)d_in[0];
    const float* key     = (const float*)d_in[1];
    const float* value   = (const float*)d_in[2];
    const float* indices = (const float*)d_in[3];
    const void*  mask    = d_in[4];
    const float* Wq      = (const float*)d_in[5];
    const float* bq      = (const float*)d_in[6];
    const float* Wk      = (const float*)d_in[7];
    const float* bk      = (const float*)d_in[8];
    const float* Wv      = (const float*)d_in[9];
    const float* Ww      = (const float*)d_in[10];
    const float* bw      = (const float*)d_in[11];
    const float* scale   = (const float*)d_in[12];
    const float* W1      = (const float*)d_in[13];
    const float* b1      = (const float*)d_in[14];
    const float* W2      = (const float*)d_in[15];
    const float* b2      = (const float*)d_in[16];
    float* out = (float*)d_out;

    float *pq, *pk;
    __nv_bfloat16 *pah, *pal, *pwh, *pwl, *pvh, *pvl;
    cudaGetSymbolAddress((void**)&pq,  g_q);
    cudaGetSymbolAddress((void**)&pk,  g_k);
    cudaGetSymbolAddress((void**)&pah, g_ah);
    cudaGetSymbolAddress((void**)&pal, g_al);
    cudaGetSymbolAddress((void**)&pwh, g_wh);
    cudaGetSymbolAddress((void**)&pwl, g_wl);
    cudaGetSymbolAddress((void**)&pvh, g_vh);
    cudaGetSymbolAddress((void**)&pvl, g_vl);

    cudaFuncSetAttribute(tgemm_kernel, cudaFuncAttributeMaxDynamicSharedMemorySize,
                         TG_SMEM);
    cudaFuncSetAttribute(attn3_kernel, cudaFuncAttributeMaxDynamicSharedMemorySize,
                         ATT3_SMEM);

    const int n4 = ROWSs * Es / 4;
    const int splitg = (n4 + 255) / 256;
    const dim3 wsg(8, 8);
    const dim3 gg(ROWSs / 128, Es / 128);

    detect_mask_kernel<<<1, 256>>>((const unsigned int*)mask);
    mask_prep_kernel<<<(BBs * LLs + 255) / 256, 256>>>(mask);
    bias_kernel<<<(LLs + 1023) / 1024, 256>>>(indices, W1, b1, W2, b2);

    // Q projection (fp32 head-split out, for normalize)
    wsplit_kernel<<<wsg, 256>>>(Wq, pwh, pwl);
    split_kernel<<<splitg, 256>>>((const float4*)query, (ushort4*)pah, (ushort4*)pal, n4);
    tgemm_kernel<<<gg, 256, TG_SMEM>>>(pah, pal, pwh, pwl, bq, pq, 1, nullptr, nullptr);
    // K projection
    wsplit_kernel<<<wsg, 256>>>(Wk, pwh, pwl);
    split_kernel<<<splitg, 256>>>((const float4*)key, (ushort4*)pah, (ushort4*)pal, n4);
    tgemm_kernel<<<gg, 256, TG_SMEM>>>(pah, pal, pwh, pwl, bk, pk, 1, nullptr, nullptr);
    // V projection: bf16 hi/lo split output directly
    wsplit_kernel<<<wsg, 256>>>(Wv, pwh, pwl);
    split_kernel<<<splitg, 256>>>((const float4*)value, (ushort4*)pah, (ushort4*)pal, n4);
    tgemm_kernel<<<gg, 256, TG_SMEM>>>(pah, pal, pwh, pwl, nullptr, nullptr, 1, pvh, pvl);

    // normalize q,k -> bf16 hi/lo
    {
        long long warps = 2LL * BBs * Hs * Ls;
        int blocks = (int)((warps * 32 + 255) / 256);
        norm_kernel<<<blocks, 256>>>();
    }

    // persistent tensorized attention (writes g_ah/g_al directly)
    attn3_kernel<<<dim3(Hs, BBs), 512, ATT3_SMEM>>>(scale);

    // output projection
    wsplit_kernel<<<wsg, 256>>>(Ww, pwh, pwl);
    tgemm_kernel<<<gg, 256, TG_SMEM>>>(pah, pal, pwh, pwl, bw, out, 0, nullptr, nullptr);
}

// round 8
// speedup vs baseline: 3.2298x; 1.2534x over previous
#include <cuda_runtime.h>
#include <cuda_bf16.h>
#include <math.h>
#include <float.h>
#include <stdint.h>

// Problem dims
#define BBs   128
#define Ls    343
#define Es    256
#define Hs    8
#define HDs   32
#define HIDs  512
#define LLs   (Ls * Ls)       // 117649
#define ROWSs (BBs * Ls)      // 43904
#define LPAD  344

// -------- scratch (device globals; no allocation allowed) --------
__device__ float g_bias[Hs * Ls * LPAD];
__device__ int   g_mask_mode;
__device__ uint8_t g_mask8[BBs * Ls * LPAD];
// bf16 split A-operands per projection input
__device__ __nv_bfloat16 g_xqh[ROWSs * Es], g_xql[ROWSs * Es];
__device__ __nv_bfloat16 g_xkh[ROWSs * Es], g_xkl[ROWSs * Es];
__device__ __nv_bfloat16 g_xvh[ROWSs * Es], g_xvl[ROWSs * Es];
// attention output (A of final GEMM)
__device__ __nv_bfloat16 g_ah[ROWSs * Es], g_al[ROWSs * Es];
// weights (4x, transposed [n][k], hi/lo)
__device__ __nv_bfloat16 g_w4h[4 * Es * Es], g_w4l[4 * Es * Es];
// normalized q/k and v operands (head-split)
__device__ __nv_bfloat16 g_qh[BBs * Hs * Ls * HDs], g_ql[BBs * Hs * Ls * HDs];
__device__ __nv_bfloat16 g_kh[BBs * Hs * Ls * HDs], g_kl[BBs * Hs * Ls * HDs];
__device__ __nv_bfloat16 g_vh[BBs * Hs * Ls * HDs], g_vl[BBs * Hs * Ls * HDs];

// ============================================================
// PTX helpers (baseline sm_80+ ISA; harness targets sm_103 w/o 'a')
// ============================================================
__device__ __forceinline__ uint32_t smem_u32(const void* p) {
    uint32_t a;
    asm("{ .reg .u64 t; cvta.to.shared.u64 t, %1; cvt.u32.u64 %0, t; }" : "=r"(a) : "l"(p));
    return a;
}
__device__ __forceinline__ void ldsm_x4(uint32_t& r0, uint32_t& r1, uint32_t& r2,
                                        uint32_t& r3, uint32_t addr) {
    asm volatile("ldmatrix.sync.aligned.m8n8.x4.shared.b16 {%0,%1,%2,%3}, [%4];"
                 : "=r"(r0), "=r"(r1), "=r"(r2), "=r"(r3) : "r"(addr));
}
__device__ __forceinline__ void ldsm_x4_t(uint32_t& r0, uint32_t& r1, uint32_t& r2,
                                          uint32_t& r3, uint32_t addr) {
    asm volatile("ldmatrix.sync.aligned.m8n8.x4.trans.shared.b16 {%0,%1,%2,%3}, [%4];"
                 : "=r"(r0), "=r"(r1), "=r"(r2), "=r"(r3) : "r"(addr));
}
__device__ __forceinline__ void mma16816(float* c, const uint32_t* a,
                                         uint32_t b0, uint32_t b1) {
    asm volatile(
        "mma.sync.aligned.m16n8k16.row.col.f32.bf16.bf16.f32 "
        "{%0,%1,%2,%3}, {%4,%5,%6,%7}, {%8,%9}, {%0,%1,%2,%3};"
        : "+f"(c[0]), "+f"(c[1]), "+f"(c[2]), "+f"(c[3])
        : "r"(a[0]), "r"(a[1]), "r"(a[2]), "r"(a[3]), "r"(b0), "r"(b1));
}
__device__ __forceinline__ void cp_async16(uint32_t dst, const void* src) {
    asm volatile("cp.async.cg.shared.global [%0], [%1], 16;" :: "r"(dst), "l"(src));
}
__device__ __forceinline__ void cp_commit() { asm volatile("cp.async.commit_group;"); }
__device__ __forceinline__ void cp_wait1() { asm volatile("cp.async.wait_group 1;"); }
__device__ __forceinline__ void cp_wait0() { asm volatile("cp.async.wait_group 0;"); }

__device__ __forceinline__ uint32_t packbf(float a, float b) {
    __nv_bfloat162 t = __floats2bfloat162_rn(a, b);
    return *(uint32_t*)&t;
}

// Fast exp on FMA/ALU pipes only (no MUFU). rel err ~2.4e-6.
__device__ __forceinline__ float fexp(float x) {
    float y = fmaxf(x * 1.4426950408889634f, -126.0f);
    float yr = __fadd_rn(y, 12582912.0f);
    float n  = __fsub_rn(yr, 12582912.0f);
    float f  = __fsub_rn(y, n);
    float p  = 1.3333558e-3f;
    p = fmaf(p, f, 9.6181291e-3f);
    p = fmaf(p, f, 5.5504109e-2f);
    p = fmaf(p, f, 2.4022651e-1f);
    p = fmaf(p, f, 6.9314718e-1f);
    p = fmaf(p, f, 1.0f);
    return __int_as_float(__float_as_int(p) + (__float_as_int(yr) << 23));
}

// ============================================================
// Kernel: detect mask dtype
// ============================================================
__global__ void detect_mask_kernel(const unsigned int* __restrict__ m)
{
    __shared__ int s_float, s_multi;
    if (threadIdx.x == 0) { s_float = 0; s_multi = 0; }
    __syncthreads();
    for (int i = threadIdx.x; i < 4096; i += 256) {
        unsigned int w = m[i];
        if (w == 0x3F800000u) atomicOr(&s_float, 1);
        else if (w != 0u && (w & 0xFFFFFF00u) != 0u) atomicOr(&s_multi, 1);
    }
    __syncthreads();
    if (threadIdx.x == 0)
        g_mask_mode = s_float ? 2 : (s_multi ? 0 : 1);
}

// ============================================================
// Kernel: normalize mask to padded uint8 table
// ============================================================
__global__ __launch_bounds__(256) void mask_prep_kernel(const void* __restrict__ maskp)
{
    int idx = blockIdx.x * 256 + threadIdx.x;
    if (idx >= BBs * LLs) return;
    int bb = idx / LLs;
    int p = idx - bb * LLs;
    int i = p / Ls, j = p - i * Ls;
    int mode = g_mask_mode;
    bool m = (mode == 0) ? (((const uint8_t*)maskp)[idx] != 0)
           : (mode == 1) ? (((const int*)maskp)[idx] != 0)
                         : (((const float*)maskp)[idx] != 0.0f);
    g_mask8[(size_t)bb * (Ls * LPAD) + i * LPAD + j] = m ? 1 : 0;
}

// ============================================================
// Kernel: CPB bias table (padded stride LPAD)
// ============================================================
__global__ __launch_bounds__(256) void bias_kernel(
    const float* __restrict__ indices, const float* __restrict__ W1,
    const float* __restrict__ b1, const float* __restrict__ W2,
    const float* __restrict__ b2)
{
    __shared__ float sW1[3 * HIDs];
    __shared__ float sb1[HIDs];
    __shared__ float sW2[HIDs * Hs];
    for (int i = threadIdx.x; i < 3 * HIDs; i += 256) sW1[i] = W1[i];
    for (int i = threadIdx.x; i < HIDs;     i += 256) sb1[i] = b1[i];
    for (int i = threadIdx.x; i < HIDs * Hs; i += 256) sW2[i] = W2[i];
    __syncthreads();

    const int p0 = blockIdx.x * 1024 + threadIdx.x;
    float x[4][3];
    bool valid[4];
#pragma unroll
    for (int k = 0; k < 4; k++) {
        int p = p0 + k * 256;
        valid[k] = (p < LLs);
        int pp = valid[k] ? p : 0;
#pragma unroll
        for (int c = 0; c < 3; c++) {
            float xv = indices[pp * 3 + c];
            x[k][c] = copysignf(log2f(1.0f + fabsf(xv)) * (1.0f / 3.0f), xv);
        }
    }
    float acc[4][8];
#pragma unroll
    for (int k = 0; k < 4; k++)
#pragma unroll
        for (int h = 0; h < 8; h++) acc[k][h] = 0.0f;

    for (int t = 0; t < HIDs; t++) {
        float w0 = sW1[t], w1 = sW1[HIDs + t], w2 = sW1[2 * HIDs + t];
        float bb1 = sb1[t];
        float hv[4];
#pragma unroll
        for (int k = 0; k < 4; k++)
            hv[k] = fmaxf(fmaf(x[k][0], w0, fmaf(x[k][1], w1, fmaf(x[k][2], w2, bb1))), 0.0f);
#pragma unroll
        for (int h = 0; h < 8; h++) {
            float w = sW2[t * 8 + h];
#pragma unroll
            for (int k = 0; k < 4; k++) acc[k][h] = fmaf(hv[k], w, acc[k][h]);
        }
    }
#pragma unroll
    for (int k = 0; k < 4; k++) {
        if (!valid[k]) continue;
        int p = p0 + k * 256;
        int ii = p / Ls, jj = p - ii * Ls;
#pragma unroll
        for (int h = 0; h < 8; h++) {
            float z = acc[k][h] + b2[h];
            g_bias[(size_t)h * (Ls * LPAD) + ii * LPAD + jj] = 16.0f / (1.0f + fexp(-z));
        }
    }
}

// ============================================================
// Kernel: split all 3 fp32 inputs -> bf16 hi/lo (batched, grid.y=3)
// ============================================================
__global__ __launch_bounds__(256) void split3_kernel(
    const float4* __restrict__ q, const float4* __restrict__ k,
    const float4* __restrict__ v, int n4)
{
    const int z = blockIdx.y;
    const float4* in = (z == 0) ? q : (z == 1) ? k : v;
    ushort4* hi = (ushort4*)((z == 0) ? g_xqh : (z == 1) ? g_xkh : g_xvh);
    ushort4* lo = (ushort4*)((z == 0) ? g_xql : (z == 1) ? g_xkl : g_xvl);
    int i = blockIdx.x * 256 + threadIdx.x;
    if (i >= n4) return;
    float4 val = in[i];
    __nv_bfloat16 h0 = __float2bfloat16(val.x), h1 = __float2bfloat16(val.y);
    __nv_bfloat16 h2 = __float2bfloat16(val.z), h3 = __float2bfloat16(val.w);
    ushort4 hv = { __bfloat16_as_ushort(h0), __bfloat16_as_ushort(h1),
                   __bfloat16_as_ushort(h2), __bfloat16_as_ushort(h3) };
    __nv_bfloat16 l0 = __float2bfloat16(val.x - __bfloat162float(h0));
    __nv_bfloat16 l1 = __float2bfloat16(val.y - __bfloat162float(h1));
    __nv_bfloat16 l2 = __float2bfloat16(val.z - __bfloat162float(h2));
    __nv_bfloat16 l3 = __float2bfloat16(val.w - __bfloat162float(h3));
    ushort4 lv = { __bfloat16_as_ushort(l0), __bfloat16_as_ushort(l1),
                   __bfloat16_as_ushort(l2), __bfloat16_as_ushort(l3) };
    hi[i] = hv; lo[i] = lv;
}

// ============================================================
// Kernel: all 4 weight transposes + splits (batched, grid.z=4)
// ============================================================
__global__ __launch_bounds__(256) void wsplit_all_kernel(
    const float* __restrict__ Wq, const float* __restrict__ Wk,
    const float* __restrict__ Wv, const float* __restrict__ Ww)
{
    __shared__ float t[32][33];
    const int z = blockIdx.z;
    const float* W = (z == 0) ? Wq : (z == 1) ? Wk : (z == 2) ? Wv : Ww;
    __nv_bfloat16* ht = g_w4h + (size_t)z * Es * Es;
    __nv_bfloat16* lt = g_w4l + (size_t)z * Es * Es;
    int bn = blockIdx.x * 32, bk = blockIdx.y * 32;
    int lx = threadIdx.x & 31, ly = threadIdx.x >> 5;
    for (int yy = ly; yy < 32; yy += 8)
        t[yy][lx] = W[(size_t)(bk + yy) * Es + bn + lx];
    __syncthreads();
    for (int yy = ly; yy < 32; yy += 8) {
        float v = t[lx][yy];
        __nv_bfloat16 h = __float2bfloat16(v);
        __nv_bfloat16 l = __float2bfloat16(v - __bfloat162float(h));
        size_t o = (size_t)(bn + yy) * Es + bk + lx;
        ht[o] = h; lt[o] = l;
    }
}

// ============================================================
// Kernel: mma.sync bf16 split-GEMM.
// Epilogue modes: fp32 C; bf16 hi/lo split (Oh/Ol); + optional fused
// per-head L2 normalize (donorm, quad shfl reduction).
// ============================================================
#define TGS 72
#define STAGE_B (128 * TGS * 2)
#define TG_SMEM (4 * STAGE_B)

__global__ __launch_bounds__(256) void tgemm_kernel(
    const __nv_bfloat16* __restrict__ Ah, const __nv_bfloat16* __restrict__ Al,
    const __nv_bfloat16* __restrict__ Wh, const __nv_bfloat16* __restrict__ Wl,
    const float* __restrict__ bias, float* __restrict__ C, int remap,
    __nv_bfloat16* __restrict__ Oh, __nv_bfloat16* __restrict__ Ol, int donorm)
{
    extern __shared__ char dsm[];
    const int tid = threadIdx.x;
    const int wid = tid >> 5;
    const int lane = tid & 31;
    const int m0 = blockIdx.x * 128;
    const int n0 = blockIdx.y * 128;
    const int wm = wid & 1;
    const int wn = wid >> 1;
    const uint32_t smb = smem_u32(dsm);

    float c[4][4][4];
#pragma unroll
    for (int i = 0; i < 4; i++)
#pragma unroll
        for (int j = 0; j < 4; j++)
#pragma unroll
            for (int k = 0; k < 4; k++) c[i][j][k] = 0.0f;

    auto prefetch = [&](int i) {
        const int t = i >> 2, kc = i & 3, s = i & 1;
        const __nv_bfloat16* As = (t == 1) ? Al : Ah;
        const __nv_bfloat16* Bs = (t == 2) ? Wl : Wh;
        const int k0 = kc * 64;
        const uint32_t bA = smb + s * 2 * STAGE_B;
        const uint32_t bB = bA + STAGE_B;
#pragma unroll
        for (int j = 0; j < 4; j++) {
            int x = tid + j * 256;
            int r = x >> 3, cc = x & 7;
            uint32_t off = (uint32_t)(r * TGS + cc * 8) * 2;
            cp_async16(bA + off, As + (size_t)(m0 + r) * Es + k0 + cc * 8);
            cp_async16(bB + off, Bs + (size_t)(n0 + r) * Es + k0 + cc * 8);
        }
    };

    prefetch(0);
    cp_commit();

    const int arow = (lane & 7) + ((lane >> 3) & 1) * 8;
    const int acolo = ((lane >> 4) & 1) * 8;
    const int brow = (lane & 7) + ((lane >> 4) & 1) * 8;
    const int bcolo = ((lane >> 3) & 1) * 8;

    for (int i = 0; i < 12; i++) {
        if (i < 11) { prefetch(i + 1); cp_commit(); }
        if (i < 11) cp_wait1(); else cp_wait0();
        __syncthreads();

        const uint32_t bA = smb + (i & 1) * 2 * STAGE_B;
        const uint32_t bB = bA + STAGE_B;
#pragma unroll
        for (int ks = 0; ks < 4; ks++) {
            const int k0 = ks * 16;
            uint32_t a[4][4], b[2][4];
#pragma unroll
            for (int mt = 0; mt < 4; mt++)
                ldsm_x4(a[mt][0], a[mt][1], a[mt][2], a[mt][3],
                        bA + (uint32_t)((wm * 64 + mt * 16 + arow) * TGS + k0 + acolo) * 2);
#pragma unroll
            for (int g = 0; g < 2; g++)
                ldsm_x4(b[g][0], b[g][1], b[g][2], b[g][3],
                        bB + (uint32_t)((wn * 32 + g * 16 + brow) * TGS + k0 + bcolo) * 2);
#pragma unroll
            for (int mt = 0; mt < 4; mt++)
#pragma unroll
                for (int nt = 0; nt < 4; nt++)
                    mma16816(c[mt][nt], a[mt], b[nt >> 1][(nt & 1) * 2],
                             b[nt >> 1][(nt & 1) * 2 + 1]);
        }
        __syncthreads();
    }

    const int tq = lane >> 2;
    const int tr = lane & 3;
#pragma unroll
    for (int mt = 0; mt < 4; mt++) {
        const int m = m0 + wm * 64 + mt * 16 + tq;
        float v0x[4], v0y[4], v1x[4], v1y[4];
#pragma unroll
        for (int nt = 0; nt < 4; nt++) {
            const int n = n0 + wn * 32 + nt * 8 + tr * 2;
            float bx = 0.0f, by = 0.0f;
            if (bias) { float2 bv = *(const float2*)(bias + n); bx = bv.x; by = bv.y; }
            v0x[nt] = c[mt][nt][0] + bx; v0y[nt] = c[mt][nt][1] + by;
            v1x[nt] = c[mt][nt][2] + bx; v1y[nt] = c[mt][nt][3] + by;
        }
        if (donorm) {
            // head row (32 dims) spans this quad: 4 lanes x 8 cols
            float ss0 = 0.0f, ss1 = 0.0f;
#pragma unroll
            for (int nt = 0; nt < 4; nt++) {
                ss0 = fmaf(v0x[nt], v0x[nt], fmaf(v0y[nt], v0y[nt], ss0));
                ss1 = fmaf(v1x[nt], v1x[nt], fmaf(v1y[nt], v1y[nt], ss1));
            }
            ss0 += __shfl_xor_sync(0xffffffffu, ss0, 1);
            ss0 += __shfl_xor_sync(0xffffffffu, ss0, 2);
            ss1 += __shfl_xor_sync(0xffffffffu, ss1, 1);
            ss1 += __shfl_xor_sync(0xffffffffu, ss1, 2);
            float i0 = 1.0f / fmaxf(sqrtf(ss0), 1e-12f);
            float i1 = 1.0f / fmaxf(sqrtf(ss1), 1e-12f);
#pragma unroll
            for (int nt = 0; nt < 4; nt++) {
                v0x[nt] *= i0; v0y[nt] *= i0;
                v1x[nt] *= i1; v1y[nt] *= i1;
            }
        }
#pragma unroll
        for (int nt = 0; nt < 4; nt++) {
            const int n = n0 + wn * 32 + nt * 8 + tr * 2;
            size_t a0, a1;
            if (remap) {
                const int hh = n >> 5, hd = n & 31;
                int bbw = m / Ls, l = m - bbw * Ls;
                a0 = ((size_t)(bbw * Hs + hh) * Ls + l) * HDs + hd;
                int m2 = m + 8;
                int bbw2 = m2 / Ls, l2 = m2 - bbw2 * Ls;
                a1 = ((size_t)(bbw2 * Hs + hh) * Ls + l2) * HDs + hd;
            } else {
                a0 = (size_t)m * Es + n;
                a1 = (size_t)(m + 8) * Es + n;
            }
            if (Oh) {
                __nv_bfloat16 h0 = __float2bfloat16(v0x[nt]), h1 = __float2bfloat16(v0y[nt]);
                __nv_bfloat16 h2 = __float2bfloat16(v1x[nt]), h3 = __float2bfloat16(v1y[nt]);
                *(uint32_t*)(Oh + a0) = packbf(__bfloat162float(h0), __bfloat162float(h1));
                *(uint32_t*)(Oh + a1) = packbf(__bfloat162float(h2), __bfloat162float(h3));
                *(uint32_t*)(Ol + a0) = packbf(v0x[nt] - __bfloat162float(h0),
                                               v0y[nt] - __bfloat162float(h1));
                *(uint32_t*)(Ol + a1) = packbf(v1x[nt] - __bfloat162float(h2),
                                               v1y[nt] - __bfloat162float(h3));
            } else {
                *(float2*)(C + a0) = make_float2(v0x[nt], v0y[nt]);
                *(float2*)(C + a1) = make_float2(v1x[nt], v1y[nt]);
            }
        }
    }
}

// ============================================================
// Kernel: persistent tensorized attention per (head, window).
// 512 threads / 16 warps. Whole K/V/Q (hi/lo) resident in SMEM.
// 2 __syncthreads per q-tile. Writes O as bf16 hi/lo (g_ah/g_al).
// ============================================================
#define ASTR 40
#define ABUF 30720                 // 384 rows x 80 B
#define OFF_KH (0 * ABUF)
#define OFF_KL (1 * ABUF)
#define OFF_VH (2 * ABUF)
#define OFF_VL (3 * ABUF)
#define OFF_QH (4 * ABUF)
#define OFF_QL (5 * ABUF)
#define OFF_RMAX (6 * ABUF)        // 184320; [4][64] float
#define OFF_RSUM (OFF_RMAX + 1024)
#define OFF_ORED (OFF_RSUM + 1024) // [3][64][ORSTR] float
#define ORSTR 34
#define ATT3_SMEM (OFF_ORED + 3 * 64 * ORSTR * 4)   // 212480

__global__ __launch_bounds__(512) void attn3_kernel(const float* __restrict__ scalep)
{
    extern __shared__ char sm2[];
    float* redmax = (float*)(sm2 + OFF_RMAX);
    float* redsum = (float*)(sm2 + OFF_RSUM);
    float* ored   = (float*)(sm2 + OFF_ORED);
    const uint32_t smb = smem_u32(sm2);

    const int tid = threadIdx.x;
    const int wid = tid >> 5;
    const int lane = tid & 31;
    const int h = blockIdx.x;
    const int bb = blockIdx.y;
    const size_t gbase = (size_t)(bb * Hs + h) * (Ls * HDs);

    // ---- fill K/V/Q hi+lo once ----
    {
        const __nv_bfloat16* gsrc[6] = { g_kh + gbase, g_kl + gbase, g_vh + gbase,
                                         g_vl + gbase, g_qh + gbase, g_ql + gbase };
#pragma unroll
        for (int arr = 0; arr < 6; arr++)
            for (int i = tid; i < 1372; i += 512) {
                int row = i >> 2, ch = i & 3;
                cp_async16(smb + arr * ABUF + row * 80 + ch * 16,
                           gsrc[arr] + row * HDs + ch * 8);
            }
        for (int i = tid; i < 984; i += 512) {   // pad rows 343..383, 4x16B each
            int arr = i / 164, j = i - arr * 164;
            int r = 343 + (j >> 2), ch = j & 3;
            *(uint4*)(sm2 + arr * ABUF + r * 80 + ch * 16) = make_uint4(0, 0, 0, 0);
        }
        cp_commit();
        cp_wait0();
        __syncthreads();
    }

    const int wm = wid & 3;
    const int wn = wid >> 2;
    const int nbase = wn * 96;

    const int arow = (lane & 7) + ((lane >> 3) & 1) * 8;
    const int acolo = ((lane >> 4) & 1) * 8;
    const int brow = (lane & 7) + ((lane >> 4) & 1) * 8;
    const int bcolo = ((lane >> 3) & 1) * 8;

    const float invscale = 1.0f / fmaxf(scalep[0], 0.01f);
    const float* bias0 = g_bias + (size_t)h * (Ls * LPAD);
    const uint8_t* mrow = g_mask8 + (size_t)bb * (Ls * LPAD);
    const int r0 = wm * 16 + (lane >> 2);
    const int r1 = r0 + 8;
    const int ncol = (lane & 3) * 2;

    for (int qt = 0; qt < 6; qt++) {
        const int q0 = qt * 64;

        // ---- Q fragments from resident buffer ----
        uint32_t qh[2][4], ql[2][4];
#pragma unroll
        for (int kk = 0; kk < 2; kk++) {
            uint32_t ro = (uint32_t)((q0 + wm * 16 + arow) * ASTR + kk * 16 + acolo) * 2;
            ldsm_x4(qh[kk][0], qh[kk][1], qh[kk][2], qh[kk][3], smb + OFF_QH + ro);
            ldsm_x4(ql[kk][0], ql[kk][1], ql[kk][2], ql[kk][3], smb + OFF_QL + ro);
        }

        // ---- phase 1: S fragments ----
        float c[12][4];
#pragma unroll
        for (int t = 0; t < 12; t++)
#pragma unroll
            for (int e = 0; e < 4; e++) c[t][e] = 0.0f;

#pragma unroll
        for (int g = 0; g < 6; g++) {
            uint32_t bh[2][4], bl[2][4];
#pragma unroll
            for (int kk = 0; kk < 2; kk++) {
                uint32_t rb = (uint32_t)((nbase + g * 16 + brow) * ASTR + kk * 16 + bcolo) * 2;
                ldsm_x4(bh[kk][0], bh[kk][1], bh[kk][2], bh[kk][3], smb + OFF_KH + rb);
                ldsm_x4(bl[kk][0], bl[kk][1], bl[kk][2], bl[kk][3], smb + OFF_KL + rb);
            }
#pragma unroll
            for (int kk = 0; kk < 2; kk++)
#pragma unroll
                for (int nt = 0; nt < 2; nt++) {
                    float* cc = c[g * 2 + nt];
                    mma16816(cc, qh[kk], bh[kk][nt * 2], bh[kk][nt * 2 + 1]);
                    mma16816(cc, ql[kk], bh[kk][nt * 2], bh[kk][nt * 2 + 1]);
                    mma16816(cc, qh[kk], bl[kk][nt * 2], bl[kk][nt * 2 + 1]);
                }
        }

        // ---- scale + bias + mask ----
        const int qrow0 = q0 + r0, qrow1 = q0 + r1;
        const bool rv0 = qrow0 < Ls, rv1 = qrow1 < Ls;
#pragma unroll
        for (int t = 0; t < 12; t++) {
            int col = nbase + t * 8 + ncol;
            bool cv0 = col < Ls, cv1 = (col + 1) < Ls;
            float2 b0v = make_float2(0.f, 0.f), b1v = make_float2(0.f, 0.f);
            uchar2 m0v = make_uchar2(0, 0), m1v = make_uchar2(0, 0);
            if (rv0 && cv0) {
                b0v = *(const float2*)(bias0 + (size_t)qrow0 * LPAD + col);
                m0v = *(const uchar2*)(mrow + (size_t)qrow0 * LPAD + col);
            }
            if (rv1 && cv0) {
                b1v = *(const float2*)(bias0 + (size_t)qrow1 * LPAD + col);
                m1v = *(const uchar2*)(mrow + (size_t)qrow1 * LPAD + col);
            }
            c[t][0] = (rv0 && cv0) ? (m0v.x ? -100000.0f : fmaf(c[t][0], invscale, b0v.x)) : -1e9f;
            c[t][1] = (rv0 && cv1) ? (m0v.y ? -100000.0f : fmaf(c[t][1], invscale, b0v.y)) : -1e9f;
            c[t][2] = (rv1 && cv0) ? (m1v.x ? -100000.0f : fmaf(c[t][2], invscale, b1v.x)) : -1e9f;
            c[t][3] = (rv1 && cv1) ? (m1v.y ? -100000.0f : fmaf(c[t][3], invscale, b1v.y)) : -1e9f;
        }

        // ---- single-sync softmax: local max+sum, then global combine ----
        float mx0 = -FLT_MAX, mx1 = -FLT_MAX;
#pragma unroll
        for (int t = 0; t < 12; t++) {
            mx0 = fmaxf(mx0, fmaxf(c[t][0], c[t][1]));
            mx1 = fmaxf(mx1, fmaxf(c[t][2], c[t][3]));
        }
        mx0 = fmaxf(mx0, __shfl_xor_sync(0xffffffffu, mx0, 1));
        mx0 = fmaxf(mx0, __shfl_xor_sync(0xffffffffu, mx0, 2));
        mx1 = fmaxf(mx1, __shfl_xor_sync(0xffffffffu, mx1, 1));
        mx1 = fmaxf(mx1, __shfl_xor_sync(0xffffffffu, mx1, 2));

        float s0 = 0.0f, s1 = 0.0f;
#pragma unroll
        for (int t = 0; t < 12; t++) {
            float e0 = fexp(c[t][0] - mx0); c[t][0] = e0; s0 += e0;
            float e1 = fexp(c[t][1] - mx0); c[t][1] = e1; s0 += e1;
            float e2 = fexp(c[t][2] - mx1); c[t][2] = e2; s1 += e2;
            float e3 = fexp(c[t][3] - mx1); c[t][3] = e3; s1 += e3;
        }
        s0 += __shfl_xor_sync(0xffffffffu, s0, 1);
        s0 += __shfl_xor_sync(0xffffffffu, s0, 2);
        s1 += __shfl_xor_sync(0xffffffffu, s1, 1);
        s1 += __shfl_xor_sync(0xffffffffu, s1, 2);
        if ((lane & 3) == 0) {
            redmax[wn * 64 + r0] = mx0; redsum[wn * 64 + r0] = s0;
            redmax[wn * 64 + r1] = mx1; redsum[wn * 64 + r1] = s1;
        }
        __syncthreads();
        {
            float gm0 = -FLT_MAX, gm1 = -FLT_MAX;
#pragma unroll
            for (int qd = 0; qd < 4; qd++) {
                gm0 = fmaxf(gm0, redmax[qd * 64 + r0]);
                gm1 = fmaxf(gm1, redmax[qd * 64 + r1]);
            }
            float S0 = 0.0f, S1 = 0.0f;
#pragma unroll
            for (int qd = 0; qd < 4; qd++) {
                S0 += redsum[qd * 64 + r0] * fexp(redmax[qd * 64 + r0] - gm0);
                S1 += redsum[qd * 64 + r1] * fexp(redmax[qd * 64 + r1] - gm1);
            }
            float f0 = fexp(mx0 - gm0) / S0;
            float f1 = fexp(mx1 - gm1) / S1;
#pragma unroll
            for (int t = 0; t < 12; t++) {
                c[t][0] *= f0; c[t][1] *= f0;
                c[t][2] *= f1; c[t][3] *= f1;
            }
        }

        // ---- phase 3: O = P V ----
        float oc[4][4];
#pragma unroll
        for (int nt = 0; nt < 4; nt++)
#pragma unroll
            for (int e = 0; e < 4; e++) oc[nt][e] = 0.0f;

#pragma unroll
        for (int kt = 0; kt < 6; kt++) {
            uint32_t ph[4], pl[4];
#pragma unroll
            for (int half = 0; half < 2; half++) {
                const float* cc = c[2 * kt + half];
                __nv_bfloat16 h0 = __float2bfloat16(cc[0]);
                __nv_bfloat16 h1 = __float2bfloat16(cc[1]);
                __nv_bfloat16 h2 = __float2bfloat16(cc[2]);
                __nv_bfloat16 h3 = __float2bfloat16(cc[3]);
                ph[half * 2 + 0] = packbf(__bfloat162float(h0), __bfloat162float(h1));
                ph[half * 2 + 1] = packbf(__bfloat162float(h2), __bfloat162float(h3));
                pl[half * 2 + 0] = packbf(cc[0] - __bfloat162float(h0),
                                          cc[1] - __bfloat162float(h1));
                pl[half * 2 + 1] = packbf(cc[2] - __bfloat162float(h2),
                                          cc[3] - __bfloat162float(h3));
            }
            const int krow = nbase + kt * 16;
            uint32_t vh[2][4], vl[2][4];
#pragma unroll
            for (int g = 0; g < 2; g++) {
                uint32_t ad = (uint32_t)((krow + arow) * ASTR + g * 16 + acolo) * 2;
                ldsm_x4_t(vh[g][0], vh[g][1], vh[g][2], vh[g][3], smb + OFF_VH + ad);
                ldsm_x4_t(vl[g][0], vl[g][1], vl[g][2], vl[g][3], smb + OFF_VL + ad);
            }
#pragma unroll
            for (int nt = 0; nt < 4; nt++) {
                const int g = nt >> 1, i2 = (nt & 1) * 2;
                mma16816(oc[nt], ph, vh[g][i2], vh[g][i2 + 1]);
                mma16816(oc[nt], pl, vh[g][i2], vh[g][i2 + 1]);
                mma16816(oc[nt], ph, vl[g][i2], vl[g][i2 + 1]);
            }
        }

        // ---- cross-quarter O reduction + split store ----
        if (wn > 0) {
            float* dst = ored + (size_t)(wn - 1) * (64 * ORSTR);
#pragma unroll
            for (int nt = 0; nt < 4; nt++) {
                *(float2*)(dst + r0 * ORSTR + nt * 8 + ncol) = make_float2(oc[nt][0], oc[nt][1]);
                *(float2*)(dst + r1 * ORSTR + nt * 8 + ncol) = make_float2(oc[nt][2], oc[nt][3]);
            }
        }
        __syncthreads();
        if (wn == 0) {
#pragma unroll
            for (int nt = 0; nt < 4; nt++) {
                float2 a0 = *(float2*)(ored + r0 * ORSTR + nt * 8 + ncol);
                float2 a1 = *(float2*)(ored + (64 * ORSTR) + r0 * ORSTR + nt * 8 + ncol);
                float2 a2 = *(float2*)(ored + (128 * ORSTR) + r0 * ORSTR + nt * 8 + ncol);
                float2 b0 = *(float2*)(ored + r1 * ORSTR + nt * 8 + ncol);
                float2 b1 = *(float2*)(ored + (64 * ORSTR) + r1 * ORSTR + nt * 8 + ncol);
                float2 b2 = *(float2*)(ored + (128 * ORSTR) + r1 * ORSTR + nt * 8 + ncol);
                float o00 = oc[nt][0] + a0.x + a1.x + a2.x;
                float o01 = oc[nt][1] + a0.y + a1.y + a2.y;
                float o10 = oc[nt][2] + b0.x + b1.x + b2.x;
                float o11 = oc[nt][3] + b0.y + b1.y + b2.y;
                int colg = h * HDs + nt * 8 + ncol;
                if (rv0) {
                    size_t ad = (size_t)(bb * Ls + qrow0) * Es + colg;
                    __nv_bfloat16 h0 = __float2bfloat16(o00), h1 = __float2bfloat16(o01);
                    *(uint32_t*)(g_ah + ad) = packbf(__bfloat162float(h0), __bfloat162float(h1));
                    *(uint32_t*)(g_al + ad) = packbf(o00 - __bfloat162float(h0),
                                                     o01 - __bfloat162float(h1));
                }
                if (rv1) {
                    size_t ad = (size_t)(bb * Ls + qrow1) * Es + colg;
                    __nv_bfloat16 h0 = __float2bfloat16(o10), h1 = __float2bfloat16(o11);
                    *(uint32_t*)(g_ah + ad) = packbf(__bfloat162float(h0), __bfloat162float(h1));
                    *(uint32_t*)(g_al + ad) = packbf(o10 - __bfloat162float(h0),
                                                     o11 - __bfloat162float(h1));
                }
            }
        }
    }
}

// ============================================================
// launch
// ============================================================
extern "C" void kernel_launch(void* const* d_in, const int* in_sizes, int n_in,
                              void* d_out, int out_size)
{
    (void)in_sizes; (void)n_in; (void)out_size;
    const float* query   = (const float*)d_in[0];
    const float* key     = (const float*)d_in[1];
    const float* value   = (const float*)d_in[2];
    const float* indices = (const float*)d_in[3];
    const void*  mask    = d_in[4];
    const float* Wq      = (const float*)d_in[5];
    const float* bq      = (const float*)d_in[6];
    const float* Wk      = (const float*)d_in[7];
    const float* bk      = (const float*)d_in[8];
    const float* Wv      = (const float*)d_in[9];
    const float* Ww      = (const float*)d_in[10];
    const float* bw      = (const float*)d_in[11];
    const float* scale   = (const float*)d_in[12];
    const float* W1      = (const float*)d_in[13];
    const float* b1      = (const float*)d_in[14];
    const float* W2      = (const float*)d_in[15];
    const float* b2      = (const float*)d_in[16];
    float* out = (float*)d_out;

    __nv_bfloat16 *pxqh, *pxql, *pxkh, *pxkl, *pxvh, *pxvl;
    __nv_bfloat16 *pah, *pal, *pwh, *pwl;
    __nv_bfloat16 *pqh, *pql, *pkh, *pkl, *pvh, *pvl;
    cudaGetSymbolAddress((void**)&pxqh, g_xqh);
    cudaGetSymbolAddress((void**)&pxql, g_xql);
    cudaGetSymbolAddress((void**)&pxkh, g_xkh);
    cudaGetSymbolAddress((void**)&pxkl, g_xkl);
    cudaGetSymbolAddress((void**)&pxvh, g_xvh);
    cudaGetSymbolAddress((void**)&pxvl, g_xvl);
    cudaGetSymbolAddress((void**)&pah,  g_ah);
    cudaGetSymbolAddress((void**)&pal,  g_al);
    cudaGetSymbolAddress((void**)&pwh,  g_w4h);
    cudaGetSymbolAddress((void**)&pwl,  g_w4l);
    cudaGetSymbolAddress((void**)&pqh,  g_qh);
    cudaGetSymbolAddress((void**)&pql,  g_ql);
    cudaGetSymbolAddress((void**)&pkh,  g_kh);
    cudaGetSymbolAddress((void**)&pkl,  g_kl);
    cudaGetSymbolAddress((void**)&pvh,  g_vh);
    cudaGetSymbolAddress((void**)&pvl,  g_vl);

    cudaFuncSetAttribute(tgemm_kernel, cudaFuncAttributeMaxDynamicSharedMemorySize,
                         TG_SMEM);
    cudaFuncSetAttribute(attn3_kernel, cudaFuncAttributeMaxDynamicSharedMemorySize,
                         ATT3_SMEM);

    const int n4 = ROWSs * Es / 4;
    const int splitg = (n4 + 255) / 256;
    const dim3 gg(ROWSs / 128, Es / 128);
    const size_t WSZ = (size_t)Es * Es;

    // 1-2: batched weight + input splits (independent of mask detect)
    wsplit_all_kernel<<<dim3(8, 8, 4), 256>>>(Wq, Wk, Wv, Ww);
    split3_kernel<<<dim3(splitg, 3), 256>>>((const float4*)query, (const float4*)key,
                                            (const float4*)value, n4);
    // 3: mask dtype detect
    detect_mask_kernel<<<1, 256>>>((const unsigned int*)mask);
    // 4: Q projection + fused norm + bf16 split  (ncu-captured slot)
    tgemm_kernel<<<gg, 256, TG_SMEM>>>(pxqh, pxql, pwh + 0 * WSZ, pwl + 0 * WSZ,
                                       bq, nullptr, 1, pqh, pql, 1);
    // 5: K projection + fused norm
    tgemm_kernel<<<gg, 256, TG_SMEM>>>(pxkh, pxkl, pwh + 1 * WSZ, pwl + 1 * WSZ,
                                       bk, nullptr, 1, pkh, pkl, 1);
    // 6: V projection (bf16 split out, no norm)
    tgemm_kernel<<<gg, 256, TG_SMEM>>>(pxvh, pxvl, pwh + 2 * WSZ, pwl + 2 * WSZ,
                                       nullptr, nullptr, 1, pvh, pvl, 0);
    // 7-8: mask table + bias table
    mask_prep_kernel<<<(BBs * LLs + 255) / 256, 256>>>(mask);
    bias_kernel<<<(LLs + 1023) / 1024, 256>>>(indices, W1, b1, W2, b2);
    // 9: persistent tensorized attention
    attn3_kernel<<<dim3(Hs, BBs), 512, ATT3_SMEM>>>(scale);
    // 10: output projection -> d_out
    tgemm_kernel<<<gg, 256, TG_SMEM>>>(pah, pal, pwh + 3 * WSZ, pwl + 3 * WSZ,
                                       bw, out, 0, nullptr, nullptr, 0);
}

// round 10
// speedup vs baseline: 3.4528x; 1.0691x over previous
#include <cuda_runtime.h>
#include <cuda_bf16.h>
#include <math.h>
#include <float.h>
#include <stdint.h>

// Problem dims
#define BBs   128
#define Ls    343
#define Es    256
#define Hs    8
#define HDs   32
#define HIDs  512
#define LLs   (Ls * Ls)       // 117649
#define ROWSs (BBs * Ls)      // 43904
#define LPAD  344
#define NCLS  2197            // 13^3 distinct index triples

// -------- scratch (device globals; no allocation allowed) --------
__device__ float g_bias[Hs * Ls * LPAD];
__device__ __align__(16) float g_blut[NCLS * 8];
__device__ int   g_mask_mode;
__device__ uint8_t g_mask8[BBs * Ls * LPAD];
__device__ __nv_bfloat16 g_xqh[ROWSs * Es], g_xql[ROWSs * Es];
__device__ __nv_bfloat16 g_xkh[ROWSs * Es], g_xkl[ROWSs * Es];
__device__ __nv_bfloat16 g_xvh[ROWSs * Es], g_xvl[ROWSs * Es];
__device__ __nv_bfloat16 g_ah[ROWSs * Es], g_al[ROWSs * Es];
__device__ __nv_bfloat16 g_w4h[4 * Es * Es], g_w4l[4 * Es * Es];
__device__ __nv_bfloat16 g_qh[BBs * Hs * Ls * HDs], g_ql[BBs * Hs * Ls * HDs];
__device__ __nv_bfloat16 g_kh[BBs * Hs * Ls * HDs], g_kl[BBs * Hs * Ls * HDs];
__device__ __nv_bfloat16 g_vh[BBs * Hs * Ls * HDs], g_vl[BBs * Hs * Ls * HDs];

// ============================================================
// PTX helpers (baseline sm_80+ ISA; harness targets sm_103 w/o 'a')
// ============================================================
__device__ __forceinline__ uint32_t smem_u32(const void* p) {
    uint32_t a;
    asm("{ .reg .u64 t; cvta.to.shared.u64 t, %1; cvt.u32.u64 %0, t; }" : "=r"(a) : "l"(p));
    return a;
}
__device__ __forceinline__ void ldsm_x4(uint32_t& r0, uint32_t& r1, uint32_t& r2,
                                        uint32_t& r3, uint32_t addr) {
    asm volatile("ldmatrix.sync.aligned.m8n8.x4.shared.b16 {%0,%1,%2,%3}, [%4];"
                 : "=r"(r0), "=r"(r1), "=r"(r2), "=r"(r3) : "r"(addr));
}
__device__ __forceinline__ void ldsm_x4_t(uint32_t& r0, uint32_t& r1, uint32_t& r2,
                                          uint32_t& r3, uint32_t addr) {
    asm volatile("ldmatrix.sync.aligned.m8n8.x4.trans.shared.b16 {%0,%1,%2,%3}, [%4];"
                 : "=r"(r0), "=r"(r1), "=r"(r2), "=r"(r3) : "r"(addr));
}
__device__ __forceinline__ void mma16816(float* c, const uint32_t* a,
                                         uint32_t b0, uint32_t b1) {
    asm volatile(
        "mma.sync.aligned.m16n8k16.row.col.f32.bf16.bf16.f32 "
        "{%0,%1,%2,%3}, {%4,%5,%6,%7}, {%8,%9}, {%0,%1,%2,%3};"
        : "+f"(c[0]), "+f"(c[1]), "+f"(c[2]), "+f"(c[3])
        : "r"(a[0]), "r"(a[1]), "r"(a[2]), "r"(a[3]), "r"(b0), "r"(b1));
}
__device__ __forceinline__ void cp_async16(uint32_t dst, const void* src) {
    asm volatile("cp.async.cg.shared.global [%0], [%1], 16;" :: "r"(dst), "l"(src));
}
__device__ __forceinline__ void cp_commit() { asm volatile("cp.async.commit_group;"); }
__device__ __forceinline__ void cp_wait1() { asm volatile("cp.async.wait_group 1;"); }
__device__ __forceinline__ void cp_wait0() { asm volatile("cp.async.wait_group 0;"); }

// pack (c0,c1) -> bf16x2 hi + bf16x2 lo residual (6-instr path)
__device__ __forceinline__ void pack2(float c0, float c1, uint32_t& hi, uint32_t& lo) {
    __nv_bfloat162 t = __floats2bfloat162_rn(c0, c1);
    uint32_t h = *(uint32_t*)&t;
    float h0 = __int_as_float(h << 16);
    float h1 = __int_as_float(h & 0xffff0000u);
    __nv_bfloat162 t2 = __floats2bfloat162_rn(c0 - h0, c1 - h1);
    hi = h; lo = *(uint32_t*)&t2;
}

// Fast exp on FMA/ALU pipes only (no MUFU). rel err ~2.4e-6.
__device__ __forceinline__ float fexp(float x) {
    float y = fmaxf(x * 1.4426950408889634f, -126.0f);
    float yr = __fadd_rn(y, 12582912.0f);
    float n  = __fsub_rn(yr, 12582912.0f);
    float f  = __fsub_rn(y, n);
    float p  = 1.3333558e-3f;
    p = fmaf(p, f, 9.6181291e-3f);
    p = fmaf(p, f, 5.5504109e-2f);
    p = fmaf(p, f, 2.4022651e-1f);
    p = fmaf(p, f, 6.9314718e-1f);
    p = fmaf(p, f, 1.0f);
    return __int_as_float(__float_as_int(p) + (__float_as_int(yr) << 23));
}

// ============================================================
// Kernel: detect mask dtype
// ============================================================
__global__ void detect_mask_kernel(const unsigned int* __restrict__ m)
{
    __shared__ int s_float, s_multi;
    if (threadIdx.x == 0) { s_float = 0; s_multi = 0; }
    __syncthreads();
    for (int i = threadIdx.x; i < 4096; i += 256) {
        unsigned int w = m[i];
        if (w == 0x3F800000u) atomicOr(&s_float, 1);
        else if (w != 0u && (w & 0xFFFFFF00u) != 0u) atomicOr(&s_multi, 1);
    }
    __syncthreads();
    if (threadIdx.x == 0)
        g_mask_mode = s_float ? 2 : (s_multi ? 0 : 1);
}

// ============================================================
// Kernel: normalize mask to padded uint8 table
// ============================================================
__global__ __launch_bounds__(256) void mask_prep_kernel(const void* __restrict__ maskp)
{
    int idx = blockIdx.x * 256 + threadIdx.x;
    if (idx >= BBs * LLs) return;
    int bb = idx / LLs;
    int p = idx - bb * LLs;
    int i = p / Ls, j = p - i * Ls;
    int mode = g_mask_mode;
    bool m = (mode == 0) ? (((const uint8_t*)maskp)[idx] != 0)
           : (mode == 1) ? (((const int*)maskp)[idx] != 0)
                         : (((const float*)maskp)[idx] != 0.0f);
    g_mask8[(size_t)bb * (Ls * LPAD) + i * LPAD + j] = m ? 1 : 0;
}

// ============================================================
// Kernel: CPB LUT — one warp per distinct index-triple class.
// ============================================================
__global__ __launch_bounds__(256) void bias_lut_kernel(
    const float* __restrict__ W1, const float* __restrict__ b1,
    const float* __restrict__ W2, const float* __restrict__ b2)
{
    int wid = threadIdx.x >> 5, lane = threadIdx.x & 31;
    int cls = blockIdx.x * 8 + wid;
    if (cls >= NCLS) return;
    int d0 = cls % 13 - 6;
    int d1 = (cls / 13) % 13 - 6;
    int d2 = cls / 169 - 6;
    float x0 = copysignf(log2f(1.0f + fabsf((float)d0)) * (1.0f / 3.0f), (float)d0);
    float x1 = copysignf(log2f(1.0f + fabsf((float)d1)) * (1.0f / 3.0f), (float)d1);
    float x2 = copysignf(log2f(1.0f + fabsf((float)d2)) * (1.0f / 3.0f), (float)d2);
    float acc[8];
#pragma unroll
    for (int h = 0; h < 8; h++) acc[h] = 0.0f;
    for (int t = lane; t < HIDs; t += 32) {
        float hv = fmaxf(fmaf(x0, W1[t], fmaf(x1, W1[HIDs + t],
                        fmaf(x2, W1[2 * HIDs + t], b1[t]))), 0.0f);
#pragma unroll
        for (int h = 0; h < 8; h++) acc[h] = fmaf(hv, W2[t * 8 + h], acc[h]);
    }
#pragma unroll
    for (int h = 0; h < 8; h++) {
#pragma unroll
        for (int o = 16; o > 0; o >>= 1)
            acc[h] += __shfl_xor_sync(0xffffffffu, acc[h], o);
    }
    if (lane == 0) {
#pragma unroll
        for (int h = 0; h < 8; h++) {
            float z = acc[h] + b2[h];
            g_blut[cls * 8 + h] = 16.0f / (1.0f + fexp(-z));
        }
    }
}

// ============================================================
// Kernel: gather LUT -> padded bias planes
// ============================================================
__global__ __launch_bounds__(256) void bias_gather_kernel(
    const float* __restrict__ indices)
{
    int p = blockIdx.x * 256 + threadIdx.x;
    if (p >= LLs) return;
    int i = p / Ls, j = p - i * Ls;
    int q0 = __float2int_rn(indices[p * 3 + 0]) + 6;
    int q1 = __float2int_rn(indices[p * 3 + 1]) + 6;
    int q2 = __float2int_rn(indices[p * 3 + 2]) + 6;
    int cls = q0 + 13 * q1 + 169 * q2;
    float4 v0 = *(const float4*)(g_blut + cls * 8);
    float4 v1 = *(const float4*)(g_blut + cls * 8 + 4);
    float vals[8] = { v0.x, v0.y, v0.z, v0.w, v1.x, v1.y, v1.z, v1.w };
#pragma unroll
    for (int h = 0; h < 8; h++)
        g_bias[(size_t)h * (Ls * LPAD) + i * LPAD + j] = vals[h];
}

// ============================================================
// Kernel: split all 3 fp32 inputs -> bf16 hi/lo (batched, grid.y=3)
// ============================================================
__global__ __launch_bounds__(256) void split3_kernel(
    const float4* __restrict__ q, const float4* __restrict__ k,
    const float4* __restrict__ v, int n4)
{
    const int z = blockIdx.y;
    const float4* in = (z == 0) ? q : (z == 1) ? k : v;
    ushort4* hi = (ushort4*)((z == 0) ? g_xqh : (z == 1) ? g_xkh : g_xvh);
    ushort4* lo = (ushort4*)((z == 0) ? g_xql : (z == 1) ? g_xkl : g_xvl);
    int i = blockIdx.x * 256 + threadIdx.x;
    if (i >= n4) return;
    float4 val = in[i];
    uint32_t h01, l01, h23, l23;
    pack2(val.x, val.y, h01, l01);
    pack2(val.z, val.w, h23, l23);
    *(uint2*)(hi + i) = make_uint2(h01, h23);
    *(uint2*)(lo + i) = make_uint2(l01, l23);
}

// ============================================================
// Kernel: all 4 weight transposes + splits (batched, grid.z=4)
// ============================================================
__global__ __launch_bounds__(256) void wsplit_all_kernel(
    const float* __restrict__ Wq, const float* __restrict__ Wk,
    const float* __restrict__ Wv, const float* __restrict__ Ww)
{
    __shared__ float t[32][33];
    const int z = blockIdx.z;
    const float* W = (z == 0) ? Wq : (z == 1) ? Wk : (z == 2) ? Wv : Ww;
    __nv_bfloat16* ht = g_w4h + (size_t)z * Es * Es;
    __nv_bfloat16* lt = g_w4l + (size_t)z * Es * Es;
    int bn = blockIdx.x * 32, bk = blockIdx.y * 32;
    int lx = threadIdx.x & 31, ly = threadIdx.x >> 5;
    for (int yy = ly; yy < 32; yy += 8)
        t[yy][lx] = W[(size_t)(bk + yy) * Es + bn + lx];
    __syncthreads();
    for (int yy = ly; yy < 32; yy += 8) {
        float v = t[lx][yy];
        __nv_bfloat16 h = __float2bfloat16(v);
        __nv_bfloat16 l = __float2bfloat16(v - __bfloat162float(h));
        size_t o = (size_t)(bn + yy) * Es + bk + lx;
        ht[o] = h; lt[o] = l;
    }
}

// ============================================================
// Kernel: mma.sync bf16 split-GEMM. 3-stage cp.async pipeline.
// Per chunk: cp_wait (own copies) -> __syncthreads (cross-thread
// visibility + retire prev stage) -> prefetch next -> compute.
// ============================================================
#define TGS 72
#define TGBUF 18432                   // 128 x 72 x 2B
#define TGSTAGE (2 * TGBUF)           // A + B per stage
#define TG_SMEM (3 * TGSTAGE)         // 110592 B -> 2 CTAs/SM

__global__ __launch_bounds__(256) void tgemm_kernel(
    const __nv_bfloat16* __restrict__ Ah, const __nv_bfloat16* __restrict__ Al,
    const __nv_bfloat16* __restrict__ Wh, const __nv_bfloat16* __restrict__ Wl,
    const float* __restrict__ bias, float* __restrict__ C, int remap,
    __nv_bfloat16* __restrict__ Oh, __nv_bfloat16* __restrict__ Ol, int donorm)
{
    extern __shared__ char dsm[];
    const int tid = threadIdx.x;
    const int wid = tid >> 5;
    const int lane = tid & 31;
    const int m0 = blockIdx.x * 128;
    const int n0 = blockIdx.y * 128;
    const int wm = wid & 1;
    const int wn = wid >> 1;
    const uint32_t smb = smem_u32(dsm);

    float c[4][4][4];
#pragma unroll
    for (int i = 0; i < 4; i++)
#pragma unroll
        for (int j = 0; j < 4; j++)
#pragma unroll
            for (int k = 0; k < 4; k++) c[i][j][k] = 0.0f;

    auto prefetch = [&](int i) {
        const int t = i >> 2, kc = i & 3, s = i % 3;
        const __nv_bfloat16* As = (t == 1) ? Al : Ah;
        const __nv_bfloat16* Bs = (t == 2) ? Wl : Wh;
        const int k0 = kc * 64;
        const uint32_t bA = smb + s * TGSTAGE;
        const uint32_t bB = bA + TGBUF;
#pragma unroll
        for (int j = 0; j < 4; j++) {
            int x = tid + j * 256;
            int r = x >> 3, cc = x & 7;
            uint32_t off = (uint32_t)(r * TGS + cc * 8) * 2;
            cp_async16(bA + off, As + (size_t)(m0 + r) * Es + k0 + cc * 8);
            cp_async16(bB + off, Bs + (size_t)(n0 + r) * Es + k0 + cc * 8);
        }
    };

    prefetch(0); cp_commit();
    prefetch(1); cp_commit();

    const int arow = (lane & 7) + ((lane >> 3) & 1) * 8;
    const int acolo = ((lane >> 4) & 1) * 8;
    const int brow = (lane & 7) + ((lane >> 4) & 1) * 8;
    const int bcolo = ((lane >> 3) & 1) * 8;

    for (int i = 0; i < 12; i++) {
        // 1) own group i complete
        if (i < 11) cp_wait1(); else cp_wait0();
        // 2) cross-thread visibility of group i; all warps retired chunk i-1
        __syncthreads();
        // 3) safe to overwrite chunk i-1's stage ((i+2)%3)
        if (i < 10) { prefetch(i + 2); cp_commit(); }

        const uint32_t bA = smb + (i % 3) * TGSTAGE;
        const uint32_t bB = bA + TGBUF;
#pragma unroll
        for (int ks = 0; ks < 4; ks++) {
            const int k0 = ks * 16;
            uint32_t a[4][4], b[2][4];
#pragma unroll
            for (int mt = 0; mt < 4; mt++)
                ldsm_x4(a[mt][0], a[mt][1], a[mt][2], a[mt][3],
                        bA + (uint32_t)((wm * 64 + mt * 16 + arow) * TGS + k0 + acolo) * 2);
#pragma unroll
            for (int g = 0; g < 2; g++)
                ldsm_x4(b[g][0], b[g][1], b[g][2], b[g][3],
                        bB + (uint32_t)((wn * 32 + g * 16 + brow) * TGS + k0 + bcolo) * 2);
#pragma unroll
            for (int mt = 0; mt < 4; mt++)
#pragma unroll
                for (int nt = 0; nt < 4; nt++)
                    mma16816(c[mt][nt], a[mt], b[nt >> 1][(nt & 1) * 2],
                             b[nt >> 1][(nt & 1) * 2 + 1]);
        }
    }

    const int tq = lane >> 2;
    const int tr = lane & 3;
#pragma unroll
    for (int mt = 0; mt < 4; mt++) {
        const int m = m0 + wm * 64 + mt * 16 + tq;
        float v0x[4], v0y[4], v1x[4], v1y[4];
#pragma unroll
        for (int nt = 0; nt < 4; nt++) {
            const int n = n0 + wn * 32 + nt * 8 + tr * 2;
            float bx = 0.0f, by = 0.0f;
            if (bias) { float2 bv = *(const float2*)(bias + n); bx = bv.x; by = bv.y; }
            v0x[nt] = c[mt][nt][0] + bx; v0y[nt] = c[mt][nt][1] + by;
            v1x[nt] = c[mt][nt][2] + bx; v1y[nt] = c[mt][nt][3] + by;
        }
        if (donorm) {
            float ss0 = 0.0f, ss1 = 0.0f;
#pragma unroll
            for (int nt = 0; nt < 4; nt++) {
                ss0 = fmaf(v0x[nt], v0x[nt], fmaf(v0y[nt], v0y[nt], ss0));
                ss1 = fmaf(v1x[nt], v1x[nt], fmaf(v1y[nt], v1y[nt], ss1));
            }
            ss0 += __shfl_xor_sync(0xffffffffu, ss0, 1);
            ss0 += __shfl_xor_sync(0xffffffffu, ss0, 2);
            ss1 += __shfl_xor_sync(0xffffffffu, ss1, 1);
            ss1 += __shfl_xor_sync(0xffffffffu, ss1, 2);
            float i0 = 1.0f / fmaxf(sqrtf(ss0), 1e-12f);
            float i1 = 1.0f / fmaxf(sqrtf(ss1), 1e-12f);
#pragma unroll
            for (int nt = 0; nt < 4; nt++) {
                v0x[nt] *= i0; v0y[nt] *= i0;
                v1x[nt] *= i1; v1y[nt] *= i1;
            }
        }
#pragma unroll
        for (int nt = 0; nt < 4; nt++) {
            const int n = n0 + wn * 32 + nt * 8 + tr * 2;
            size_t a0, a1;
            if (remap) {
                const int hh = n >> 5, hd = n & 31;
                int bbw = m / Ls, l = m - bbw * Ls;
                a0 = ((size_t)(bbw * Hs + hh) * Ls + l) * HDs + hd;
                int m2 = m + 8;
                int bbw2 = m2 / Ls, l2 = m2 - bbw2 * Ls;
                a1 = ((size_t)(bbw2 * Hs + hh) * Ls + l2) * HDs + hd;
            } else {
                a0 = (size_t)m * Es + n;
                a1 = (size_t)(m + 8) * Es + n;
            }
            if (Oh) {
                uint32_t h0, l0, h1, l1;
                pack2(v0x[nt], v0y[nt], h0, l0);
                pack2(v1x[nt], v1y[nt], h1, l1);
                *(uint32_t*)(Oh + a0) = h0;
                *(uint32_t*)(Oh + a1) = h1;
                *(uint32_t*)(Ol + a0) = l0;
                *(uint32_t*)(Ol + a1) = l1;
            } else {
                *(float2*)(C + a0) = make_float2(v0x[nt], v0y[nt]);
                *(float2*)(C + a1) = make_float2(v1x[nt], v1y[nt]);
            }
        }
    }
}

// ============================================================
// Kernel: persistent tensorized attention per (head, window).
// 512 threads / 16 warps; whole K/V/Q hi/lo resident in SMEM.
// 2 syncs per q-tile; distributed O reduce across all warps.
// ============================================================
#define ASTR 40
#define ABUF 30720
#define OFF_KH (0 * ABUF)
#define OFF_KL (1 * ABUF)
#define OFF_VH (2 * ABUF)
#define OFF_VL (3 * ABUF)
#define OFF_QH (4 * ABUF)
#define OFF_QL (5 * ABUF)
#define OFF_RMAX (6 * ABUF)
#define OFF_RSUM (OFF_RMAX + 1024)
#define OFF_ORED (OFF_RSUM + 1024)
#define ORSTR 34
#define ATT3_SMEM (OFF_ORED + 4 * 64 * ORSTR * 4)   // 221184

__global__ __launch_bounds__(512) void attn3_kernel(const float* __restrict__ scalep)
{
    extern __shared__ char sm2[];
    float* redmax = (float*)(sm2 + OFF_RMAX);
    float* redsum = (float*)(sm2 + OFF_RSUM);
    float* ored   = (float*)(sm2 + OFF_ORED);
    const uint32_t smb = smem_u32(sm2);

    const int tid = threadIdx.x;
    const int wid = tid >> 5;
    const int lane = tid & 31;
    const int h = blockIdx.x;
    const int bb = blockIdx.y;
    const size_t gbase = (size_t)(bb * Hs + h) * (Ls * HDs);

    // ---- fill K/V/Q hi+lo once (wait -> sync: correct cp.async protocol) ----
    {
        const __nv_bfloat16* gsrc[6] = { g_kh + gbase, g_kl + gbase, g_vh + gbase,
                                         g_vl + gbase, g_qh + gbase, g_ql + gbase };
#pragma unroll
        for (int arr = 0; arr < 6; arr++)
            for (int i = tid; i < 1372; i += 512) {
                int row = i >> 2, ch = i & 3;
                cp_async16(smb + arr * ABUF + row * 80 + ch * 16,
                           gsrc[arr] + row * HDs + ch * 8);
            }
        for (int i = tid; i < 984; i += 512) {
            int arr = i / 164, j = i - arr * 164;
            int r = 343 + (j >> 2), ch = j & 3;
            *(uint4*)(sm2 + arr * ABUF + r * 80 + ch * 16) = make_uint4(0, 0, 0, 0);
        }
        cp_commit();
        cp_wait0();
        __syncthreads();
    }

    const int wm = wid & 3;
    const int wn = wid >> 2;
    const int nbase = wn * 96;

    const int arow = (lane & 7) + ((lane >> 3) & 1) * 8;
    const int acolo = ((lane >> 4) & 1) * 8;
    const int brow = (lane & 7) + ((lane >> 4) & 1) * 8;
    const int bcolo = ((lane >> 3) & 1) * 8;

    const float invscale = 1.0f / fmaxf(scalep[0], 0.01f);
    const float* bias0 = g_bias + (size_t)h * (Ls * LPAD);
    const uint8_t* mrow = g_mask8 + (size_t)bb * (Ls * LPAD);
    const int r0 = wm * 16 + (lane >> 2);
    const int r1 = r0 + 8;
    const int ncol = (lane & 3) * 2;
    const int lane16 = lane & 15;
    const int halfr = lane >> 4;

    for (int qt = 0; qt < 6; qt++) {
        const int q0 = qt * 64;

        // ---- Q fragments from resident buffer ----
        uint32_t qh[2][4], ql[2][4];
#pragma unroll
        for (int kk = 0; kk < 2; kk++) {
            uint32_t ro = (uint32_t)((q0 + wm * 16 + arow) * ASTR + kk * 16 + acolo) * 2;
            ldsm_x4(qh[kk][0], qh[kk][1], qh[kk][2], qh[kk][3], smb + OFF_QH + ro);
            ldsm_x4(ql[kk][0], ql[kk][1], ql[kk][2], ql[kk][3], smb + OFF_QL + ro);
        }

        // ---- phase 1: S fragments ----
        float c[12][4];
#pragma unroll
        for (int t = 0; t < 12; t++)
#pragma unroll
            for (int e = 0; e < 4; e++) c[t][e] = 0.0f;

#pragma unroll
        for (int g = 0; g < 6; g++) {
            uint32_t bh[2][4], bl[2][4];
#pragma unroll
            for (int kk = 0; kk < 2; kk++) {
                uint32_t rb = (uint32_t)((nbase + g * 16 + brow) * ASTR + kk * 16 + bcolo) * 2;
                ldsm_x4(bh[kk][0], bh[kk][1], bh[kk][2], bh[kk][3], smb + OFF_KH + rb);
                ldsm_x4(bl[kk][0], bl[kk][1], bl[kk][2], bl[kk][3], smb + OFF_KL + rb);
            }
#pragma unroll
            for (int kk = 0; kk < 2; kk++)
#pragma unroll
                for (int nt = 0; nt < 2; nt++) {
                    float* cc = c[g * 2 + nt];
                    mma16816(cc, qh[kk], bh[kk][nt * 2], bh[kk][nt * 2 + 1]);
                    mma16816(cc, ql[kk], bh[kk][nt * 2], bh[kk][nt * 2 + 1]);
                    mma16816(cc, qh[kk], bl[kk][nt * 2], bl[kk][nt * 2 + 1]);
                }
        }

        // ---- scale + bias + mask ----
        const int qrow0 = q0 + r0, qrow1 = q0 + r1;
        const bool rv0 = qrow0 < Ls, rv1 = qrow1 < Ls;
#pragma unroll
        for (int t = 0; t < 12; t++) {
            int col = nbase + t * 8 + ncol;
            bool cv0 = col < Ls, cv1 = (col + 1) < Ls;
            float2 b0v = make_float2(0.f, 0.f), b1v = make_float2(0.f, 0.f);
            uchar2 m0v = make_uchar2(0, 0), m1v = make_uchar2(0, 0);
            if (rv0 && cv0) {
                b0v = *(const float2*)(bias0 + (size_t)qrow0 * LPAD + col);
                m0v = *(const uchar2*)(mrow + (size_t)qrow0 * LPAD + col);
            }
            if (rv1 && cv0) {
                b1v = *(const float2*)(bias0 + (size_t)qrow1 * LPAD + col);
                m1v = *(const uchar2*)(mrow + (size_t)qrow1 * LPAD + col);
            }
            c[t][0] = (rv0 && cv0) ? (m0v.x ? -100000.0f : fmaf(c[t][0], invscale, b0v.x)) : -1e9f;
            c[t][1] = (rv0 && cv1) ? (m0v.y ? -100000.0f : fmaf(c[t][1], invscale, b0v.y)) : -1e9f;
            c[t][2] = (rv1 && cv0) ? (m1v.x ? -100000.0f : fmaf(c[t][2], invscale, b1v.x)) : -1e9f;
            c[t][3] = (rv1 && cv1) ? (m1v.y ? -100000.0f : fmaf(c[t][3], invscale, b1v.y)) : -1e9f;
        }

        // ---- single-sync softmax ----
        float mx0 = -FLT_MAX, mx1 = -FLT_MAX;
#pragma unroll
        for (int t = 0; t < 12; t++) {
            mx0 = fmaxf(mx0, fmaxf(c[t][0], c[t][1]));
            mx1 = fmaxf(mx1, fmaxf(c[t][2], c[t][3]));
        }
        mx0 = fmaxf(mx0, __shfl_xor_sync(0xffffffffu, mx0, 1));
        mx0 = fmaxf(mx0, __shfl_xor_sync(0xffffffffu, mx0, 2));
        mx1 = fmaxf(mx1, __shfl_xor_sync(0xffffffffu, mx1, 1));
        mx1 = fmaxf(mx1, __shfl_xor_sync(0xffffffffu, mx1, 2));

        float s0 = 0.0f, s1 = 0.0f;
#pragma unroll
        for (int t = 0; t < 12; t++) {
            float e0 = fexp(c[t][0] - mx0); c[t][0] = e0; s0 += e0;
            float e1 = fexp(c[t][1] - mx0); c[t][1] = e1; s0 += e1;
            float e2 = fexp(c[t][2] - mx1); c[t][2] = e2; s1 += e2;
            float e3 = fexp(c[t][3] - mx1); c[t][3] = e3; s1 += e3;
        }
        s0 += __shfl_xor_sync(0xffffffffu, s0, 1);
        s0 += __shfl_xor_sync(0xffffffffu, s0, 2);
        s1 += __shfl_xor_sync(0xffffffffu, s1, 1);
        s1 += __shfl_xor_sync(0xffffffffu, s1, 2);
        if ((lane & 3) == 0) {
            redmax[wn * 64 + r0] = mx0; redsum[wn * 64 + r0] = s0;
            redmax[wn * 64 + r1] = mx1; redsum[wn * 64 + r1] = s1;
        }
        __syncthreads();
        {
            float gm0 = -FLT_MAX, gm1 = -FLT_MAX;
#pragma unroll
            for (int qd = 0; qd < 4; qd++) {
                gm0 = fmaxf(gm0, redmax[qd * 64 + r0]);
                gm1 = fmaxf(gm1, redmax[qd * 64 + r1]);
            }
            float S0 = 0.0f, S1 = 0.0f;
#pragma unroll
            for (int qd = 0; qd < 4; qd++) {
                S0 += redsum[qd * 64 + r0] * fexp(redmax[qd * 64 + r0] - gm0);
                S1 += redsum[qd * 64 + r1] * fexp(redmax[qd * 64 + r1] - gm1);
            }
            float f0 = fexp(mx0 - gm0) / S0;
            float f1 = fexp(mx1 - gm1) / S1;
#pragma unroll
            for (int t = 0; t < 12; t++) {
                c[t][0] *= f0; c[t][1] *= f0;
                c[t][2] *= f1; c[t][3] *= f1;
            }
        }

        // ---- phase 3: O = P V ----
        float oc[4][4];
#pragma unroll
        for (int nt = 0; nt < 4; nt++)
#pragma unroll
            for (int e = 0; e < 4; e++) oc[nt][e] = 0.0f;

#pragma unroll
        for (int kt = 0; kt < 6; kt++) {
            uint32_t ph[4], pl[4];
#pragma unroll
            for (int half = 0; half < 2; half++) {
                const float* cc = c[2 * kt + half];
                pack2(cc[0], cc[1], ph[half * 2 + 0], pl[half * 2 + 0]);
                pack2(cc[2], cc[3], ph[half * 2 + 1], pl[half * 2 + 1]);
            }
            const int krow = nbase + kt * 16;
            uint32_t vh[2][4], vl[2][4];
#pragma unroll
            for (int g = 0; g < 2; g++) {
                uint32_t ad = (uint32_t)((krow + arow) * ASTR + g * 16 + acolo) * 2;
                ldsm_x4_t(vh[g][0], vh[g][1], vh[g][2], vh[g][3], smb + OFF_VH + ad);
                ldsm_x4_t(vl[g][0], vl[g][1], vl[g][2], vl[g][3], smb + OFF_VL + ad);
            }
#pragma unroll
            for (int nt = 0; nt < 4; nt++) {
                const int g = nt >> 1, i2 = (nt & 1) * 2;
                mma16816(oc[nt], ph, vh[g][i2], vh[g][i2 + 1]);
                mma16816(oc[nt], pl, vh[g][i2], vh[g][i2 + 1]);
                mma16816(oc[nt], ph, vl[g][i2], vl[g][i2 + 1]);
            }
        }

        // ---- all quarters write slabs; distributed reduce + store ----
        {
            float* dst = ored + (size_t)wn * (64 * ORSTR);
#pragma unroll
            for (int nt = 0; nt < 4; nt++) {
                *(float2*)(dst + r0 * ORSTR + nt * 8 + ncol) = make_float2(oc[nt][0], oc[nt][1]);
                *(float2*)(dst + r1 * ORSTR + nt * 8 + ncol) = make_float2(oc[nt][2], oc[nt][3]);
            }
        }
        __syncthreads();
#pragma unroll
        for (int p = 0; p < 2; p++) {
            int row = wid * 4 + p * 2 + halfr;
            int qrow = q0 + row;
            if (qrow < Ls) {
                int col = lane16 * 2;
                float s0o = 0.0f, s1o = 0.0f;
#pragma unroll
                for (int qd = 0; qd < 4; qd++) {
                    float2 v = *(float2*)(ored + qd * (64 * ORSTR) + row * ORSTR + col);
                    s0o += v.x; s1o += v.y;
                }
                uint32_t hw, lw;
                pack2(s0o, s1o, hw, lw);
                size_t ad = (size_t)(bb * Ls + qrow) * Es + h * HDs + col;
                *(uint32_t*)(g_ah + ad) = hw;
                *(uint32_t*)(g_al + ad) = lw;
            }
        }
    }
}

// ============================================================
// launch
// ============================================================
extern "C" void kernel_launch(void* const* d_in, const int* in_sizes, int n_in,
                              void* d_out, int out_size)
{
    (void)in_sizes; (void)n_in; (void)out_size;
    const float* query   = (const float*)d_in[0];
    const float* key     = (const float*)d_in[1];
    const float* value   = (const float*)d_in[2];
    const float* indices = (const float*)d_in[3];
    const void*  mask    = d_in[4];
    const float* Wq      = (const float*)d_in[5];
    const float* bq      = (const float*)d_in[6];
    const float* Wk      = (const float*)d_in[7];
    const float* bk      = (const float*)d_in[8];
    const float* Wv      = (const float*)d_in[9];
    const float* Ww      = (const float*)d_in[10];
    const float* bw      = (const float*)d_in[11];
    const float* scale   = (const float*)d_in[12];
    const float* W1      = (const float*)d_in[13];
    const float* b1      = (const float*)d_in[14];
    const float* W2      = (const float*)d_in[15];
    const float* b2      = (const float*)d_in[16];
    float* out = (float*)d_out;

    __nv_bfloat16 *pxqh, *pxql, *pxkh, *pxkl, *pxvh, *pxvl;
    __nv_bfloat16 *pah, *pal, *pwh, *pwl;
    __nv_bfloat16 *pqh, *pql, *pkh, *pkl, *pvh, *pvl;
    cudaGetSymbolAddress((void**)&pxqh, g_xqh);
    cudaGetSymbolAddress((void**)&pxql, g_xql);
    cudaGetSymbolAddress((void**)&pxkh, g_xkh);
    cudaGetSymbolAddress((void**)&pxkl, g_xkl);
    cudaGetSymbolAddress((void**)&pxvh, g_xvh);
    cudaGetSymbolAddress((void**)&pxvl, g_xvl);
    cudaGetSymbolAddress((void**)&pah,  g_ah);
    cudaGetSymbolAddress((void**)&pal,  g_al);
    cudaGetSymbolAddress((void**)&pwh,  g_w4h);
    cudaGetSymbolAddress((void**)&pwl,  g_w4l);
    cudaGetSymbolAddress((void**)&pqh,  g_qh);
    cudaGetSymbolAddress((void**)&pql,  g_ql);
    cudaGetSymbolAddress((void**)&pkh,  g_kh);
    cudaGetSymbolAddress((void**)&pkl,  g_kl);
    cudaGetSymbolAddress((void**)&pvh,  g_vh);
    cudaGetSymbolAddress((void**)&pvl,  g_vl);

    cudaFuncSetAttribute(tgemm_kernel, cudaFuncAttributeMaxDynamicSharedMemorySize,
                         TG_SMEM);
    cudaFuncSetAttribute(attn3_kernel, cudaFuncAttributeMaxDynamicSharedMemorySize,
                         ATT3_SMEM);

    const int n4 = ROWSs * Es / 4;
    const int splitg = (n4 + 255) / 256;
    const dim3 gg(ROWSs / 128, Es / 128);
    const size_t WSZ = (size_t)Es * Es;

    wsplit_all_kernel<<<dim3(8, 8, 4), 256>>>(Wq, Wk, Wv, Ww);
    split3_kernel<<<dim3(splitg, 3), 256>>>((const float4*)query, (const float4*)key,
                                            (const float4*)value, n4);
    detect_mask_kernel<<<1, 256>>>((const unsigned int*)mask);
    // Q projection + fused norm + bf16 split  (ncu-captured slot)
    tgemm_kernel<<<gg, 256, TG_SMEM>>>(pxqh, pxql, pwh + 0 * WSZ, pwl + 0 * WSZ,
                                       bq, nullptr, 1, pqh, pql, 1);
    tgemm_kernel<<<gg, 256, TG_SMEM>>>(pxkh, pxkl, pwh + 1 * WSZ, pwl + 1 * WSZ,
                                       bk, nullptr, 1, pkh, pkl, 1);
    tgemm_kernel<<<gg, 256, TG_SMEM>>>(pxvh, pxvl, pwh + 2 * WSZ, pwl + 2 * WSZ,
                                       nullptr, nullptr, 1, pvh, pvl, 0);
    mask_prep_kernel<<<(BBs * LLs + 255) / 256, 256>>>(mask);
    bias_lut_kernel<<<(NCLS + 7) / 8, 256>>>(W1, b1, W2, b2);
    bias_gather_kernel<<<(LLs + 255) / 256, 256>>>(indices);
    attn3_kernel<<<dim3(Hs, BBs), 512, ATT3_SMEM>>>(scale);
    tgemm_kernel<<<gg, 256, TG_SMEM>>>(pah, pal, pwh + 3 * WSZ, pwl + 3 * WSZ,
                                       bw, out, 0, nullptr, nullptr, 0);
}

// round 11
// speedup vs baseline: 4.3520x; 1.2604x over previous
#include <cuda_runtime.h>
#include <cuda_fp16.h>
#include <math.h>
#include <float.h>
#include <stdint.h>

// Problem dims
#define BBs   128
#define Ls    343
#define Es    256
#define Hs    8
#define HDs   32
#define HIDs  512
#define LLs   (Ls * Ls)       // 117649
#define ROWSs (BBs * Ls)      // 43904
#define LPAD  344
#define NCLS  2197            // 13^3 distinct index triples

// -------- scratch (device globals; no allocation allowed) --------
__device__ float g_bias[Hs * Ls * LPAD];
__device__ __align__(16) float g_blut[NCLS * 8];
__device__ int   g_mask_mode;
__device__ uint8_t g_mask8[BBs * Ls * LPAD];
// fp16 A-operands (single, rounded) per projection input
__device__ __half g_xq[ROWSs * Es], g_xk[ROWSs * Es], g_xv[ROWSs * Es];
// attention output (single fp16, A of final GEMM)
__device__ __half g_a[ROWSs * Es];
// weights (4x, transposed [n][k], hi/lo fp16 split)
__device__ __half g_w4h[4 * Es * Es], g_w4l[4 * Es * Es];
// attention operands (head-split): Q single; K,V hi/lo
__device__ __half g_qh[BBs * Hs * Ls * HDs];
__device__ __half g_kh[BBs * Hs * Ls * HDs], g_kl[BBs * Hs * Ls * HDs];
__device__ __half g_vh[BBs * Hs * Ls * HDs], g_vl[BBs * Hs * Ls * HDs];

// ============================================================
// PTX helpers (baseline sm_80+ ISA; harness targets sm_103 w/o 'a')
// ============================================================
__device__ __forceinline__ uint32_t smem_u32(const void* p) {
    uint32_t a;
    asm("{ .reg .u64 t; cvta.to.shared.u64 t, %1; cvt.u32.u64 %0, t; }" : "=r"(a) : "l"(p));
    return a;
}
__device__ __forceinline__ void ldsm_x4(uint32_t& r0, uint32_t& r1, uint32_t& r2,
                                        uint32_t& r3, uint32_t addr) {
    asm volatile("ldmatrix.sync.aligned.m8n8.x4.shared.b16 {%0,%1,%2,%3}, [%4];"
                 : "=r"(r0), "=r"(r1), "=r"(r2), "=r"(r3) : "r"(addr));
}
__device__ __forceinline__ void ldsm_x4_t(uint32_t& r0, uint32_t& r1, uint32_t& r2,
                                          uint32_t& r3, uint32_t addr) {
    asm volatile("ldmatrix.sync.aligned.m8n8.x4.trans.shared.b16 {%0,%1,%2,%3}, [%4];"
                 : "=r"(r0), "=r"(r1), "=r"(r2), "=r"(r3) : "r"(addr));
}
__device__ __forceinline__ void mma16816(float* c, const uint32_t* a,
                                         uint32_t b0, uint32_t b1) {
    asm volatile(
        "mma.sync.aligned.m16n8k16.row.col.f32.f16.f16.f32 "
        "{%0,%1,%2,%3}, {%4,%5,%6,%7}, {%8,%9}, {%0,%1,%2,%3};"
        : "+f"(c[0]), "+f"(c[1]), "+f"(c[2]), "+f"(c[3])
        : "r"(a[0]), "r"(a[1]), "r"(a[2]), "r"(a[3]), "r"(b0), "r"(b1));
}
__device__ __forceinline__ void cp_async16(uint32_t dst, const void* src) {
    asm volatile("cp.async.cg.shared.global [%0], [%1], 16;" :: "r"(dst), "l"(src));
}
__device__ __forceinline__ void cp_commit() { asm volatile("cp.async.commit_group;"); }
__device__ __forceinline__ void cp_wait1() { asm volatile("cp.async.wait_group 1;"); }
__device__ __forceinline__ void cp_wait0() { asm volatile("cp.async.wait_group 0;"); }

__device__ __forceinline__ uint32_t packh(float a, float b) {
    __half2 t = __floats2half2_rn(a, b);
    return *(uint32_t*)&t;
}
// fp16 hi + fp16 residual pair
__device__ __forceinline__ void pack2h(float c0, float c1, uint32_t& hi, uint32_t& lo) {
    __half2 t = __floats2half2_rn(c0, c1);
    float h0 = __half2float(__low2half(t));
    float h1 = __half2float(__high2half(t));
    __half2 r = __floats2half2_rn(c0 - h0, c1 - h1);
    hi = *(uint32_t*)&t; lo = *(uint32_t*)&r;
}

// Fast exp on FMA/ALU pipes only (no MUFU). rel err ~2.4e-6.
__device__ __forceinline__ float fexp(float x) {
    float y = fmaxf(x * 1.4426950408889634f, -126.0f);
    float yr = __fadd_rn(y, 12582912.0f);
    float n  = __fsub_rn(yr, 12582912.0f);
    float f  = __fsub_rn(y, n);
    float p  = 1.3333558e-3f;
    p = fmaf(p, f, 9.6181291e-3f);
    p = fmaf(p, f, 5.5504109e-2f);
    p = fmaf(p, f, 2.4022651e-1f);
    p = fmaf(p, f, 6.9314718e-1f);
    p = fmaf(p, f, 1.0f);
    return __int_as_float(__float_as_int(p) + (__float_as_int(yr) << 23));
}

// ============================================================
// Kernel: detect mask dtype
// ============================================================
__global__ void detect_mask_kernel(const unsigned int* __restrict__ m)
{
    __shared__ int s_float, s_multi;
    if (threadIdx.x == 0) { s_float = 0; s_multi = 0; }
    __syncthreads();
    for (int i = threadIdx.x; i < 4096; i += 256) {
        unsigned int w = m[i];
        if (w == 0x3F800000u) atomicOr(&s_float, 1);
        else if (w != 0u && (w & 0xFFFFFF00u) != 0u) atomicOr(&s_multi, 1);
    }
    __syncthreads();
    if (threadIdx.x == 0)
        g_mask_mode = s_float ? 2 : (s_multi ? 0 : 1);
}

// ============================================================
// Kernel: normalize mask to padded uint8 table
// ============================================================
__global__ __launch_bounds__(256) void mask_prep_kernel(const void* __restrict__ maskp)
{
    int idx = blockIdx.x * 256 + threadIdx.x;
    if (idx >= BBs * LLs) return;
    int bb = idx / LLs;
    int p = idx - bb * LLs;
    int i = p / Ls, j = p - i * Ls;
    int mode = g_mask_mode;
    bool m = (mode == 0) ? (((const uint8_t*)maskp)[idx] != 0)
           : (mode == 1) ? (((const int*)maskp)[idx] != 0)
                         : (((const float*)maskp)[idx] != 0.0f);
    g_mask8[(size_t)bb * (Ls * LPAD) + i * LPAD + j] = m ? 1 : 0;
}

// ============================================================
// Kernel: CPB LUT — one warp per distinct index-triple class.
// ============================================================
__global__ __launch_bounds__(256) void bias_lut_kernel(
    const float* __restrict__ W1, const float* __restrict__ b1,
    const float* __restrict__ W2, const float* __restrict__ b2)
{
    int wid = threadIdx.x >> 5, lane = threadIdx.x & 31;
    int cls = blockIdx.x * 8 + wid;
    if (cls >= NCLS) return;
    int d0 = cls % 13 - 6;
    int d1 = (cls / 13) % 13 - 6;
    int d2 = cls / 169 - 6;
    float x0 = copysignf(log2f(1.0f + fabsf((float)d0)) * (1.0f / 3.0f), (float)d0);
    float x1 = copysignf(log2f(1.0f + fabsf((float)d1)) * (1.0f / 3.0f), (float)d1);
    float x2 = copysignf(log2f(1.0f + fabsf((float)d2)) * (1.0f / 3.0f), (float)d2);
    float acc[8];
#pragma unroll
    for (int h = 0; h < 8; h++) acc[h] = 0.0f;
    for (int t = lane; t < HIDs; t += 32) {
        float hv = fmaxf(fmaf(x0, W1[t], fmaf(x1, W1[HIDs + t],
                        fmaf(x2, W1[2 * HIDs + t], b1[t]))), 0.0f);
#pragma unroll
        for (int h = 0; h < 8; h++) acc[h] = fmaf(hv, W2[t * 8 + h], acc[h]);
    }
#pragma unroll
    for (int h = 0; h < 8; h++) {
#pragma unroll
        for (int o = 16; o > 0; o >>= 1)
            acc[h] += __shfl_xor_sync(0xffffffffu, acc[h], o);
    }
    if (lane == 0) {
#pragma unroll
        for (int h = 0; h < 8; h++) {
            float z = acc[h] + b2[h];
            g_blut[cls * 8 + h] = 16.0f / (1.0f + fexp(-z));
        }
    }
}

// ============================================================
// Kernel: gather LUT -> padded bias planes
// ============================================================
__global__ __launch_bounds__(256) void bias_gather_kernel(
    const float* __restrict__ indices)
{
    int p = blockIdx.x * 256 + threadIdx.x;
    if (p >= LLs) return;
    int i = p / Ls, j = p - i * Ls;
    int q0 = __float2int_rn(indices[p * 3 + 0]) + 6;
    int q1 = __float2int_rn(indices[p * 3 + 1]) + 6;
    int q2 = __float2int_rn(indices[p * 3 + 2]) + 6;
    int cls = q0 + 13 * q1 + 169 * q2;
    float4 v0 = *(const float4*)(g_blut + cls * 8);
    float4 v1 = *(const float4*)(g_blut + cls * 8 + 4);
    float vals[8] = { v0.x, v0.y, v0.z, v0.w, v1.x, v1.y, v1.z, v1.w };
#pragma unroll
    for (int h = 0; h < 8; h++)
        g_bias[(size_t)h * (Ls * LPAD) + i * LPAD + j] = vals[h];
}

// ============================================================
// Kernel: round all 3 fp32 inputs -> single fp16 (batched, grid.y=3)
// ============================================================
__global__ __launch_bounds__(256) void split3_kernel(
    const float4* __restrict__ q, const float4* __restrict__ k,
    const float4* __restrict__ v, int n4)
{
    const int z = blockIdx.y;
    const float4* in = (z == 0) ? q : (z == 1) ? k : v;
    __half* dst = (z == 0) ? g_xq : (z == 1) ? g_xk : g_xv;
    int i = blockIdx.x * 256 + threadIdx.x;
    if (i >= n4) return;
    float4 val = in[i];
    uint2 o = make_uint2(packh(val.x, val.y), packh(val.z, val.w));
    *(uint2*)(dst + (size_t)i * 4) = o;
}

// ============================================================
// Kernel: all 4 weight transposes + fp16 hi/lo splits (grid.z=4)
// ============================================================
__global__ __launch_bounds__(256) void wsplit_all_kernel(
    const float* __restrict__ Wq, const float* __restrict__ Wk,
    const float* __restrict__ Wv, const float* __restrict__ Ww)
{
    __shared__ float t[32][33];
    const int z = blockIdx.z;
    const float* W = (z == 0) ? Wq : (z == 1) ? Wk : (z == 2) ? Wv : Ww;
    __half* ht = g_w4h + (size_t)z * Es * Es;
    __half* lt = g_w4l + (size_t)z * Es * Es;
    int bn = blockIdx.x * 32, bk = blockIdx.y * 32;
    int lx = threadIdx.x & 31, ly = threadIdx.x >> 5;
    for (int yy = ly; yy < 32; yy += 8)
        t[yy][lx] = W[(size_t)(bk + yy) * Es + bn + lx];
    __syncthreads();
    for (int yy = ly; yy < 32; yy += 8) {
        float v = t[lx][yy];
        __half h = __float2half_rn(v);
        __half l = __float2half_rn(v - __half2float(h));
        size_t o = (size_t)(bn + yy) * Es + bk + lx;
        ht[o] = h; lt[o] = l;
    }
}

// ============================================================
// Kernel: mma.sync fp16 split-GEMM: C = A*(Wh+Wl), fp32 accum.
// 8 K-chunks (2 terms x 4), 3-stage cp.async pipeline.
// ============================================================
#define TGS 72
#define TGBUF 18432
#define TGSTAGE (2 * TGBUF)
#define TG_SMEM (3 * TGSTAGE)         // 110592 B

__global__ __launch_bounds__(256) void tgemm_kernel(
    const __half* __restrict__ A,
    const __half* __restrict__ Wh, const __half* __restrict__ Wl,
    const float* __restrict__ bias, float* __restrict__ C, int remap,
    __half* __restrict__ Oh, __half* __restrict__ Ol, int donorm)
{
    extern __shared__ char dsm[];
    const int tid = threadIdx.x;
    const int wid = tid >> 5;
    const int lane = tid & 31;
    const int m0 = blockIdx.x * 128;
    const int n0 = blockIdx.y * 128;
    const int wm = wid & 1;
    const int wn = wid >> 1;
    const uint32_t smb = smem_u32(dsm);

    float c[4][4][4];
#pragma unroll
    for (int i = 0; i < 4; i++)
#pragma unroll
        for (int j = 0; j < 4; j++)
#pragma unroll
            for (int k = 0; k < 4; k++) c[i][j][k] = 0.0f;

    auto prefetch = [&](int i) {
        const int t = i >> 2, kc = i & 3, s = i % 3;
        const __half* Bs = t ? Wl : Wh;
        const int k0 = kc * 64;
        const uint32_t bA = smb + s * TGSTAGE;
        const uint32_t bB = bA + TGBUF;
#pragma unroll
        for (int j = 0; j < 4; j++) {
            int x = tid + j * 256;
            int r = x >> 3, cc = x & 7;
            uint32_t off = (uint32_t)(r * TGS + cc * 8) * 2;
            cp_async16(bA + off, A + (size_t)(m0 + r) * Es + k0 + cc * 8);
            cp_async16(bB + off, Bs + (size_t)(n0 + r) * Es + k0 + cc * 8);
        }
    };

    prefetch(0); cp_commit();
    prefetch(1); cp_commit();

    const int arow = (lane & 7) + ((lane >> 3) & 1) * 8;
    const int acolo = ((lane >> 4) & 1) * 8;
    const int brow = (lane & 7) + ((lane >> 4) & 1) * 8;
    const int bcolo = ((lane >> 3) & 1) * 8;

    for (int i = 0; i < 8; i++) {
        if (i < 7) cp_wait1(); else cp_wait0();
        __syncthreads();
        if (i < 6) { prefetch(i + 2); cp_commit(); }

        const uint32_t bA = smb + (i % 3) * TGSTAGE;
        const uint32_t bB = bA + TGBUF;
#pragma unroll
        for (int ks = 0; ks < 4; ks++) {
            const int k0 = ks * 16;
            uint32_t a[4][4], b[2][4];
#pragma unroll
            for (int mt = 0; mt < 4; mt++)
                ldsm_x4(a[mt][0], a[mt][1], a[mt][2], a[mt][3],
                        bA + (uint32_t)((wm * 64 + mt * 16 + arow) * TGS + k0 + acolo) * 2);
#pragma unroll
            for (int g = 0; g < 2; g++)
                ldsm_x4(b[g][0], b[g][1], b[g][2], b[g][3],
                        bB + (uint32_t)((wn * 32 + g * 16 + brow) * TGS + k0 + bcolo) * 2);
#pragma unroll
            for (int mt = 0; mt < 4; mt++)
#pragma unroll
                for (int nt = 0; nt < 4; nt++)
                    mma16816(c[mt][nt], a[mt], b[nt >> 1][(nt & 1) * 2],
                             b[nt >> 1][(nt & 1) * 2 + 1]);
        }
    }

    const int tq = lane >> 2;
    const int tr = lane & 3;
#pragma unroll
    for (int mt = 0; mt < 4; mt++) {
        const int m = m0 + wm * 64 + mt * 16 + tq;
        float v0x[4], v0y[4], v1x[4], v1y[4];
#pragma unroll
        for (int nt = 0; nt < 4; nt++) {
            const int n = n0 + wn * 32 + nt * 8 + tr * 2;
            float bx = 0.0f, by = 0.0f;
            if (bias) { float2 bv = *(const float2*)(bias + n); bx = bv.x; by = bv.y; }
            v0x[nt] = c[mt][nt][0] + bx; v0y[nt] = c[mt][nt][1] + by;
            v1x[nt] = c[mt][nt][2] + bx; v1y[nt] = c[mt][nt][3] + by;
        }
        if (donorm) {
            float ss0 = 0.0f, ss1 = 0.0f;
#pragma unroll
            for (int nt = 0; nt < 4; nt++) {
                ss0 = fmaf(v0x[nt], v0x[nt], fmaf(v0y[nt], v0y[nt], ss0));
                ss1 = fmaf(v1x[nt], v1x[nt], fmaf(v1y[nt], v1y[nt], ss1));
            }
            ss0 += __shfl_xor_sync(0xffffffffu, ss0, 1);
            ss0 += __shfl_xor_sync(0xffffffffu, ss0, 2);
            ss1 += __shfl_xor_sync(0xffffffffu, ss1, 1);
            ss1 += __shfl_xor_sync(0xffffffffu, ss1, 2);
            float i0 = 1.0f / fmaxf(sqrtf(ss0), 1e-12f);
            float i1 = 1.0f / fmaxf(sqrtf(ss1), 1e-12f);
#pragma unroll
            for (int nt = 0; nt < 4; nt++) {
                v0x[nt] *= i0; v0y[nt] *= i0;
                v1x[nt] *= i1; v1y[nt] *= i1;
            }
        }
#pragma unroll
        for (int nt = 0; nt < 4; nt++) {
            const int n = n0 + wn * 32 + nt * 8 + tr * 2;
            size_t a0, a1;
            if (remap) {
                const int hh = n >> 5, hd = n & 31;
                int bbw = m / Ls, l = m - bbw * Ls;
                a0 = ((size_t)(bbw * Hs + hh) * Ls + l) * HDs + hd;
                int m2 = m + 8;
                int bbw2 = m2 / Ls, l2 = m2 - bbw2 * Ls;
                a1 = ((size_t)(bbw2 * Hs + hh) * Ls + l2) * HDs + hd;
            } else {
                a0 = (size_t)m * Es + n;
                a1 = (size_t)(m + 8) * Es + n;
            }
            if (Oh) {
                if (Ol) {
                    uint32_t h0, l0, h1, l1;
                    pack2h(v0x[nt], v0y[nt], h0, l0);
                    pack2h(v1x[nt], v1y[nt], h1, l1);
                    *(uint32_t*)(Oh + a0) = h0;
                    *(uint32_t*)(Oh + a1) = h1;
                    *(uint32_t*)(Ol + a0) = l0;
                    *(uint32_t*)(Ol + a1) = l1;
                } else {
                    *(uint32_t*)(Oh + a0) = packh(v0x[nt], v0y[nt]);
                    *(uint32_t*)(Oh + a1) = packh(v1x[nt], v1y[nt]);
                }
            } else {
                *(float2*)(C + a0) = make_float2(v0x[nt], v0y[nt]);
                *(float2*)(C + a1) = make_float2(v1x[nt], v1y[nt]);
            }
        }
    }
}

// ============================================================
// Kernel: persistent fp16 tensorized attention per (head, window).
// 512 threads / 16 warps. SMEM: Qh, Kh, Kl, Vh, Vl (384x80B each).
// QK = Qh*(Kh+Kl); PV = Ph*(Vh+Vl); softmax scale folded post-PV.
// ============================================================
#define ASTR 40
#define ABUF 30720
#define OFF_QH (0 * ABUF)
#define OFF_KH (1 * ABUF)
#define OFF_KL (2 * ABUF)
#define OFF_VH (3 * ABUF)
#define OFF_VL (4 * ABUF)
#define OFF_RMAX (5 * ABUF)           // 153600
#define OFF_RSUM (OFF_RMAX + 1024)
#define OFF_ORED (OFF_RSUM + 1024)
#define ORSTR 34
#define ATT3_SMEM (OFF_ORED + 4 * 64 * ORSTR * 4)   // 190464

__global__ __launch_bounds__(512) void attn3_kernel(const float* __restrict__ scalep)
{
    extern __shared__ char sm2[];
    float* redmax = (float*)(sm2 + OFF_RMAX);
    float* redsum = (float*)(sm2 + OFF_RSUM);
    float* ored   = (float*)(sm2 + OFF_ORED);
    const uint32_t smb = smem_u32(sm2);

    const int tid = threadIdx.x;
    const int wid = tid >> 5;
    const int lane = tid & 31;
    const int h = blockIdx.x;
    const int bb = blockIdx.y;
    const size_t gbase = (size_t)(bb * Hs + h) * (Ls * HDs);

    // ---- fill Qh,Kh,Kl,Vh,Vl once ----
    {
        const __half* gsrc[5] = { g_qh + gbase, g_kh + gbase, g_kl + gbase,
                                  g_vh + gbase, g_vl + gbase };
#pragma unroll
        for (int arr = 0; arr < 5; arr++)
            for (int i = tid; i < 1372; i += 512) {
                int row = i >> 2, ch = i & 3;
                cp_async16(smb + arr * ABUF + row * 80 + ch * 16,
                           gsrc[arr] + row * HDs + ch * 8);
            }
        for (int i = tid; i < 820; i += 512) {   // pad rows 343..383 x 4 x 16B
            int arr = i / 164, j = i - arr * 164;
            int r = 343 + (j >> 2), ch = j & 3;
            *(uint4*)(sm2 + arr * ABUF + r * 80 + ch * 16) = make_uint4(0, 0, 0, 0);
        }
        cp_commit();
        cp_wait0();
        __syncthreads();
    }

    const int wm = wid & 3;
    const int wn = wid >> 2;
    const int nbase = wn * 96;

    const int arow = (lane & 7) + ((lane >> 3) & 1) * 8;
    const int acolo = ((lane >> 4) & 1) * 8;
    const int brow = (lane & 7) + ((lane >> 4) & 1) * 8;
    const int bcolo = ((lane >> 3) & 1) * 8;

    const float invscale = 1.0f / fmaxf(scalep[0], 0.01f);
    const float* bias0 = g_bias + (size_t)h * (Ls * LPAD);
    const uint8_t* mrow = g_mask8 + (size_t)bb * (Ls * LPAD);
    const int r0 = wm * 16 + (lane >> 2);
    const int r1 = r0 + 8;
    const int ncol = (lane & 3) * 2;
    const int lane16 = lane & 15;
    const int halfr = lane >> 4;

    for (int qt = 0; qt < 6; qt++) {
        const int q0 = qt * 64;

        // ---- Q fragments (single fp16) ----
        uint32_t qh[2][4];
#pragma unroll
        for (int kk = 0; kk < 2; kk++) {
            uint32_t ro = (uint32_t)((q0 + wm * 16 + arow) * ASTR + kk * 16 + acolo) * 2;
            ldsm_x4(qh[kk][0], qh[kk][1], qh[kk][2], qh[kk][3], smb + OFF_QH + ro);
        }

        // ---- phase 1: S = Qh*(Kh+Kl) ----
        float c[12][4];
#pragma unroll
        for (int t = 0; t < 12; t++)
#pragma unroll
            for (int e = 0; e < 4; e++) c[t][e] = 0.0f;

#pragma unroll
        for (int g = 0; g < 6; g++) {
            uint32_t bh[2][4], bl[2][4];
#pragma unroll
            for (int kk = 0; kk < 2; kk++) {
                uint32_t rb = (uint32_t)((nbase + g * 16 + brow) * ASTR + kk * 16 + bcolo) * 2;
                ldsm_x4(bh[kk][0], bh[kk][1], bh[kk][2], bh[kk][3], smb + OFF_KH + rb);
                ldsm_x4(bl[kk][0], bl[kk][1], bl[kk][2], bl[kk][3], smb + OFF_KL + rb);
            }
#pragma unroll
            for (int kk = 0; kk < 2; kk++)
#pragma unroll
                for (int nt = 0; nt < 2; nt++) {
                    float* cc = c[g * 2 + nt];
                    mma16816(cc, qh[kk], bh[kk][nt * 2], bh[kk][nt * 2 + 1]);
                    mma16816(cc, qh[kk], bl[kk][nt * 2], bl[kk][nt * 2 + 1]);
                }
        }

        // ---- scale + bias + mask ----
        const int qrow0 = q0 + r0, qrow1 = q0 + r1;
        const bool rv0 = qrow0 < Ls, rv1 = qrow1 < Ls;
#pragma unroll
        for (int t = 0; t < 12; t++) {
            int col = nbase + t * 8 + ncol;
            bool cv0 = col < Ls, cv1 = (col + 1) < Ls;
            float2 b0v = make_float2(0.f, 0.f), b1v = make_float2(0.f, 0.f);
            uchar2 m0v = make_uchar2(0, 0), m1v = make_uchar2(0, 0);
            if (rv0 && cv0) {
                b0v = *(const float2*)(bias0 + (size_t)qrow0 * LPAD + col);
                m0v = *(const uchar2*)(mrow + (size_t)qrow0 * LPAD + col);
            }
            if (rv1 && cv0) {
                b1v = *(const float2*)(bias0 + (size_t)qrow1 * LPAD + col);
                m1v = *(const uchar2*)(mrow + (size_t)qrow1 * LPAD + col);
            }
            c[t][0] = (rv0 && cv0) ? (m0v.x ? -100000.0f : fmaf(c[t][0], invscale, b0v.x)) : -1e9f;
            c[t][1] = (rv0 && cv1) ? (m0v.y ? -100000.0f : fmaf(c[t][1], invscale, b0v.y)) : -1e9f;
            c[t][2] = (rv1 && cv0) ? (m1v.x ? -100000.0f : fmaf(c[t][2], invscale, b1v.x)) : -1e9f;
            c[t][3] = (rv1 && cv1) ? (m1v.y ? -100000.0f : fmaf(c[t][3], invscale, b1v.y)) : -1e9f;
        }

        // ---- single-sync softmax; normalization deferred to post-PV ----
        float mx0 = -FLT_MAX, mx1 = -FLT_MAX;
#pragma unroll
        for (int t = 0; t < 12; t++) {
            mx0 = fmaxf(mx0, fmaxf(c[t][0], c[t][1]));
            mx1 = fmaxf(mx1, fmaxf(c[t][2], c[t][3]));
        }
        mx0 = fmaxf(mx0, __shfl_xor_sync(0xffffffffu, mx0, 1));
        mx0 = fmaxf(mx0, __shfl_xor_sync(0xffffffffu, mx0, 2));
        mx1 = fmaxf(mx1, __shfl_xor_sync(0xffffffffu, mx1, 1));
        mx1 = fmaxf(mx1, __shfl_xor_sync(0xffffffffu, mx1, 2));

        float s0 = 0.0f, s1 = 0.0f;
#pragma unroll
        for (int t = 0; t < 12; t++) {
            float e0 = fexp(c[t][0] - mx0); c[t][0] = e0; s0 += e0;
            float e1 = fexp(c[t][1] - mx0); c[t][1] = e1; s0 += e1;
            float e2 = fexp(c[t][2] - mx1); c[t][2] = e2; s1 += e2;
            float e3 = fexp(c[t][3] - mx1); c[t][3] = e3; s1 += e3;
        }
        s0 += __shfl_xor_sync(0xffffffffu, s0, 1);
        s0 += __shfl_xor_sync(0xffffffffu, s0, 2);
        s1 += __shfl_xor_sync(0xffffffffu, s1, 1);
        s1 += __shfl_xor_sync(0xffffffffu, s1, 2);
        if ((lane & 3) == 0) {
            redmax[wn * 64 + r0] = mx0; redsum[wn * 64 + r0] = s0;
            redmax[wn * 64 + r1] = mx1; redsum[wn * 64 + r1] = s1;
        }
        __syncthreads();
        float f0, f1;
        {
            float gm0 = -FLT_MAX, gm1 = -FLT_MAX;
#pragma unroll
            for (int qd = 0; qd < 4; qd++) {
                gm0 = fmaxf(gm0, redmax[qd * 64 + r0]);
                gm1 = fmaxf(gm1, redmax[qd * 64 + r1]);
            }
            float S0 = 0.0f, S1 = 0.0f;
#pragma unroll
            for (int qd = 0; qd < 4; qd++) {
                S0 += redsum[qd * 64 + r0] * fexp(redmax[qd * 64 + r0] - gm0);
                S1 += redsum[qd * 64 + r1] * fexp(redmax[qd * 64 + r1] - gm1);
            }
            f0 = fexp(mx0 - gm0) / S0;
            f1 = fexp(mx1 - gm1) / S1;
        }

        // ---- phase 3: O = (Ph) * (Vh + Vl), then scale by f ----
        float oc[4][4];
#pragma unroll
        for (int nt = 0; nt < 4; nt++)
#pragma unroll
            for (int e = 0; e < 4; e++) oc[nt][e] = 0.0f;

#pragma unroll
        for (int kt = 0; kt < 6; kt++) {
            uint32_t ph[4];
#pragma unroll
            for (int half = 0; half < 2; half++) {
                const float* cc = c[2 * kt + half];
                ph[half * 2 + 0] = packh(cc[0], cc[1]);
                ph[half * 2 + 1] = packh(cc[2], cc[3]);
            }
            const int krow = nbase + kt * 16;
            uint32_t vh[2][4], vl[2][4];
#pragma unroll
            for (int g = 0; g < 2; g++) {
                uint32_t ad = (uint32_t)((krow + arow) * ASTR + g * 16 + acolo) * 2;
                ldsm_x4_t(vh[g][0], vh[g][1], vh[g][2], vh[g][3], smb + OFF_VH + ad);
                ldsm_x4_t(vl[g][0], vl[g][1], vl[g][2], vl[g][3], smb + OFF_VL + ad);
            }
#pragma unroll
            for (int nt = 0; nt < 4; nt++) {
                const int g = nt >> 1, i2 = (nt & 1) * 2;
                mma16816(oc[nt], ph, vh[g][i2], vh[g][i2 + 1]);
                mma16816(oc[nt], ph, vl[g][i2], vl[g][i2 + 1]);
            }
        }
#pragma unroll
        for (int nt = 0; nt < 4; nt++) {
            oc[nt][0] *= f0; oc[nt][1] *= f0;
            oc[nt][2] *= f1; oc[nt][3] *= f1;
        }

        // ---- all quarters write slabs; distributed reduce + fp16 store ----
        {
            float* dst = ored + (size_t)wn * (64 * ORSTR);
#pragma unroll
            for (int nt = 0; nt < 4; nt++) {
                *(float2*)(dst + r0 * ORSTR + nt * 8 + ncol) = make_float2(oc[nt][0], oc[nt][1]);
                *(float2*)(dst + r1 * ORSTR + nt * 8 + ncol) = make_float2(oc[nt][2], oc[nt][3]);
            }
        }
        __syncthreads();
#pragma unroll
        for (int p = 0; p < 2; p++) {
            int row = wid * 4 + p * 2 + halfr;
            int qrow = q0 + row;
            if (qrow < Ls) {
                int col = lane16 * 2;
                float s0o = 0.0f, s1o = 0.0f;
#pragma unroll
                for (int qd = 0; qd < 4; qd++) {
                    float2 v = *(float2*)(ored + qd * (64 * ORSTR) + row * ORSTR + col);
                    s0o += v.x; s1o += v.y;
                }
                size_t ad = (size_t)(bb * Ls + qrow) * Es + h * HDs + col;
                *(uint32_t*)(g_a + ad) = packh(s0o, s1o);
            }
        }
    }
}

// ============================================================
// launch
// ============================================================
extern "C" void kernel_launch(void* const* d_in, const int* in_sizes, int n_in,
                              void* d_out, int out_size)
{
    (void)in_sizes; (void)n_in; (void)out_size;
    const float* query   = (const float*)d_in[0];
    const float* key     = (const float*)d_in[1];
    const float* value   = (const float*)d_in[2];
    const float* indices = (const float*)d_in[3];
    const void*  mask    = d_in[4];
    const float* Wq      = (const float*)d_in[5];
    const float* bq      = (const float*)d_in[6];
    const float* Wk      = (const float*)d_in[7];
    const float* bk      = (const float*)d_in[8];
    const float* Wv      = (const float*)d_in[9];
    const float* Ww      = (const float*)d_in[10];
    const float* bw      = (const float*)d_in[11];
    const float* scale   = (const float*)d_in[12];
    const float* W1      = (const float*)d_in[13];
    const float* b1      = (const float*)d_in[14];
    const float* W2      = (const float*)d_in[15];
    const float* b2      = (const float*)d_in[16];
    float* out = (float*)d_out;

    __half *pxq, *pxk, *pxv, *pa, *pwh, *pwl;
    __half *pqh, *pkh, *pkl, *pvh, *pvl;
    cudaGetSymbolAddress((void**)&pxq, g_xq);
    cudaGetSymbolAddress((void**)&pxk, g_xk);
    cudaGetSymbolAddress((void**)&pxv, g_xv);
    cudaGetSymbolAddress((void**)&pa,  g_a);
    cudaGetSymbolAddress((void**)&pwh, g_w4h);
    cudaGetSymbolAddress((void**)&pwl, g_w4l);
    cudaGetSymbolAddress((void**)&pqh, g_qh);
    cudaGetSymbolAddress((void**)&pkh, g_kh);
    cudaGetSymbolAddress((void**)&pkl, g_kl);
    cudaGetSymbolAddress((void**)&pvh, g_vh);
    cudaGetSymbolAddress((void**)&pvl, g_vl);

    cudaFuncSetAttribute(tgemm_kernel, cudaFuncAttributeMaxDynamicSharedMemorySize,
                         TG_SMEM);
    cudaFuncSetAttribute(attn3_kernel, cudaFuncAttributeMaxDynamicSharedMemorySize,
                         ATT3_SMEM);

    const int n4 = ROWSs * Es / 4;
    const int splitg = (n4 + 255) / 256;
    const dim3 gg(ROWSs / 128, Es / 128);
    const size_t WSZ = (size_t)Es * Es;

    wsplit_all_kernel<<<dim3(8, 8, 4), 256>>>(Wq, Wk, Wv, Ww);
    split3_kernel<<<dim3(splitg, 3), 256>>>((const float4*)query, (const float4*)key,
                                            (const float4*)value, n4);
    detect_mask_kernel<<<1, 256>>>((const unsigned int*)mask);
    // Q projection + fused norm -> single fp16  (ncu-captured slot)
    tgemm_kernel<<<gg, 256, TG_SMEM>>>(pxq, pwh + 0 * WSZ, pwl + 0 * WSZ,
                                       bq, nullptr, 1, pqh, nullptr, 1);
    // K projection + fused norm -> fp16 hi/lo
    tgemm_kernel<<<gg, 256, TG_SMEM>>>(pxk, pwh + 1 * WSZ, pwl + 1 * WSZ,
                                       bk, nullptr, 1, pkh, pkl, 1);
    // V projection -> fp16 hi/lo
    tgemm_kernel<<<gg, 256, TG_SMEM>>>(pxv, pwh + 2 * WSZ, pwl + 2 * WSZ,
                                       nullptr, nullptr, 1, pvh, pvl, 0);
    mask_prep_kernel<<<(BBs * LLs + 255) / 256, 256>>>(mask);
    bias_lut_kernel<<<(NCLS + 7) / 8, 256>>>(W1, b1, W2, b2);
    bias_gather_kernel<<<(LLs + 255) / 256, 256>>>(indices);
    attn3_kernel<<<dim3(Hs, BBs), 512, ATT3_SMEM>>>(scale);
    // output projection -> d_out (fp32)
    tgemm_kernel<<<gg, 256, TG_SMEM>>>(pa, pwh + 3 * WSZ, pwl + 3 * WSZ,
                                       bw, out, 0, nullptr, nullptr, 0);
}

// round 12
// speedup vs baseline: 4.4963x; 1.0332x over previous
#include <cuda_runtime.h>
#include <cuda_fp16.h>
#include <math.h>
#include <float.h>
#include <stdint.h>

// Problem dims
#define BBs   128
#define Ls    343
#define Es    256
#define Hs    8
#define HDs   32
#define HIDs  512
#define LLs   (Ls * Ls)       // 117649
#define ROWSs (BBs * Ls)      // 43904
#define LPAD  344
#define NCLS  2197            // 13^3 distinct index triples

// -------- scratch (device globals; no allocation allowed) --------
__device__ float g_bias[Hs * Ls * LPAD];
__device__ __align__(16) float g_blut[NCLS * 8];
__device__ int   g_mask_mode;
__device__ uint8_t g_mask8[BBs * Ls * LPAD];
__device__ __half g_xq[ROWSs * Es], g_xk[ROWSs * Es], g_xv[ROWSs * Es];
__device__ __half g_a[ROWSs * Es];
__device__ __half g_w4h[4 * Es * Es], g_w4l[4 * Es * Es];
__device__ __half g_qh[BBs * Hs * Ls * HDs];
__device__ __half g_kh[BBs * Hs * Ls * HDs], g_kl[BBs * Hs * Ls * HDs];
__device__ __half g_vh[BBs * Hs * Ls * HDs], g_vl[BBs * Hs * Ls * HDs];

// ============================================================
// PTX helpers (baseline sm_80+ ISA; harness targets sm_103 w/o 'a')
// ============================================================
__device__ __forceinline__ uint32_t smem_u32(const void* p) {
    uint32_t a;
    asm("{ .reg .u64 t; cvta.to.shared.u64 t, %1; cvt.u32.u64 %0, t; }" : "=r"(a) : "l"(p));
    return a;
}
__device__ __forceinline__ void ldsm_x4(uint32_t& r0, uint32_t& r1, uint32_t& r2,
                                        uint32_t& r3, uint32_t addr) {
    asm volatile("ldmatrix.sync.aligned.m8n8.x4.shared.b16 {%0,%1,%2,%3}, [%4];"
                 : "=r"(r0), "=r"(r1), "=r"(r2), "=r"(r3) : "r"(addr));
}
__device__ __forceinline__ void ldsm_x4_t(uint32_t& r0, uint32_t& r1, uint32_t& r2,
                                          uint32_t& r3, uint32_t addr) {
    asm volatile("ldmatrix.sync.aligned.m8n8.x4.trans.shared.b16 {%0,%1,%2,%3}, [%4];"
                 : "=r"(r0), "=r"(r1), "=r"(r2), "=r"(r3) : "r"(addr));
}
__device__ __forceinline__ void mma16816(float* c, const uint32_t* a,
                                         uint32_t b0, uint32_t b1) {
    asm volatile(
        "mma.sync.aligned.m16n8k16.row.col.f32.f16.f16.f32 "
        "{%0,%1,%2,%3}, {%4,%5,%6,%7}, {%8,%9}, {%0,%1,%2,%3};"
        : "+f"(c[0]), "+f"(c[1]), "+f"(c[2]), "+f"(c[3])
        : "r"(a[0]), "r"(a[1]), "r"(a[2]), "r"(a[3]), "r"(b0), "r"(b1));
}
__device__ __forceinline__ void cp_async16(uint32_t dst, const void* src) {
    asm volatile("cp.async.cg.shared.global [%0], [%1], 16;" :: "r"(dst), "l"(src));
}
__device__ __forceinline__ void cp_commit() { asm volatile("cp.async.commit_group;"); }
__device__ __forceinline__ void cp_wait1() { asm volatile("cp.async.wait_group 1;"); }
__device__ __forceinline__ void cp_wait0() { asm volatile("cp.async.wait_group 0;"); }

__device__ __forceinline__ uint32_t packh(float a, float b) {
    __half2 t = __floats2half2_rn(a, b);
    return *(uint32_t*)&t;
}
__device__ __forceinline__ void pack2h(float c0, float c1, uint32_t& hi, uint32_t& lo) {
    __half2 t = __floats2half2_rn(c0, c1);
    float h0 = __half2float(__low2half(t));
    float h1 = __half2float(__high2half(t));
    __half2 r = __floats2half2_rn(c0 - h0, c1 - h1);
    hi = *(uint32_t*)&t; lo = *(uint32_t*)&r;
}

// Fast exp on FMA/ALU pipes only (no MUFU). rel err ~2.4e-6.
__device__ __forceinline__ float fexp(float x) {
    float y = fmaxf(x * 1.4426950408889634f, -126.0f);
    float yr = __fadd_rn(y, 12582912.0f);
    float n  = __fsub_rn(yr, 12582912.0f);
    float f  = __fsub_rn(y, n);
    float p  = 1.3333558e-3f;
    p = fmaf(p, f, 9.6181291e-3f);
    p = fmaf(p, f, 5.5504109e-2f);
    p = fmaf(p, f, 2.4022651e-1f);
    p = fmaf(p, f, 6.9314718e-1f);
    p = fmaf(p, f, 1.0f);
    return __int_as_float(__float_as_int(p) + (__float_as_int(yr) << 23));
}

// ============================================================
// Kernel: detect mask dtype
// ============================================================
__global__ void detect_mask_kernel(const unsigned int* __restrict__ m)
{
    __shared__ int s_float, s_multi;
    if (threadIdx.x == 0) { s_float = 0; s_multi = 0; }
    __syncthreads();
    for (int i = threadIdx.x; i < 4096; i += 256) {
        unsigned int w = m[i];
        if (w == 0x3F800000u) atomicOr(&s_float, 1);
        else if (w != 0u && (w & 0xFFFFFF00u) != 0u) atomicOr(&s_multi, 1);
    }
    __syncthreads();
    if (threadIdx.x == 0)
        g_mask_mode = s_float ? 2 : (s_multi ? 0 : 1);
}

// ============================================================
// Kernel: normalize mask to padded uint8 table
// ============================================================
__global__ __launch_bounds__(256) void mask_prep_kernel(const void* __restrict__ maskp)
{
    int idx = blockIdx.x * 256 + threadIdx.x;
    if (idx >= BBs * LLs) return;
    int bb = idx / LLs;
    int p = idx - bb * LLs;
    int i = p / Ls, j = p - i * Ls;
    int mode = g_mask_mode;
    bool m = (mode == 0) ? (((const uint8_t*)maskp)[idx] != 0)
           : (mode == 1) ? (((const int*)maskp)[idx] != 0)
                         : (((const float*)maskp)[idx] != 0.0f);
    g_mask8[(size_t)bb * (Ls * LPAD) + i * LPAD + j] = m ? 1 : 0;
}

// ============================================================
// Kernel: CPB LUT — one warp per distinct index-triple class.
// ============================================================
__global__ __launch_bounds__(256) void bias_lut_kernel(
    const float* __restrict__ W1, const float* __restrict__ b1,
    const float* __restrict__ W2, const float* __restrict__ b2)
{
    int wid = threadIdx.x >> 5, lane = threadIdx.x & 31;
    int cls = blockIdx.x * 8 + wid;
    if (cls >= NCLS) return;
    int d0 = cls % 13 - 6;
    int d1 = (cls / 13) % 13 - 6;
    int d2 = cls / 169 - 6;
    float x0 = copysignf(log2f(1.0f + fabsf((float)d0)) * (1.0f / 3.0f), (float)d0);
    float x1 = copysignf(log2f(1.0f + fabsf((float)d1)) * (1.0f / 3.0f), (float)d1);
    float x2 = copysignf(log2f(1.0f + fabsf((float)d2)) * (1.0f / 3.0f), (float)d2);
    float acc[8];
#pragma unroll
    for (int h = 0; h < 8; h++) acc[h] = 0.0f;
    for (int t = lane; t < HIDs; t += 32) {
        float hv = fmaxf(fmaf(x0, W1[t], fmaf(x1, W1[HIDs + t],
                        fmaf(x2, W1[2 * HIDs + t], b1[t]))), 0.0f);
#pragma unroll
        for (int h = 0; h < 8; h++) acc[h] = fmaf(hv, W2[t * 8 + h], acc[h]);
    }
#pragma unroll
    for (int h = 0; h < 8; h++) {
#pragma unroll
        for (int o = 16; o > 0; o >>= 1)
            acc[h] += __shfl_xor_sync(0xffffffffu, acc[h], o);
    }
    if (lane == 0) {
#pragma unroll
        for (int h = 0; h < 8; h++) {
            float z = acc[h] + b2[h];
            g_blut[cls * 8 + h] = 16.0f / (1.0f + fexp(-z));
        }
    }
}

// ============================================================
// Kernel: gather LUT -> padded bias planes
// ============================================================
__global__ __launch_bounds__(256) void bias_gather_kernel(
    const float* __restrict__ indices)
{
    int p = blockIdx.x * 256 + threadIdx.x;
    if (p >= LLs) return;
    int i = p / Ls, j = p - i * Ls;
    int q0 = __float2int_rn(indices[p * 3 + 0]) + 6;
    int q1 = __float2int_rn(indices[p * 3 + 1]) + 6;
    int q2 = __float2int_rn(indices[p * 3 + 2]) + 6;
    int cls = q0 + 13 * q1 + 169 * q2;
    float4 v0 = *(const float4*)(g_blut + cls * 8);
    float4 v1 = *(const float4*)(g_blut + cls * 8 + 4);
    float vals[8] = { v0.x, v0.y, v0.z, v0.w, v1.x, v1.y, v1.z, v1.w };
#pragma unroll
    for (int h = 0; h < 8; h++)
        g_bias[(size_t)h * (Ls * LPAD) + i * LPAD + j] = vals[h];
}

// ============================================================
// Kernel: round all 3 fp32 inputs -> single fp16 (batched, grid.y=3)
// ============================================================
__global__ __launch_bounds__(256) void split3_kernel(
    const float4* __restrict__ q, const float4* __restrict__ k,
    const float4* __restrict__ v, int n4)
{
    const int z = blockIdx.y;
    const float4* in = (z == 0) ? q : (z == 1) ? k : v;
    __half* dst = (z == 0) ? g_xq : (z == 1) ? g_xk : g_xv;
    int i = blockIdx.x * 256 + threadIdx.x;
    if (i >= n4) return;
    float4 val = in[i];
    uint2 o = make_uint2(packh(val.x, val.y), packh(val.z, val.w));
    *(uint2*)(dst + (size_t)i * 4) = o;
}

// ============================================================
// Kernel: all 4 weight transposes + fp16 hi/lo splits (grid.z=4)
// ============================================================
__global__ __launch_bounds__(256) void wsplit_all_kernel(
    const float* __restrict__ Wq, const float* __restrict__ Wk,
    const float* __restrict__ Wv, const float* __restrict__ Ww)
{
    __shared__ float t[32][33];
    const int z = blockIdx.z;
    const float* W = (z == 0) ? Wq : (z == 1) ? Wk : (z == 2) ? Wv : Ww;
    __half* ht = g_w4h + (size_t)z * Es * Es;
    __half* lt = g_w4l + (size_t)z * Es * Es;
    int bn = blockIdx.x * 32, bk = blockIdx.y * 32;
    int lx = threadIdx.x & 31, ly = threadIdx.x >> 5;
    for (int yy = ly; yy < 32; yy += 8)
        t[yy][lx] = W[(size_t)(bk + yy) * Es + bn + lx];
    __syncthreads();
    for (int yy = ly; yy < 32; yy += 8) {
        float v = t[lx][yy];
        __half h = __float2half_rn(v);
        __half l = __float2half_rn(v - __half2float(h));
        size_t o = (size_t)(bn + yy) * Es + bk + lx;
        ht[o] = h; lt[o] = l;
    }
}

// ============================================================
// Shared fp16 split-GEMM body: C = A*(Wh+Wl), fp32 accum.
// 8 K-chunks, 3-stage cp.async pipeline, one sync per chunk.
// ============================================================
#define TGS 72
#define TGBUF 18432
#define TGSTAGE (2 * TGBUF)
#define TG_SMEM (3 * TGSTAGE)         // 110592 B

__device__ __forceinline__ void tgemm_body(
    char* dsm,
    const __half* __restrict__ A,
    const __half* __restrict__ Wh, const __half* __restrict__ Wl,
    const float* __restrict__ bias, float* __restrict__ C, int remap,
    __half* __restrict__ Oh, __half* __restrict__ Ol, int donorm)
{
    const int tid = threadIdx.x;
    const int wid = tid >> 5;
    const int lane = tid & 31;
    const int m0 = blockIdx.x * 128;
    const int n0 = blockIdx.y * 128;
    const int wm = wid & 1;
    const int wn = wid >> 1;
    const uint32_t smb = smem_u32(dsm);

    float c[4][4][4];
#pragma unroll
    for (int i = 0; i < 4; i++)
#pragma unroll
        for (int j = 0; j < 4; j++)
#pragma unroll
            for (int k = 0; k < 4; k++) c[i][j][k] = 0.0f;

    auto prefetch = [&](int i) {
        const int t = i >> 2, kc = i & 3, s = i % 3;
        const __half* Bs = t ? Wl : Wh;
        const int k0 = kc * 64;
        const uint32_t bA = smb + s * TGSTAGE;
        const uint32_t bB = bA + TGBUF;
#pragma unroll
        for (int j = 0; j < 4; j++) {
            int x = tid + j * 256;
            int r = x >> 3, cc = x & 7;
            uint32_t off = (uint32_t)(r * TGS + cc * 8) * 2;
            cp_async16(bA + off, A + (size_t)(m0 + r) * Es + k0 + cc * 8);
            cp_async16(bB + off, Bs + (size_t)(n0 + r) * Es + k0 + cc * 8);
        }
    };

    prefetch(0); cp_commit();
    prefetch(1); cp_commit();

    const int arow = (lane & 7) + ((lane >> 3) & 1) * 8;
    const int acolo = ((lane >> 4) & 1) * 8;
    const int brow = (lane & 7) + ((lane >> 4) & 1) * 8;
    const int bcolo = ((lane >> 3) & 1) * 8;

    for (int i = 0; i < 8; i++) {
        if (i < 7) cp_wait1(); else cp_wait0();
        __syncthreads();
        if (i < 6) { prefetch(i + 2); cp_commit(); }

        const uint32_t bA = smb + (i % 3) * TGSTAGE;
        const uint32_t bB = bA + TGBUF;
#pragma unroll
        for (int ks = 0; ks < 4; ks++) {
            const int k0 = ks * 16;
            uint32_t a[4][4], b[2][4];
#pragma unroll
            for (int mt = 0; mt < 4; mt++)
                ldsm_x4(a[mt][0], a[mt][1], a[mt][2], a[mt][3],
                        bA + (uint32_t)((wm * 64 + mt * 16 + arow) * TGS + k0 + acolo) * 2);
#pragma unroll
            for (int g = 0; g < 2; g++)
                ldsm_x4(b[g][0], b[g][1], b[g][2], b[g][3],
                        bB + (uint32_t)((wn * 32 + g * 16 + brow) * TGS + k0 + bcolo) * 2);
#pragma unroll
            for (int mt = 0; mt < 4; mt++)
#pragma unroll
                for (int nt = 0; nt < 4; nt++)
                    mma16816(c[mt][nt], a[mt], b[nt >> 1][(nt & 1) * 2],
                             b[nt >> 1][(nt & 1) * 2 + 1]);
        }
    }

    const int tq = lane >> 2;
    const int tr = lane & 3;
#pragma unroll
    for (int mt = 0; mt < 4; mt++) {
        const int m = m0 + wm * 64 + mt * 16 + tq;
        float v0x[4], v0y[4], v1x[4], v1y[4];
#pragma unroll
        for (int nt = 0; nt < 4; nt++) {
            const int n = n0 + wn * 32 + nt * 8 + tr * 2;
            float bx = 0.0f, by = 0.0f;
            if (bias) { float2 bv = *(const float2*)(bias + n); bx = bv.x; by = bv.y; }
            v0x[nt] = c[mt][nt][0] + bx; v0y[nt] = c[mt][nt][1] + by;
            v1x[nt] = c[mt][nt][2] + bx; v1y[nt] = c[mt][nt][3] + by;
        }
        if (donorm) {
            float ss0 = 0.0f, ss1 = 0.0f;
#pragma unroll
            for (int nt = 0; nt < 4; nt++) {
                ss0 = fmaf(v0x[nt], v0x[nt], fmaf(v0y[nt], v0y[nt], ss0));
                ss1 = fmaf(v1x[nt], v1x[nt], fmaf(v1y[nt], v1y[nt], ss1));
            }
            ss0 += __shfl_xor_sync(0xffffffffu, ss0, 1);
            ss0 += __shfl_xor_sync(0xffffffffu, ss0, 2);
            ss1 += __shfl_xor_sync(0xffffffffu, ss1, 1);
            ss1 += __shfl_xor_sync(0xffffffffu, ss1, 2);
            float i0 = 1.0f / fmaxf(sqrtf(ss0), 1e-12f);
            float i1 = 1.0f / fmaxf(sqrtf(ss1), 1e-12f);
#pragma unroll
            for (int nt = 0; nt < 4; nt++) {
                v0x[nt] *= i0; v0y[nt] *= i0;
                v1x[nt] *= i1; v1y[nt] *= i1;
            }
        }
#pragma unroll
        for (int nt = 0; nt < 4; nt++) {
            const int n = n0 + wn * 32 + nt * 8 + tr * 2;
            size_t a0, a1;
            if (remap) {
                const int hh = n >> 5, hd = n & 31;
                int bbw = m / Ls, l = m - bbw * Ls;
                a0 = ((size_t)(bbw * Hs + hh) * Ls + l) * HDs + hd;
                int m2 = m + 8;
                int bbw2 = m2 / Ls, l2 = m2 - bbw2 * Ls;
                a1 = ((size_t)(bbw2 * Hs + hh) * Ls + l2) * HDs + hd;
            } else {
                a0 = (size_t)m * Es + n;
                a1 = (size_t)(m + 8) * Es + n;
            }
            if (Oh) {
                if (Ol) {
                    uint32_t h0, l0, h1, l1;
                    pack2h(v0x[nt], v0y[nt], h0, l0);
                    pack2h(v1x[nt], v1y[nt], h1, l1);
                    *(uint32_t*)(Oh + a0) = h0;
                    *(uint32_t*)(Oh + a1) = h1;
                    *(uint32_t*)(Ol + a0) = l0;
                    *(uint32_t*)(Ol + a1) = l1;
                } else {
                    *(uint32_t*)(Oh + a0) = packh(v0x[nt], v0y[nt]);
                    *(uint32_t*)(Oh + a1) = packh(v1x[nt], v1y[nt]);
                }
            } else {
                *(float2*)(C + a0) = make_float2(v0x[nt], v0y[nt]);
                *(float2*)(C + a1) = make_float2(v1x[nt], v1y[nt]);
            }
        }
    }
}

// Q/K/V projections in ONE launch (grid.z selects operand set)
__global__ __launch_bounds__(256) void qkv_gemm_kernel(
    const float* __restrict__ bq, const float* __restrict__ bk)
{
    extern __shared__ char dsm[];
    const int z = blockIdx.z;
    const __half* A  = (z == 0) ? g_xq : (z == 1) ? g_xk : g_xv;
    const __half* Wh = g_w4h + (size_t)z * Es * Es;
    const __half* Wl = g_w4l + (size_t)z * Es * Es;
    const float* bias = (z == 0) ? bq : (z == 1) ? bk : nullptr;
    __half* Oh = (z == 0) ? g_qh : (z == 1) ? g_kh : g_vh;
    __half* Ol = (z == 0) ? nullptr : (z == 1) ? g_kl : g_vl;
    tgemm_body(dsm, A, Wh, Wl, bias, nullptr, 1, Oh, Ol, z < 2);
}

// output projection -> fp32 d_out
__global__ __launch_bounds__(256) void out_gemm_kernel(
    const float* __restrict__ bw, float* __restrict__ out)
{
    extern __shared__ char dsm[];
    tgemm_body(dsm, g_a, g_w4h + 3 * (size_t)Es * Es, g_w4l + 3 * (size_t)Es * Es,
               bw, out, 0, nullptr, nullptr, 0);
}

// ============================================================
// Kernel: persistent fp16 tensorized attention per (head, window).
// Bias/mask LDGs fused into the QK mma loop (latency overlap).
// ============================================================
#define ASTR 40
#define ABUF 30720
#define OFF_QH (0 * ABUF)
#define OFF_KH (1 * ABUF)
#define OFF_KL (2 * ABUF)
#define OFF_VH (3 * ABUF)
#define OFF_VL (4 * ABUF)
#define OFF_RMAX (5 * ABUF)
#define OFF_RSUM (OFF_RMAX + 1024)
#define OFF_ORED (OFF_RSUM + 1024)
#define ORSTR 34
#define ATT3_SMEM (OFF_ORED + 4 * 64 * ORSTR * 4)   // 190464

__global__ __launch_bounds__(512) void attn3_kernel(const float* __restrict__ scalep)
{
    extern __shared__ char sm2[];
    float* redmax = (float*)(sm2 + OFF_RMAX);
    float* redsum = (float*)(sm2 + OFF_RSUM);
    float* ored   = (float*)(sm2 + OFF_ORED);
    const uint32_t smb = smem_u32(sm2);

    const int tid = threadIdx.x;
    const int wid = tid >> 5;
    const int lane = tid & 31;
    const int h = blockIdx.x;
    const int bb = blockIdx.y;
    const size_t gbase = (size_t)(bb * Hs + h) * (Ls * HDs);

    // ---- fill Qh,Kh,Kl,Vh,Vl once ----
    {
        const __half* gsrc[5] = { g_qh + gbase, g_kh + gbase, g_kl + gbase,
                                  g_vh + gbase, g_vl + gbase };
#pragma unroll
        for (int arr = 0; arr < 5; arr++)
            for (int i = tid; i < 1372; i += 512) {
                int row = i >> 2, ch = i & 3;
                cp_async16(smb + arr * ABUF + row * 80 + ch * 16,
                           gsrc[arr] + row * HDs + ch * 8);
            }
        for (int i = tid; i < 820; i += 512) {
            int arr = i / 164, j = i - arr * 164;
            int r = 343 + (j >> 2), ch = j & 3;
            *(uint4*)(sm2 + arr * ABUF + r * 80 + ch * 16) = make_uint4(0, 0, 0, 0);
        }
        cp_commit();
        cp_wait0();
        __syncthreads();
    }

    const int wm = wid & 3;
    const int wn = wid >> 2;
    const int nbase = wn * 96;

    const int arow = (lane & 7) + ((lane >> 3) & 1) * 8;
    const int acolo = ((lane >> 4) & 1) * 8;
    const int brow = (lane & 7) + ((lane >> 4) & 1) * 8;
    const int bcolo = ((lane >> 3) & 1) * 8;

    const float invscale = 1.0f / fmaxf(scalep[0], 0.01f);
    const float* bias0 = g_bias + (size_t)h * (Ls * LPAD);
    const uint8_t* mrow = g_mask8 + (size_t)bb * (Ls * LPAD);
    const int r0 = wm * 16 + (lane >> 2);
    const int r1 = r0 + 8;
    const int ncol = (lane & 3) * 2;
    const int lane16 = lane & 15;
    const int halfr = lane >> 4;

    for (int qt = 0; qt < 6; qt++) {
        const int q0 = qt * 64;
        const int qrow0 = q0 + r0, qrow1 = q0 + r1;
        const bool rv0 = qrow0 < Ls, rv1 = qrow1 < Ls;

        // ---- Q fragments (single fp16) ----
        uint32_t qh[2][4];
#pragma unroll
        for (int kk = 0; kk < 2; kk++) {
            uint32_t ro = (uint32_t)((q0 + wm * 16 + arow) * ASTR + kk * 16 + acolo) * 2;
            ldsm_x4(qh[kk][0], qh[kk][1], qh[kk][2], qh[kk][3], smb + OFF_QH + ro);
        }

        // ---- fused phase 1: per g, LDG bias/mask early; mma; epilogue ----
        float c[12][4];
        float mx0 = -FLT_MAX, mx1 = -FLT_MAX;
#pragma unroll
        for (int g = 0; g < 6; g++) {
            // issue bias/mask loads for this iteration's two n-tiles FIRST
            float2 bT[2][2]; uchar2 mT[2][2];   // [nt][row01]
#pragma unroll
            for (int nt = 0; nt < 2; nt++) {
                int col = nbase + g * 16 + nt * 8 + ncol;
                bool cv = col < Ls;
                bT[nt][0] = make_float2(0.f, 0.f); bT[nt][1] = make_float2(0.f, 0.f);
                mT[nt][0] = make_uchar2(0, 0);     mT[nt][1] = make_uchar2(0, 0);
                if (rv0 && cv) {
                    bT[nt][0] = *(const float2*)(bias0 + (size_t)qrow0 * LPAD + col);
                    mT[nt][0] = *(const uchar2*)(mrow + (size_t)qrow0 * LPAD + col);
                }
                if (rv1 && cv) {
                    bT[nt][1] = *(const float2*)(bias0 + (size_t)qrow1 * LPAD + col);
                    mT[nt][1] = *(const uchar2*)(mrow + (size_t)qrow1 * LPAD + col);
                }
            }

            uint32_t bh[2][4], bl[2][4];
#pragma unroll
            for (int kk = 0; kk < 2; kk++) {
                uint32_t rb = (uint32_t)((nbase + g * 16 + brow) * ASTR + kk * 16 + bcolo) * 2;
                ldsm_x4(bh[kk][0], bh[kk][1], bh[kk][2], bh[kk][3], smb + OFF_KH + rb);
                ldsm_x4(bl[kk][0], bl[kk][1], bl[kk][2], bl[kk][3], smb + OFF_KL + rb);
            }
            float cg[2][4];
#pragma unroll
            for (int nt = 0; nt < 2; nt++)
#pragma unroll
                for (int e = 0; e < 4; e++) cg[nt][e] = 0.0f;
#pragma unroll
            for (int kk = 0; kk < 2; kk++)
#pragma unroll
                for (int nt = 0; nt < 2; nt++) {
                    mma16816(cg[nt], qh[kk], bh[kk][nt * 2], bh[kk][nt * 2 + 1]);
                    mma16816(cg[nt], qh[kk], bl[kk][nt * 2], bl[kk][nt * 2 + 1]);
                }
            // epilogue for tiles 2g, 2g+1 (fully accumulated here)
#pragma unroll
            for (int nt = 0; nt < 2; nt++) {
                const int t = g * 2 + nt;
                int col = nbase + g * 16 + nt * 8 + ncol;
                bool cv0 = col < Ls, cv1 = (col + 1) < Ls;
                c[t][0] = (rv0 && cv0) ? (mT[nt][0].x ? -100000.0f
                          : fmaf(cg[nt][0], invscale, bT[nt][0].x)) : -1e9f;
                c[t][1] = (rv0 && cv1) ? (mT[nt][0].y ? -100000.0f
                          : fmaf(cg[nt][1], invscale, bT[nt][0].y)) : -1e9f;
                c[t][2] = (rv1 && cv0) ? (mT[nt][1].x ? -100000.0f
                          : fmaf(cg[nt][2], invscale, bT[nt][1].x)) : -1e9f;
                c[t][3] = (rv1 && cv1) ? (mT[nt][1].y ? -100000.0f
                          : fmaf(cg[nt][3], invscale, bT[nt][1].y)) : -1e9f;
                mx0 = fmaxf(mx0, fmaxf(c[t][0], c[t][1]));
                mx1 = fmaxf(mx1, fmaxf(c[t][2], c[t][3]));
            }
        }

        // ---- single-sync softmax; normalization deferred to post-PV ----
        mx0 = fmaxf(mx0, __shfl_xor_sync(0xffffffffu, mx0, 1));
        mx0 = fmaxf(mx0, __shfl_xor_sync(0xffffffffu, mx0, 2));
        mx1 = fmaxf(mx1, __shfl_xor_sync(0xffffffffu, mx1, 1));
        mx1 = fmaxf(mx1, __shfl_xor_sync(0xffffffffu, mx1, 2));

        float s0 = 0.0f, s1 = 0.0f;
#pragma unroll
        for (int t = 0; t < 12; t++) {
            float e0 = fexp(c[t][0] - mx0); c[t][0] = e0; s0 += e0;
            float e1 = fexp(c[t][1] - mx0); c[t][1] = e1; s0 += e1;
            float e2 = fexp(c[t][2] - mx1); c[t][2] = e2; s1 += e2;
            float e3 = fexp(c[t][3] - mx1); c[t][3] = e3; s1 += e3;
        }
        s0 += __shfl_xor_sync(0xffffffffu, s0, 1);
        s0 += __shfl_xor_sync(0xffffffffu, s0, 2);
        s1 += __shfl_xor_sync(0xffffffffu, s1, 1);
        s1 += __shfl_xor_sync(0xffffffffu, s1, 2);
        if ((lane & 3) == 0) {
            redmax[wn * 64 + r0] = mx0; redsum[wn * 64 + r0] = s0;
            redmax[wn * 64 + r1] = mx1; redsum[wn * 64 + r1] = s1;
        }
        __syncthreads();
        float f0, f1;
        {
            float gm0 = -FLT_MAX, gm1 = -FLT_MAX;
#pragma unroll
            for (int qd = 0; qd < 4; qd++) {
                gm0 = fmaxf(gm0, redmax[qd * 64 + r0]);
                gm1 = fmaxf(gm1, redmax[qd * 64 + r1]);
            }
            float S0 = 0.0f, S1 = 0.0f;
#pragma unroll
            for (int qd = 0; qd < 4; qd++) {
                S0 += redsum[qd * 64 + r0] * fexp(redmax[qd * 64 + r0] - gm0);
                S1 += redsum[qd * 64 + r1] * fexp(redmax[qd * 64 + r1] - gm1);
            }
            f0 = fexp(mx0 - gm0) / S0;
            f1 = fexp(mx1 - gm1) / S1;
        }

        // ---- phase 3: O = Ph * (Vh + Vl), then scale by f ----
        float oc[4][4];
#pragma unroll
        for (int nt = 0; nt < 4; nt++)
#pragma unroll
            for (int e = 0; e < 4; e++) oc[nt][e] = 0.0f;

#pragma unroll
        for (int kt = 0; kt < 6; kt++) {
            uint32_t ph[4];
#pragma unroll
            for (int half = 0; half < 2; half++) {
                const float* cc = c[2 * kt + half];
                ph[half * 2 + 0] = packh(cc[0], cc[1]);
                ph[half * 2 + 1] = packh(cc[2], cc[3]);
            }
            const int krow = nbase + kt * 16;
            uint32_t vh[2][4], vl[2][4];
#pragma unroll
            for (int g = 0; g < 2; g++) {
                uint32_t ad = (uint32_t)((krow + arow) * ASTR + g * 16 + acolo) * 2;
                ldsm_x4_t(vh[g][0], vh[g][1], vh[g][2], vh[g][3], smb + OFF_VH + ad);
                ldsm_x4_t(vl[g][0], vl[g][1], vl[g][2], vl[g][3], smb + OFF_VL + ad);
            }
#pragma unroll
            for (int nt = 0; nt < 4; nt++) {
                const int g = nt >> 1, i2 = (nt & 1) * 2;
                mma16816(oc[nt], ph, vh[g][i2], vh[g][i2 + 1]);
                mma16816(oc[nt], ph, vl[g][i2], vl[g][i2 + 1]);
            }
        }
#pragma unroll
        for (int nt = 0; nt < 4; nt++) {
            oc[nt][0] *= f0; oc[nt][1] *= f0;
            oc[nt][2] *= f1; oc[nt][3] *= f1;
        }

        // ---- all quarters write slabs; distributed reduce + fp16 store ----
        {
            float* dst = ored + (size_t)wn * (64 * ORSTR);
#pragma unroll
            for (int nt = 0; nt < 4; nt++) {
                *(float2*)(dst + r0 * ORSTR + nt * 8 + ncol) = make_float2(oc[nt][0], oc[nt][1]);
                *(float2*)(dst + r1 * ORSTR + nt * 8 + ncol) = make_float2(oc[nt][2], oc[nt][3]);
            }
        }
        __syncthreads();
#pragma unroll
        for (int p = 0; p < 2; p++) {
            int row = wid * 4 + p * 2 + halfr;
            int qrow = q0 + row;
            if (qrow < Ls) {
                int col = lane16 * 2;
                float s0o = 0.0f, s1o = 0.0f;
#pragma unroll
                for (int qd = 0; qd < 4; qd++) {
                    float2 v = *(float2*)(ored + qd * (64 * ORSTR) + row * ORSTR + col);
                    s0o += v.x; s1o += v.y;
                }
                size_t ad = (size_t)(bb * Ls + qrow) * Es + h * HDs + col;
                *(uint32_t*)(g_a + ad) = packh(s0o, s1o);
            }
        }
    }
}

// ============================================================
// launch
// ============================================================
extern "C" void kernel_launch(void* const* d_in, const int* in_sizes, int n_in,
                              void* d_out, int out_size)
{
    (void)in_sizes; (void)n_in; (void)out_size;
    const float* query   = (const float*)d_in[0];
    const float* key     = (const float*)d_in[1];
    const float* value   = (const float*)d_in[2];
    const float* indices = (const float*)d_in[3];
    const void*  mask    = d_in[4];
    const float* bq      = (const float*)d_in[6];
    const float* Wq      = (const float*)d_in[5];
    const float* Wk      = (const float*)d_in[7];
    const float* bk      = (const float*)d_in[8];
    const float* Wv      = (const float*)d_in[9];
    const float* Ww      = (const float*)d_in[10];
    const float* bw      = (const float*)d_in[11];
    const float* scale   = (const float*)d_in[12];
    const float* W1      = (const float*)d_in[13];
    const float* b1      = (const float*)d_in[14];
    const float* W2      = (const float*)d_in[15];
    const float* b2      = (const float*)d_in[16];
    float* out = (float*)d_out;

    cudaFuncSetAttribute(qkv_gemm_kernel, cudaFuncAttributeMaxDynamicSharedMemorySize,
                         TG_SMEM);
    cudaFuncSetAttribute(out_gemm_kernel, cudaFuncAttributeMaxDynamicSharedMemorySize,
                         TG_SMEM);
    cudaFuncSetAttribute(attn3_kernel, cudaFuncAttributeMaxDynamicSharedMemorySize,
                         ATT3_SMEM);

    const int n4 = ROWSs * Es / 4;
    const int splitg = (n4 + 255) / 256;

    wsplit_all_kernel<<<dim3(8, 8, 4), 256>>>(Wq, Wk, Wv, Ww);
    split3_kernel<<<dim3(splitg, 3), 256>>>((const float4*)query, (const float4*)key,
                                            (const float4*)value, n4);
    detect_mask_kernel<<<1, 256>>>((const unsigned int*)mask);
    // Q/K/V projections (+fused norm for Q,K) in ONE launch  (ncu slot)
    qkv_gemm_kernel<<<dim3(ROWSs / 128, Es / 128, 3), 256, TG_SMEM>>>(bq, bk);
    mask_prep_kernel<<<(BBs * LLs + 255) / 256, 256>>>(mask);
    bias_lut_kernel<<<(NCLS + 7) / 8, 256>>>(W1, b1, W2, b2);
    bias_gather_kernel<<<(LLs + 255) / 256, 256>>>(indices);
    attn3_kernel<<<dim3(Hs, BBs), 512, ATT3_SMEM>>>(scale);
    out_gemm_kernel<<<dim3(ROWSs / 128, Es / 128), 256, TG_SMEM>>>(bw, out);
}

// round 13
// speedup vs baseline: 5.2509x; 1.1678x over previous
#include <cuda_runtime.h>
#include <cuda_fp16.h>
#include <math.h>
#include <float.h>
#include <stdint.h>

// Problem dims
#define BBs   128
#define Ls    343
#define Es    256
#define Hs    8
#define HDs   32
#define HIDs  512
#define LLs   (Ls * Ls)       // 117649
#define ROWSs (BBs * Ls)      // 43904
#define LPAD  344
#define NCLS  2197            // 13^3 distinct index triples

// -------- scratch (device globals; no allocation allowed) --------
__device__ float g_bias[Hs * Ls * LPAD];
__device__ __align__(16) float g_blut[NCLS * 8];
__device__ int   g_mask_mode;
__device__ uint8_t g_mask8[BBs * Ls * LPAD];
__device__ __half g_xq[ROWSs * Es], g_xk[ROWSs * Es], g_xv[ROWSs * Es];
__device__ __half g_a[ROWSs * Es];
__device__ __half g_w4[4 * Es * Es];          // weights, transposed [n][k], fp16
__device__ __half g_qh[BBs * Hs * Ls * HDs];  // normalized q (fp16)
__device__ __half g_kh[BBs * Hs * Ls * HDs];  // normalized k (fp16)
__device__ __half g_vh[BBs * Hs * Ls * HDs];  // v (fp16)

// ============================================================
// PTX helpers (baseline sm_80+ ISA; harness targets sm_103 w/o 'a')
// ============================================================
__device__ __forceinline__ uint32_t smem_u32(const void* p) {
    uint32_t a;
    asm("{ .reg .u64 t; cvta.to.shared.u64 t, %1; cvt.u32.u64 %0, t; }" : "=r"(a) : "l"(p));
    return a;
}
__device__ __forceinline__ void ldsm_x4(uint32_t& r0, uint32_t& r1, uint32_t& r2,
                                        uint32_t& r3, uint32_t addr) {
    asm volatile("ldmatrix.sync.aligned.m8n8.x4.shared.b16 {%0,%1,%2,%3}, [%4];"
                 : "=r"(r0), "=r"(r1), "=r"(r2), "=r"(r3) : "r"(addr));
}
__device__ __forceinline__ void ldsm_x4_t(uint32_t& r0, uint32_t& r1, uint32_t& r2,
                                          uint32_t& r3, uint32_t addr) {
    asm volatile("ldmatrix.sync.aligned.m8n8.x4.trans.shared.b16 {%0,%1,%2,%3}, [%4];"
                 : "=r"(r0), "=r"(r1), "=r"(r2), "=r"(r3) : "r"(addr));
}
__device__ __forceinline__ void mma16816(float* c, const uint32_t* a,
                                         uint32_t b0, uint32_t b1) {
    asm volatile(
        "mma.sync.aligned.m16n8k16.row.col.f32.f16.f16.f32 "
        "{%0,%1,%2,%3}, {%4,%5,%6,%7}, {%8,%9}, {%0,%1,%2,%3};"
        : "+f"(c[0]), "+f"(c[1]), "+f"(c[2]), "+f"(c[3])
        : "r"(a[0]), "r"(a[1]), "r"(a[2]), "r"(a[3]), "r"(b0), "r"(b1));
}
__device__ __forceinline__ void cp_async16(uint32_t dst, const void* src) {
    asm volatile("cp.async.cg.shared.global [%0], [%1], 16;" :: "r"(dst), "l"(src));
}
__device__ __forceinline__ void cp_commit() { asm volatile("cp.async.commit_group;"); }
__device__ __forceinline__ void cp_wait1() { asm volatile("cp.async.wait_group 1;"); }
__device__ __forceinline__ void cp_wait0() { asm volatile("cp.async.wait_group 0;"); }

__device__ __forceinline__ uint32_t packh(float a, float b) {
    __half2 t = __floats2half2_rn(a, b);
    return *(uint32_t*)&t;
}

// Fast exp on FMA/ALU pipes only (no MUFU). rel err ~2.4e-6.
__device__ __forceinline__ float fexp(float x) {
    float y = fmaxf(x * 1.4426950408889634f, -126.0f);
    float yr = __fadd_rn(y, 12582912.0f);
    float n  = __fsub_rn(yr, 12582912.0f);
    float f  = __fsub_rn(y, n);
    float p  = 1.3333558e-3f;
    p = fmaf(p, f, 9.6181291e-3f);
    p = fmaf(p, f, 5.5504109e-2f);
    p = fmaf(p, f, 2.4022651e-1f);
    p = fmaf(p, f, 6.9314718e-1f);
    p = fmaf(p, f, 1.0f);
    return __int_as_float(__float_as_int(p) + (__float_as_int(yr) << 23));
}

// ============================================================
// Kernel: detect mask dtype
// ============================================================
__global__ void detect_mask_kernel(const unsigned int* __restrict__ m)
{
    __shared__ int s_float, s_multi;
    if (threadIdx.x == 0) { s_float = 0; s_multi = 0; }
    __syncthreads();
    for (int i = threadIdx.x; i < 4096; i += 256) {
        unsigned int w = m[i];
        if (w == 0x3F800000u) atomicOr(&s_float, 1);
        else if (w != 0u && (w & 0xFFFFFF00u) != 0u) atomicOr(&s_multi, 1);
    }
    __syncthreads();
    if (threadIdx.x == 0)
        g_mask_mode = s_float ? 2 : (s_multi ? 0 : 1);
}

// ============================================================
// Kernel: normalize mask to padded uint8 table
// ============================================================
__global__ __launch_bounds__(256) void mask_prep_kernel(const void* __restrict__ maskp)
{
    int idx = blockIdx.x * 256 + threadIdx.x;
    if (idx >= BBs * LLs) return;
    int bb = idx / LLs;
    int p = idx - bb * LLs;
    int i = p / Ls, j = p - i * Ls;
    int mode = g_mask_mode;
    bool m = (mode == 0) ? (((const uint8_t*)maskp)[idx] != 0)
           : (mode == 1) ? (((const int*)maskp)[idx] != 0)
                         : (((const float*)maskp)[idx] != 0.0f);
    g_mask8[(size_t)bb * (Ls * LPAD) + i * LPAD + j] = m ? 1 : 0;
}

// ============================================================
// Kernel: CPB LUT — one warp per distinct index-triple class.
// ============================================================
__global__ __launch_bounds__(256) void bias_lut_kernel(
    const float* __restrict__ W1, const float* __restrict__ b1,
    const float* __restrict__ W2, const float* __restrict__ b2)
{
    int wid = threadIdx.x >> 5, lane = threadIdx.x & 31;
    int cls = blockIdx.x * 8 + wid;
    if (cls >= NCLS) return;
    int d0 = cls % 13 - 6;
    int d1 = (cls / 13) % 13 - 6;
    int d2 = cls / 169 - 6;
    float x0 = copysignf(log2f(1.0f + fabsf((float)d0)) * (1.0f / 3.0f), (float)d0);
    float x1 = copysignf(log2f(1.0f + fabsf((float)d1)) * (1.0f / 3.0f), (float)d1);
    float x2 = copysignf(log2f(1.0f + fabsf((float)d2)) * (1.0f / 3.0f), (float)d2);
    float acc[8];
#pragma unroll
    for (int h = 0; h < 8; h++) acc[h] = 0.0f;
    for (int t = lane; t < HIDs; t += 32) {
        float hv = fmaxf(fmaf(x0, W1[t], fmaf(x1, W1[HIDs + t],
                        fmaf(x2, W1[2 * HIDs + t], b1[t]))), 0.0f);
#pragma unroll
        for (int h = 0; h < 8; h++) acc[h] = fmaf(hv, W2[t * 8 + h], acc[h]);
    }
#pragma unroll
    for (int h = 0; h < 8; h++) {
#pragma unroll
        for (int o = 16; o > 0; o >>= 1)
            acc[h] += __shfl_xor_sync(0xffffffffu, acc[h], o);
    }
    if (lane == 0) {
#pragma unroll
        for (int h = 0; h < 8; h++) {
            float z = acc[h] + b2[h];
            g_blut[cls * 8 + h] = 16.0f / (1.0f + fexp(-z));
        }
    }
}

// ============================================================
// Kernel: gather LUT -> padded bias planes
// ============================================================
__global__ __launch_bounds__(256) void bias_gather_kernel(
    const float* __restrict__ indices)
{
    int p = blockIdx.x * 256 + threadIdx.x;
    if (p >= LLs) return;
    int i = p / Ls, j = p - i * Ls;
    int q0 = __float2int_rn(indices[p * 3 + 0]) + 6;
    int q1 = __float2int_rn(indices[p * 3 + 1]) + 6;
    int q2 = __float2int_rn(indices[p * 3 + 2]) + 6;
    int cls = q0 + 13 * q1 + 169 * q2;
    float4 v0 = *(const float4*)(g_blut + cls * 8);
    float4 v1 = *(const float4*)(g_blut + cls * 8 + 4);
    float vals[8] = { v0.x, v0.y, v0.z, v0.w, v1.x, v1.y, v1.z, v1.w };
#pragma unroll
    for (int h = 0; h < 8; h++)
        g_bias[(size_t)h * (Ls * LPAD) + i * LPAD + j] = vals[h];
}

// ============================================================
// Kernel: round all 3 fp32 inputs -> single fp16 (batched, grid.y=3)
// ============================================================
__global__ __launch_bounds__(256) void split3_kernel(
    const float4* __restrict__ q, const float4* __restrict__ k,
    const float4* __restrict__ v, int n4)
{
    const int z = blockIdx.y;
    const float4* in = (z == 0) ? q : (z == 1) ? k : v;
    __half* dst = (z == 0) ? g_xq : (z == 1) ? g_xk : g_xv;
    int i = blockIdx.x * 256 + threadIdx.x;
    if (i >= n4) return;
    float4 val = in[i];
    uint2 o = make_uint2(packh(val.x, val.y), packh(val.z, val.w));
    *(uint2*)(dst + (size_t)i * 4) = o;
}

// ============================================================
// Kernel: all 4 weight transposes -> fp16 (grid.z=4)
// ============================================================
__global__ __launch_bounds__(256) void wsplit_all_kernel(
    const float* __restrict__ Wq, const float* __restrict__ Wk,
    const float* __restrict__ Wv, const float* __restrict__ Ww)
{
    __shared__ float t[32][33];
    const int z = blockIdx.z;
    const float* W = (z == 0) ? Wq : (z == 1) ? Wk : (z == 2) ? Wv : Ww;
    __half* ht = g_w4 + (size_t)z * Es * Es;
    int bn = blockIdx.x * 32, bk = blockIdx.y * 32;
    int lx = threadIdx.x & 31, ly = threadIdx.x >> 5;
    for (int yy = ly; yy < 32; yy += 8)
        t[yy][lx] = W[(size_t)(bk + yy) * Es + bn + lx];
    __syncthreads();
    for (int yy = ly; yy < 32; yy += 8)
        ht[(size_t)(bn + yy) * Es + bk + lx] = __float2half_rn(t[lx][yy]);
}

// ============================================================
// Shared fp16 GEMM body: C = A*W, fp32 accum.
// 4 K-chunks of 64, 3-stage cp.async pipeline, one sync per chunk.
// ============================================================
#define TGS 72
#define TGBUF 18432
#define TGSTAGE (2 * TGBUF)
#define TG_SMEM (3 * TGSTAGE)         // 110592 B

__device__ __forceinline__ void tgemm_body(
    char* dsm,
    const __half* __restrict__ A, const __half* __restrict__ W,
    const float* __restrict__ bias, float* __restrict__ C, int remap,
    __half* __restrict__ Oh, int donorm)
{
    const int tid = threadIdx.x;
    const int wid = tid >> 5;
    const int lane = tid & 31;
    const int m0 = blockIdx.x * 128;
    const int n0 = blockIdx.y * 128;
    const int wm = wid & 1;
    const int wn = wid >> 1;
    const uint32_t smb = smem_u32(dsm);

    float c[4][4][4];
#pragma unroll
    for (int i = 0; i < 4; i++)
#pragma unroll
        for (int j = 0; j < 4; j++)
#pragma unroll
            for (int k = 0; k < 4; k++) c[i][j][k] = 0.0f;

    auto prefetch = [&](int i) {
        const int s = i % 3;
        const int k0 = i * 64;
        const uint32_t bA = smb + s * TGSTAGE;
        const uint32_t bB = bA + TGBUF;
#pragma unroll
        for (int j = 0; j < 4; j++) {
            int x = tid + j * 256;
            int r = x >> 3, cc = x & 7;
            uint32_t off = (uint32_t)(r * TGS + cc * 8) * 2;
            cp_async16(bA + off, A + (size_t)(m0 + r) * Es + k0 + cc * 8);
            cp_async16(bB + off, W + (size_t)(n0 + r) * Es + k0 + cc * 8);
        }
    };

    prefetch(0); cp_commit();
    prefetch(1); cp_commit();

    const int arow = (lane & 7) + ((lane >> 3) & 1) * 8;
    const int acolo = ((lane >> 4) & 1) * 8;
    const int brow = (lane & 7) + ((lane >> 4) & 1) * 8;
    const int bcolo = ((lane >> 3) & 1) * 8;

    for (int i = 0; i < 4; i++) {
        if (i < 3) cp_wait1(); else cp_wait0();
        __syncthreads();
        if (i < 2) { prefetch(i + 2); cp_commit(); }

        const uint32_t bA = smb + (i % 3) * TGSTAGE;
        const uint32_t bB = bA + TGBUF;
#pragma unroll
        for (int ks = 0; ks < 4; ks++) {
            const int k0 = ks * 16;
            uint32_t a[4][4], b[2][4];
#pragma unroll
            for (int mt = 0; mt < 4; mt++)
                ldsm_x4(a[mt][0], a[mt][1], a[mt][2], a[mt][3],
                        bA + (uint32_t)((wm * 64 + mt * 16 + arow) * TGS + k0 + acolo) * 2);
#pragma unroll
            for (int g = 0; g < 2; g++)
                ldsm_x4(b[g][0], b[g][1], b[g][2], b[g][3],
                        bB + (uint32_t)((wn * 32 + g * 16 + brow) * TGS + k0 + bcolo) * 2);
#pragma unroll
            for (int mt = 0; mt < 4; mt++)
#pragma unroll
                for (int nt = 0; nt < 4; nt++)
                    mma16816(c[mt][nt], a[mt], b[nt >> 1][(nt & 1) * 2],
                             b[nt >> 1][(nt & 1) * 2 + 1]);
        }
    }

    const int tq = lane >> 2;
    const int tr = lane & 3;
#pragma unroll
    for (int mt = 0; mt < 4; mt++) {
        const int m = m0 + wm * 64 + mt * 16 + tq;
        float v0x[4], v0y[4], v1x[4], v1y[4];
#pragma unroll
        for (int nt = 0; nt < 4; nt++) {
            const int n = n0 + wn * 32 + nt * 8 + tr * 2;
            float bx = 0.0f, by = 0.0f;
            if (bias) { float2 bv = *(const float2*)(bias + n); bx = bv.x; by = bv.y; }
            v0x[nt] = c[mt][nt][0] + bx; v0y[nt] = c[mt][nt][1] + by;
            v1x[nt] = c[mt][nt][2] + bx; v1y[nt] = c[mt][nt][3] + by;
        }
        if (donorm) {
            float ss0 = 0.0f, ss1 = 0.0f;
#pragma unroll
            for (int nt = 0; nt < 4; nt++) {
                ss0 = fmaf(v0x[nt], v0x[nt], fmaf(v0y[nt], v0y[nt], ss0));
                ss1 = fmaf(v1x[nt], v1x[nt], fmaf(v1y[nt], v1y[nt], ss1));
            }
            ss0 += __shfl_xor_sync(0xffffffffu, ss0, 1);
            ss0 += __shfl_xor_sync(0xffffffffu, ss0, 2);
            ss1 += __shfl_xor_sync(0xffffffffu, ss1, 1);
            ss1 += __shfl_xor_sync(0xffffffffu, ss1, 2);
            float i0 = 1.0f / fmaxf(sqrtf(ss0), 1e-12f);
            float i1 = 1.0f / fmaxf(sqrtf(ss1), 1e-12f);
#pragma unroll
            for (int nt = 0; nt < 4; nt++) {
                v0x[nt] *= i0; v0y[nt] *= i0;
                v1x[nt] *= i1; v1y[nt] *= i1;
            }
        }
#pragma unroll
        for (int nt = 0; nt < 4; nt++) {
            const int n = n0 + wn * 32 + nt * 8 + tr * 2;
            size_t a0, a1;
            if (remap) {
                const int hh = n >> 5, hd = n & 31;
                int bbw = m / Ls, l = m - bbw * Ls;
                a0 = ((size_t)(bbw * Hs + hh) * Ls + l) * HDs + hd;
                int m2 = m + 8;
                int bbw2 = m2 / Ls, l2 = m2 - bbw2 * Ls;
                a1 = ((size_t)(bbw2 * Hs + hh) * Ls + l2) * HDs + hd;
            } else {
                a0 = (size_t)m * Es + n;
                a1 = (size_t)(m + 8) * Es + n;
            }
            if (Oh) {
                *(uint32_t*)(Oh + a0) = packh(v0x[nt], v0y[nt]);
                *(uint32_t*)(Oh + a1) = packh(v1x[nt], v1y[nt]);
            } else {
                *(float2*)(C + a0) = make_float2(v0x[nt], v0y[nt]);
                *(float2*)(C + a1) = make_float2(v1x[nt], v1y[nt]);
            }
        }
    }
}

// Q/K/V projections in ONE launch (grid.z selects operand set)
__global__ __launch_bounds__(256) void qkv_gemm_kernel(
    const float* __restrict__ bq, const float* __restrict__ bk)
{
    extern __shared__ char dsm[];
    const int z = blockIdx.z;
    const __half* A  = (z == 0) ? g_xq : (z == 1) ? g_xk : g_xv;
    const __half* W  = g_w4 + (size_t)z * Es * Es;
    const float* bias = (z == 0) ? bq : (z == 1) ? bk : nullptr;
    __half* Oh = (z == 0) ? g_qh : (z == 1) ? g_kh : g_vh;
    tgemm_body(dsm, A, W, bias, nullptr, 1, Oh, z < 2);
}

// output projection -> fp32 d_out
__global__ __launch_bounds__(256) void out_gemm_kernel(
    const float* __restrict__ bw, float* __restrict__ out)
{
    extern __shared__ char dsm[];
    tgemm_body(dsm, g_a, g_w4 + 3 * (size_t)Es * Es, bw, out, 0, nullptr, 0);
}

// ============================================================
// Kernel: persistent fp16 attention per (head, window).
// SMEM: Q, K, V single fp16 (384x80B each) + reductions.
// ============================================================
#define ASTR 40
#define ABUF 30720
#define OFF_QH (0 * ABUF)
#define OFF_KH (1 * ABUF)
#define OFF_VH (2 * ABUF)
#define OFF_RMAX (3 * ABUF)            // 92160
#define OFF_RSUM (OFF_RMAX + 1024)
#define OFF_ORED (OFF_RSUM + 1024)
#define ORSTR 34
#define ATT3_SMEM (OFF_ORED + 4 * 64 * ORSTR * 4)   // 129024

__global__ __launch_bounds__(512) void attn3_kernel(const float* __restrict__ scalep)
{
    extern __shared__ char sm2[];
    float* redmax = (float*)(sm2 + OFF_RMAX);
    float* redsum = (float*)(sm2 + OFF_RSUM);
    float* ored   = (float*)(sm2 + OFF_ORED);
    const uint32_t smb = smem_u32(sm2);

    const int tid = threadIdx.x;
    const int wid = tid >> 5;
    const int lane = tid & 31;
    const int h = blockIdx.x;
    const int bb = blockIdx.y;
    const size_t gbase = (size_t)(bb * Hs + h) * (Ls * HDs);

    // ---- fill Q,K,V once ----
    {
        const __half* gsrc[3] = { g_qh + gbase, g_kh + gbase, g_vh + gbase };
#pragma unroll
        for (int arr = 0; arr < 3; arr++)
            for (int i = tid; i < 1372; i += 512) {
                int row = i >> 2, ch = i & 3;
                cp_async16(smb + arr * ABUF + row * 80 + ch * 16,
                           gsrc[arr] + row * HDs + ch * 8);
            }
        for (int i = tid; i < 492; i += 512) {   // pad rows 343..383 x 4 x 16B
            int arr = i / 164, j = i - arr * 164;
            int r = 343 + (j >> 2), ch = j & 3;
            *(uint4*)(sm2 + arr * ABUF + r * 80 + ch * 16) = make_uint4(0, 0, 0, 0);
        }
        cp_commit();
        cp_wait0();
        __syncthreads();
    }

    const int wm = wid & 3;
    const int wn = wid >> 2;
    const int nbase = wn * 96;

    const int arow = (lane & 7) + ((lane >> 3) & 1) * 8;
    const int acolo = ((lane >> 4) & 1) * 8;
    const int brow = (lane & 7) + ((lane >> 4) & 1) * 8;
    const int bcolo = ((lane >> 3) & 1) * 8;

    const float invscale = 1.0f / fmaxf(scalep[0], 0.01f);
    const float* bias0 = g_bias + (size_t)h * (Ls * LPAD);
    const uint8_t* mrow = g_mask8 + (size_t)bb * (Ls * LPAD);
    const int r0 = wm * 16 + (lane >> 2);
    const int r1 = r0 + 8;
    const int ncol = (lane & 3) * 2;
    const int lane16 = lane & 15;
    const int halfr = lane >> 4;

    for (int qt = 0; qt < 6; qt++) {
        const int q0 = qt * 64;
        const int qrow0 = q0 + r0, qrow1 = q0 + r1;
        const bool rv0 = qrow0 < Ls, rv1 = qrow1 < Ls;

        // ---- Q fragments ----
        uint32_t qh[2][4];
#pragma unroll
        for (int kk = 0; kk < 2; kk++) {
            uint32_t ro = (uint32_t)((q0 + wm * 16 + arow) * ASTR + kk * 16 + acolo) * 2;
            ldsm_x4(qh[kk][0], qh[kk][1], qh[kk][2], qh[kk][3], smb + OFF_QH + ro);
        }

        // ---- fused phase 1: per g, LDG bias/mask early; mma; epilogue ----
        float c[12][4];
        float mx0 = -FLT_MAX, mx1 = -FLT_MAX;
#pragma unroll
        for (int g = 0; g < 6; g++) {
            float2 bT[2][2]; uchar2 mT[2][2];
#pragma unroll
            for (int nt = 0; nt < 2; nt++) {
                int col = nbase + g * 16 + nt * 8 + ncol;
                bool cv = col < Ls;
                bT[nt][0] = make_float2(0.f, 0.f); bT[nt][1] = make_float2(0.f, 0.f);
                mT[nt][0] = make_uchar2(0, 0);     mT[nt][1] = make_uchar2(0, 0);
                if (rv0 && cv) {
                    bT[nt][0] = *(const float2*)(bias0 + (size_t)qrow0 * LPAD + col);
                    mT[nt][0] = *(const uchar2*)(mrow + (size_t)qrow0 * LPAD + col);
                }
                if (rv1 && cv) {
                    bT[nt][1] = *(const float2*)(bias0 + (size_t)qrow1 * LPAD + col);
                    mT[nt][1] = *(const uchar2*)(mrow + (size_t)qrow1 * LPAD + col);
                }
            }

            uint32_t bh[2][4];
#pragma unroll
            for (int kk = 0; kk < 2; kk++) {
                uint32_t rb = (uint32_t)((nbase + g * 16 + brow) * ASTR + kk * 16 + bcolo) * 2;
                ldsm_x4(bh[kk][0], bh[kk][1], bh[kk][2], bh[kk][3], smb + OFF_KH + rb);
            }
            float cg[2][4];
#pragma unroll
            for (int nt = 0; nt < 2; nt++)
#pragma unroll
                for (int e = 0; e < 4; e++) cg[nt][e] = 0.0f;
#pragma unroll
            for (int kk = 0; kk < 2; kk++)
#pragma unroll
                for (int nt = 0; nt < 2; nt++)
                    mma16816(cg[nt], qh[kk], bh[kk][nt * 2], bh[kk][nt * 2 + 1]);
#pragma unroll
            for (int nt = 0; nt < 2; nt++) {
                const int t = g * 2 + nt;
                int col = nbase + g * 16 + nt * 8 + ncol;
                bool cv0 = col < Ls, cv1 = (col + 1) < Ls;
                c[t][0] = (rv0 && cv0) ? (mT[nt][0].x ? -100000.0f
                          : fmaf(cg[nt][0], invscale, bT[nt][0].x)) : -1e9f;
                c[t][1] = (rv0 && cv1) ? (mT[nt][0].y ? -100000.0f
                          : fmaf(cg[nt][1], invscale, bT[nt][0].y)) : -1e9f;
                c[t][2] = (rv1 && cv0) ? (mT[nt][1].x ? -100000.0f
                          : fmaf(cg[nt][2], invscale, bT[nt][1].x)) : -1e9f;
                c[t][3] = (rv1 && cv1) ? (mT[nt][1].y ? -100000.0f
                          : fmaf(cg[nt][3], invscale, bT[nt][1].y)) : -1e9f;
                mx0 = fmaxf(mx0, fmaxf(c[t][0], c[t][1]));
                mx1 = fmaxf(mx1, fmaxf(c[t][2], c[t][3]));
            }
        }

        // ---- single-sync softmax; normalization deferred to post-PV ----
        mx0 = fmaxf(mx0, __shfl_xor_sync(0xffffffffu, mx0, 1));
        mx0 = fmaxf(mx0, __shfl_xor_sync(0xffffffffu, mx0, 2));
        mx1 = fmaxf(mx1, __shfl_xor_sync(0xffffffffu, mx1, 1));
        mx1 = fmaxf(mx1, __shfl_xor_sync(0xffffffffu, mx1, 2));

        float s0 = 0.0f, s1 = 0.0f;
#pragma unroll
        for (int t = 0; t < 12; t++) {
            float e0 = fexp(c[t][0] - mx0); c[t][0] = e0; s0 += e0;
            float e1 = fexp(c[t][1] - mx0); c[t][1] = e1; s0 += e1;
            float e2 = fexp(c[t][2] - mx1); c[t][2] = e2; s1 += e2;
            float e3 = fexp(c[t][3] - mx1); c[t][3] = e3; s1 += e3;
        }
        s0 += __shfl_xor_sync(0xffffffffu, s0, 1);
        s0 += __shfl_xor_sync(0xffffffffu, s0, 2);
        s1 += __shfl_xor_sync(0xffffffffu, s1, 1);
        s1 += __shfl_xor_sync(0xffffffffu, s1, 2);
        if ((lane & 3) == 0) {
            redmax[wn * 64 + r0] = mx0; redsum[wn * 64 + r0] = s0;
            redmax[wn * 64 + r1] = mx1; redsum[wn * 64 + r1] = s1;
        }
        __syncthreads();
        float f0, f1;
        {
            float gm0 = -FLT_MAX, gm1 = -FLT_MAX;
#pragma unroll
            for (int qd = 0; qd < 4; qd++) {
                gm0 = fmaxf(gm0, redmax[qd * 64 + r0]);
                gm1 = fmaxf(gm1, redmax[qd * 64 + r1]);
            }
            float S0 = 0.0f, S1 = 0.0f;
#pragma unroll
            for (int qd = 0; qd < 4; qd++) {
                S0 += redsum[qd * 64 + r0] * fexp(redmax[qd * 64 + r0] - gm0);
                S1 += redsum[qd * 64 + r1] * fexp(redmax[qd * 64 + r1] - gm1);
            }
            f0 = fexp(mx0 - gm0) / S0;
            f1 = fexp(mx1 - gm1) / S1;
        }

        // ---- phase 3: O = P * V, then scale by f ----
        float oc[4][4];
#pragma unroll
        for (int nt = 0; nt < 4; nt++)
#pragma unroll
            for (int e = 0; e < 4; e++) oc[nt][e] = 0.0f;

#pragma unroll
        for (int kt = 0; kt < 6; kt++) {
            uint32_t ph[4];
#pragma unroll
            for (int half = 0; half < 2; half++) {
                const float* cc = c[2 * kt + half];
                ph[half * 2 + 0] = packh(cc[0], cc[1]);
                ph[half * 2 + 1] = packh(cc[2], cc[3]);
            }
            const int krow = nbase + kt * 16;
            uint32_t vh[2][4];
#pragma unroll
            for (int g = 0; g < 2; g++) {
                uint32_t ad = (uint32_t)((krow + arow) * ASTR + g * 16 + acolo) * 2;
                ldsm_x4_t(vh[g][0], vh[g][1], vh[g][2], vh[g][3], smb + OFF_VH + ad);
            }
#pragma unroll
            for (int nt = 0; nt < 4; nt++) {
                const int g = nt >> 1, i2 = (nt & 1) * 2;
                mma16816(oc[nt], ph, vh[g][i2], vh[g][i2 + 1]);
            }
        }
#pragma unroll
        for (int nt = 0; nt < 4; nt++) {
            oc[nt][0] *= f0; oc[nt][1] *= f0;
            oc[nt][2] *= f1; oc[nt][3] *= f1;
        }

        // ---- all quarters write slabs; distributed reduce + fp16 store ----
        {
            float* dst = ored + (size_t)wn * (64 * ORSTR);
#pragma unroll
            for (int nt = 0; nt < 4; nt++) {
                *(float2*)(dst + r0 * ORSTR + nt * 8 + ncol) = make_float2(oc[nt][0], oc[nt][1]);
                *(float2*)(dst + r1 * ORSTR + nt * 8 + ncol) = make_float2(oc[nt][2], oc[nt][3]);
            }
        }
        __syncthreads();
#pragma unroll
        for (int p = 0; p < 2; p++) {
            int row = wid * 4 + p * 2 + halfr;
            int qrow = q0 + row;
            if (qrow < Ls) {
                int col = lane16 * 2;
                float s0o = 0.0f, s1o = 0.0f;
#pragma unroll
                for (int qd = 0; qd < 4; qd++) {
                    float2 v = *(float2*)(ored + qd * (64 * ORSTR) + row * ORSTR + col);
                    s0o += v.x; s1o += v.y;
                }
                size_t ad = (size_t)(bb * Ls + qrow) * Es + h * HDs + col;
                *(uint32_t*)(g_a + ad) = packh(s0o, s1o);
            }
        }
    }
}

// ============================================================
// launch
// ============================================================
extern "C" void kernel_launch(void* const* d_in, const int* in_sizes, int n_in,
                              void* d_out, int out_size)
{
    (void)in_sizes; (void)n_in; (void)out_size;
    const float* query   = (const float*)d_in[0];
    const float* key     = (const float*)d_in[1];
    const float* value   = (const float*)d_in[2];
    const float* indices = (const float*)d_in[3];
    const void*  mask    = d_in[4];
    const float* Wq      = (const float*)d_in[5];
    const float* bq      = (const float*)d_in[6];
    const float* Wk      = (const float*)d_in[7];
    const float* bk      = (const float*)d_in[8];
    const float* Wv      = (const float*)d_in[9];
    const float* Ww      = (const float*)d_in[10];
    const float* bw      = (const float*)d_in[11];
    const float* scale   = (const float*)d_in[12];
    const float* W1      = (const float*)d_in[13];
    const float* b1      = (const float*)d_in[14];
    const float* W2      = (const float*)d_in[15];
    const float* b2      = (const float*)d_in[16];
    float* out = (float*)d_out;

    cudaFuncSetAttribute(qkv_gemm_kernel, cudaFuncAttributeMaxDynamicSharedMemorySize,
                         TG_SMEM);
    cudaFuncSetAttribute(out_gemm_kernel, cudaFuncAttributeMaxDynamicSharedMemorySize,
                         TG_SMEM);
    cudaFuncSetAttribute(attn3_kernel, cudaFuncAttributeMaxDynamicSharedMemorySize,
                         ATT3_SMEM);

    const int n4 = ROWSs * Es / 4;
    const int splitg = (n4 + 255) / 256;

    wsplit_all_kernel<<<dim3(8, 8, 4), 256>>>(Wq, Wk, Wv, Ww);
    split3_kernel<<<dim3(splitg, 3), 256>>>((const float4*)query, (const float4*)key,
                                            (const float4*)value, n4);
    detect_mask_kernel<<<1, 256>>>((const unsigned int*)mask);
    // Q/K/V projections (+fused norm for Q,K) in ONE launch  (ncu slot)
    qkv_gemm_kernel<<<dim3(ROWSs / 128, Es / 128, 3), 256, TG_SMEM>>>(bq, bk);
    mask_prep_kernel<<<(BBs * LLs + 255) / 256, 256>>>(mask);
    bias_lut_kernel<<<(NCLS + 7) / 8, 256>>>(W1, b1, W2, b2);
    bias_gather_kernel<<<(LLs + 255) / 256, 256>>>(indices);
    attn3_kernel<<<dim3(Hs, BBs), 512, ATT3_SMEM>>>(scale);
    out_gemm_kernel<<<dim3(ROWSs / 128, Es / 128), 256, TG_SMEM>>>(bw, out);
}

// round 14
// speedup vs baseline: 5.7930x; 1.1033x over previous
#include <cuda_runtime.h>
#include <cuda_fp16.h>
#include <math.h>
#include <float.h>
#include <stdint.h>

// Problem dims
#define BBs   128
#define Ls    343
#define Es    256
#define Hs    8
#define HDs   32
#define HIDs  512
#define LLs   (Ls * Ls)       // 117649
#define ROWSs (BBs * Ls)      // 43904
#define LPAD  344
#define NCLS  2197            // 13^3 distinct index triples
#define MW    12              // mask words per row (384 bits)

// -------- scratch (device globals; no allocation allowed) --------
__device__ float g_bias[Hs * Ls * LPAD];
__device__ __align__(16) float g_blut[NCLS * 8];
__device__ int   g_mask_mode;
__device__ uint32_t g_maskb[BBs * 344 * MW];   // bit-packed mask
__device__ __half g_xq[ROWSs * Es], g_xk[ROWSs * Es], g_xv[ROWSs * Es];
__device__ __half g_a[ROWSs * Es];
__device__ __half g_w4[4 * Es * Es];
__device__ __half g_qh[BBs * Hs * Ls * HDs];
__device__ __half g_kh[BBs * Hs * Ls * HDs];
__device__ __half g_vh[BBs * Hs * Ls * HDs];

// ============================================================
// PTX helpers (baseline sm_80+ ISA; harness targets sm_103 w/o 'a')
// ============================================================
__device__ __forceinline__ uint32_t smem_u32(const void* p) {
    uint32_t a;
    asm("{ .reg .u64 t; cvta.to.shared.u64 t, %1; cvt.u32.u64 %0, t; }" : "=r"(a) : "l"(p));
    return a;
}
__device__ __forceinline__ void ldsm_x4(uint32_t& r0, uint32_t& r1, uint32_t& r2,
                                        uint32_t& r3, uint32_t addr) {
    asm volatile("ldmatrix.sync.aligned.m8n8.x4.shared.b16 {%0,%1,%2,%3}, [%4];"
                 : "=r"(r0), "=r"(r1), "=r"(r2), "=r"(r3) : "r"(addr));
}
__device__ __forceinline__ void ldsm_x4_t(uint32_t& r0, uint32_t& r1, uint32_t& r2,
                                          uint32_t& r3, uint32_t addr) {
    asm volatile("ldmatrix.sync.aligned.m8n8.x4.trans.shared.b16 {%0,%1,%2,%3}, [%4];"
                 : "=r"(r0), "=r"(r1), "=r"(r2), "=r"(r3) : "r"(addr));
}
__device__ __forceinline__ void mma16816(float* c, const uint32_t* a,
                                         uint32_t b0, uint32_t b1) {
    asm volatile(
        "mma.sync.aligned.m16n8k16.row.col.f32.f16.f16.f32 "
        "{%0,%1,%2,%3}, {%4,%5,%6,%7}, {%8,%9}, {%0,%1,%2,%3};"
        : "+f"(c[0]), "+f"(c[1]), "+f"(c[2]), "+f"(c[3])
        : "r"(a[0]), "r"(a[1]), "r"(a[2]), "r"(a[3]), "r"(b0), "r"(b1));
}
__device__ __forceinline__ void cp_async16(uint32_t dst, const void* src) {
    asm volatile("cp.async.cg.shared.global [%0], [%1], 16;" :: "r"(dst), "l"(src));
}
__device__ __forceinline__ void cp_commit() { asm volatile("cp.async.commit_group;"); }
__device__ __forceinline__ void cp_wait1() { asm volatile("cp.async.wait_group 1;"); }
__device__ __forceinline__ void cp_wait0() { asm volatile("cp.async.wait_group 0;"); }

__device__ __forceinline__ uint32_t packh(float a, float b) {
    __half2 t = __floats2half2_rn(a, b);
    return *(uint32_t*)&t;
}

// Fast exp on FMA/ALU pipes only (no MUFU). rel err ~2.4e-6.
__device__ __forceinline__ float fexp(float x) {
    float y = fmaxf(x * 1.4426950408889634f, -126.0f);
    float yr = __fadd_rn(y, 12582912.0f);
    float n  = __fsub_rn(yr, 12582912.0f);
    float f  = __fsub_rn(y, n);
    float p  = 1.3333558e-3f;
    p = fmaf(p, f, 9.6181291e-3f);
    p = fmaf(p, f, 5.5504109e-2f);
    p = fmaf(p, f, 2.4022651e-1f);
    p = fmaf(p, f, 6.9314718e-1f);
    p = fmaf(p, f, 1.0f);
    return __int_as_float(__float_as_int(p) + (__float_as_int(yr) << 23));
}

// ============================================================
// Kernel: detect mask dtype
// ============================================================
__global__ void detect_mask_kernel(const unsigned int* __restrict__ m)
{
    __shared__ int s_float, s_multi;
    if (threadIdx.x == 0) { s_float = 0; s_multi = 0; }
    __syncthreads();
    for (int i = threadIdx.x; i < 4096; i += 256) {
        unsigned int w = m[i];
        if (w == 0x3F800000u) atomicOr(&s_float, 1);
        else if (w != 0u && (w & 0xFFFFFF00u) != 0u) atomicOr(&s_multi, 1);
    }
    __syncthreads();
    if (threadIdx.x == 0)
        g_mask_mode = s_float ? 2 : (s_multi ? 0 : 1);
}

// ============================================================
// Kernel: pack mask into bit table (bb, row, 12 words of 32 cols)
// ============================================================
__global__ __launch_bounds__(256) void mask_prep_kernel(const void* __restrict__ maskp)
{
    int idx = blockIdx.x * 256 + threadIdx.x;
    if (idx >= BBs * Ls * MW) return;
    int w = idx % MW;
    int t = idx / MW;
    int row = t % Ls;
    int bb = t / Ls;
    const int mode = g_mask_mode;
    const size_t rbase = (size_t)bb * LLs + (size_t)row * Ls;
    uint32_t bits = 0;
    int c0 = w * 32;
    int cend = min(32, Ls - c0);
    if (mode == 0) {
        const uint8_t* p = (const uint8_t*)maskp + rbase + c0;
        for (int b = 0; b < cend; b++) if (p[b]) bits |= (1u << b);
    } else if (mode == 1) {
        const int* p = (const int*)maskp + rbase + c0;
        for (int b = 0; b < cend; b++) if (p[b]) bits |= (1u << b);
    } else {
        const float* p = (const float*)maskp + rbase + c0;
        for (int b = 0; b < cend; b++) if (p[b] != 0.0f) bits |= (1u << b);
    }
    g_maskb[((size_t)bb * 344 + row) * MW + w] = bits;
}

// ============================================================
// Kernel: CPB LUT — one warp per distinct index-triple class.
// ============================================================
__global__ __launch_bounds__(256) void bias_lut_kernel(
    const float* __restrict__ W1, const float* __restrict__ b1,
    const float* __restrict__ W2, const float* __restrict__ b2)
{
    int wid = threadIdx.x >> 5, lane = threadIdx.x & 31;
    int cls = blockIdx.x * 8 + wid;
    if (cls >= NCLS) return;
    int d0 = cls % 13 - 6;
    int d1 = (cls / 13) % 13 - 6;
    int d2 = cls / 169 - 6;
    float x0 = copysignf(log2f(1.0f + fabsf((float)d0)) * (1.0f / 3.0f), (float)d0);
    float x1 = copysignf(log2f(1.0f + fabsf((float)d1)) * (1.0f / 3.0f), (float)d1);
    float x2 = copysignf(log2f(1.0f + fabsf((float)d2)) * (1.0f / 3.0f), (float)d2);
    float acc[8];
#pragma unroll
    for (int h = 0; h < 8; h++) acc[h] = 0.0f;
    for (int t = lane; t < HIDs; t += 32) {
        float hv = fmaxf(fmaf(x0, W1[t], fmaf(x1, W1[HIDs + t],
                        fmaf(x2, W1[2 * HIDs + t], b1[t]))), 0.0f);
#pragma unroll
        for (int h = 0; h < 8; h++) acc[h] = fmaf(hv, W2[t * 8 + h], acc[h]);
    }
#pragma unroll
    for (int h = 0; h < 8; h++) {
#pragma unroll
        for (int o = 16; o > 0; o >>= 1)
            acc[h] += __shfl_xor_sync(0xffffffffu, acc[h], o);
    }
    if (lane == 0) {
#pragma unroll
        for (int h = 0; h < 8; h++) {
            float z = acc[h] + b2[h];
            g_blut[cls * 8 + h] = 16.0f / (1.0f + fexp(-z));
        }
    }
}

// ============================================================
// Kernel: gather LUT -> padded bias planes
// ============================================================
__global__ __launch_bounds__(256) void bias_gather_kernel(
    const float* __restrict__ indices)
{
    int p = blockIdx.x * 256 + threadIdx.x;
    if (p >= LLs) return;
    int i = p / Ls, j = p - i * Ls;
    int q0 = __float2int_rn(indices[p * 3 + 0]) + 6;
    int q1 = __float2int_rn(indices[p * 3 + 1]) + 6;
    int q2 = __float2int_rn(indices[p * 3 + 2]) + 6;
    int cls = q0 + 13 * q1 + 169 * q2;
    float4 v0 = *(const float4*)(g_blut + cls * 8);
    float4 v1 = *(const float4*)(g_blut + cls * 8 + 4);
    float vals[8] = { v0.x, v0.y, v0.z, v0.w, v1.x, v1.y, v1.z, v1.w };
#pragma unroll
    for (int h = 0; h < 8; h++)
        g_bias[(size_t)h * (Ls * LPAD) + i * LPAD + j] = vals[h];
}

// ============================================================
// Kernel: round all 3 fp32 inputs -> single fp16 (batched, grid.y=3)
// ============================================================
__global__ __launch_bounds__(256) void split3_kernel(
    const float4* __restrict__ q, const float4* __restrict__ k,
    const float4* __restrict__ v, int n4)
{
    const int z = blockIdx.y;
    const float4* in = (z == 0) ? q : (z == 1) ? k : v;
    __half* dst = (z == 0) ? g_xq : (z == 1) ? g_xk : g_xv;
    int i = blockIdx.x * 256 + threadIdx.x;
    if (i >= n4) return;
    float4 val = in[i];
    uint2 o = make_uint2(packh(val.x, val.y), packh(val.z, val.w));
    *(uint2*)(dst + (size_t)i * 4) = o;
}

// ============================================================
// Kernel: all 4 weight transposes -> fp16 (grid.z=4)
// ============================================================
__global__ __launch_bounds__(256) void wsplit_all_kernel(
    const float* __restrict__ Wq, const float* __restrict__ Wk,
    const float* __restrict__ Wv, const float* __restrict__ Ww)
{
    __shared__ float t[32][33];
    const int z = blockIdx.z;
    const float* W = (z == 0) ? Wq : (z == 1) ? Wk : (z == 2) ? Wv : Ww;
    __half* ht = g_w4 + (size_t)z * Es * Es;
    int bn = blockIdx.x * 32, bk = blockIdx.y * 32;
    int lx = threadIdx.x & 31, ly = threadIdx.x >> 5;
    for (int yy = ly; yy < 32; yy += 8)
        t[yy][lx] = W[(size_t)(bk + yy) * Es + bn + lx];
    __syncthreads();
    for (int yy = ly; yy < 32; yy += 8)
        ht[(size_t)(bn + yy) * Es + bk + lx] = __float2half_rn(t[lx][yy]);
}

// ============================================================
// Shared fp16 GEMM body: C = A*W, fp32 accum.
// ============================================================
#define TGS 72
#define TGBUF 18432
#define TGSTAGE (2 * TGBUF)
#define TG_SMEM (3 * TGSTAGE)         // 110592 B -> 2 CTAs/SM

__device__ __forceinline__ void tgemm_body(
    char* dsm,
    const __half* __restrict__ A, const __half* __restrict__ W,
    const float* __restrict__ bias, float* __restrict__ C, int remap,
    __half* __restrict__ Oh, int donorm)
{
    const int tid = threadIdx.x;
    const int wid = tid >> 5;
    const int lane = tid & 31;
    const int m0 = blockIdx.x * 128;
    const int n0 = blockIdx.y * 128;
    const int wm = wid & 1;
    const int wn = wid >> 1;
    const uint32_t smb = smem_u32(dsm);

    float c[4][4][4];
#pragma unroll
    for (int i = 0; i < 4; i++)
#pragma unroll
        for (int j = 0; j < 4; j++)
#pragma unroll
            for (int k = 0; k < 4; k++) c[i][j][k] = 0.0f;

    auto prefetch = [&](int i) {
        const int s = i % 3;
        const int k0 = i * 64;
        const uint32_t bA = smb + s * TGSTAGE;
        const uint32_t bB = bA + TGBUF;
#pragma unroll
        for (int j = 0; j < 4; j++) {
            int x = tid + j * 256;
            int r = x >> 3, cc = x & 7;
            uint32_t off = (uint32_t)(r * TGS + cc * 8) * 2;
            cp_async16(bA + off, A + (size_t)(m0 + r) * Es + k0 + cc * 8);
            cp_async16(bB + off, W + (size_t)(n0 + r) * Es + k0 + cc * 8);
        }
    };

    prefetch(0); cp_commit();
    prefetch(1); cp_commit();

    const int arow = (lane & 7) + ((lane >> 3) & 1) * 8;
    const int acolo = ((lane >> 4) & 1) * 8;
    const int brow = (lane & 7) + ((lane >> 4) & 1) * 8;
    const int bcolo = ((lane >> 3) & 1) * 8;

    for (int i = 0; i < 4; i++) {
        if (i < 3) cp_wait1(); else cp_wait0();
        __syncthreads();
        if (i < 2) { prefetch(i + 2); cp_commit(); }

        const uint32_t bA = smb + (i % 3) * TGSTAGE;
        const uint32_t bB = bA + TGBUF;
#pragma unroll
        for (int ks = 0; ks < 4; ks++) {
            const int k0 = ks * 16;
            uint32_t a[4][4], b[2][4];
#pragma unroll
            for (int mt = 0; mt < 4; mt++)
                ldsm_x4(a[mt][0], a[mt][1], a[mt][2], a[mt][3],
                        bA + (uint32_t)((wm * 64 + mt * 16 + arow) * TGS + k0 + acolo) * 2);
#pragma unroll
            for (int g = 0; g < 2; g++)
                ldsm_x4(b[g][0], b[g][1], b[g][2], b[g][3],
                        bB + (uint32_t)((wn * 32 + g * 16 + brow) * TGS + k0 + bcolo) * 2);
#pragma unroll
            for (int mt = 0; mt < 4; mt++)
#pragma unroll
                for (int nt = 0; nt < 4; nt++)
                    mma16816(c[mt][nt], a[mt], b[nt >> 1][(nt & 1) * 2],
                             b[nt >> 1][(nt & 1) * 2 + 1]);
        }
    }

    const int tq = lane >> 2;
    const int tr = lane & 3;
#pragma unroll
    for (int mt = 0; mt < 4; mt++) {
        const int m = m0 + wm * 64 + mt * 16 + tq;
        float v0x[4], v0y[4], v1x[4], v1y[4];
#pragma unroll
        for (int nt = 0; nt < 4; nt++) {
            const int n = n0 + wn * 32 + nt * 8 + tr * 2;
            float bx = 0.0f, by = 0.0f;
            if (bias) { float2 bv = *(const float2*)(bias + n); bx = bv.x; by = bv.y; }
            v0x[nt] = c[mt][nt][0] + bx; v0y[nt] = c[mt][nt][1] + by;
            v1x[nt] = c[mt][nt][2] + bx; v1y[nt] = c[mt][nt][3] + by;
        }
        if (donorm) {
            float ss0 = 0.0f, ss1 = 0.0f;
#pragma unroll
            for (int nt = 0; nt < 4; nt++) {
                ss0 = fmaf(v0x[nt], v0x[nt], fmaf(v0y[nt], v0y[nt], ss0));
                ss1 = fmaf(v1x[nt], v1x[nt], fmaf(v1y[nt], v1y[nt], ss1));
            }
            ss0 += __shfl_xor_sync(0xffffffffu, ss0, 1);
            ss0 += __shfl_xor_sync(0xffffffffu, ss0, 2);
            ss1 += __shfl_xor_sync(0xffffffffu, ss1, 1);
            ss1 += __shfl_xor_sync(0xffffffffu, ss1, 2);
            float i0 = 1.0f / fmaxf(sqrtf(ss0), 1e-12f);
            float i1 = 1.0f / fmaxf(sqrtf(ss1), 1e-12f);
#pragma unroll
            for (int nt = 0; nt < 4; nt++) {
                v0x[nt] *= i0; v0y[nt] *= i0;
                v1x[nt] *= i1; v1y[nt] *= i1;
            }
        }
#pragma unroll
        for (int nt = 0; nt < 4; nt++) {
            const int n = n0 + wn * 32 + nt * 8 + tr * 2;
            size_t a0, a1;
            if (remap) {
                const int hh = n >> 5, hd = n & 31;
                int bbw = m / Ls, l = m - bbw * Ls;
                a0 = ((size_t)(bbw * Hs + hh) * Ls + l) * HDs + hd;
                int m2 = m + 8;
                int bbw2 = m2 / Ls, l2 = m2 - bbw2 * Ls;
                a1 = ((size_t)(bbw2 * Hs + hh) * Ls + l2) * HDs + hd;
            } else {
                a0 = (size_t)m * Es + n;
                a1 = (size_t)(m + 8) * Es + n;
            }
            if (Oh) {
                *(uint32_t*)(Oh + a0) = packh(v0x[nt], v0y[nt]);
                *(uint32_t*)(Oh + a1) = packh(v1x[nt], v1y[nt]);
            } else {
                *(float2*)(C + a0) = make_float2(v0x[nt], v0y[nt]);
                *(float2*)(C + a1) = make_float2(v1x[nt], v1y[nt]);
            }
        }
    }
}

// Q/K/V projections in ONE launch (grid.z selects operand set)
__global__ __launch_bounds__(256, 2) void qkv_gemm_kernel(
    const float* __restrict__ bq, const float* __restrict__ bk)
{
    extern __shared__ char dsm[];
    const int z = blockIdx.z;
    const __half* A  = (z == 0) ? g_xq : (z == 1) ? g_xk : g_xv;
    const __half* W  = g_w4 + (size_t)z * Es * Es;
    const float* bias = (z == 0) ? bq : (z == 1) ? bk : nullptr;
    __half* Oh = (z == 0) ? g_qh : (z == 1) ? g_kh : g_vh;
    tgemm_body(dsm, A, W, bias, nullptr, 1, Oh, z < 2);
}

// output projection -> fp32 d_out
__global__ __launch_bounds__(256, 2) void out_gemm_kernel(
    const float* __restrict__ bw, float* __restrict__ out)
{
    extern __shared__ char dsm[];
    tgemm_body(dsm, g_a, g_w4 + 3 * (size_t)Es * Es, bw, out, 0, nullptr, 0);
}

// ============================================================
// Kernel: persistent fp16 attention per (head, window).
// Bit-packed mask: 3 words per row per quarter.
// ============================================================
#define ASTR 40
#define ABUF 30720
#define OFF_QH (0 * ABUF)
#define OFF_KH (1 * ABUF)
#define OFF_VH (2 * ABUF)
#define OFF_RMAX (3 * ABUF)
#define OFF_RSUM (OFF_RMAX + 1024)
#define OFF_ORED (OFF_RSUM + 1024)
#define ORSTR 34
#define ATT3_SMEM (OFF_ORED + 4 * 64 * ORSTR * 4)   // 129024

__global__ __launch_bounds__(512) void attn3_kernel(const float* __restrict__ scalep)
{
    extern __shared__ char sm2[];
    float* redmax = (float*)(sm2 + OFF_RMAX);
    float* redsum = (float*)(sm2 + OFF_RSUM);
    float* ored   = (float*)(sm2 + OFF_ORED);
    const uint32_t smb = smem_u32(sm2);

    const int tid = threadIdx.x;
    const int wid = tid >> 5;
    const int lane = tid & 31;
    const int h = blockIdx.x;
    const int bb = blockIdx.y;
    const size_t gbase = (size_t)(bb * Hs + h) * (Ls * HDs);

    // ---- fill Q,K,V once ----
    {
        const __half* gsrc[3] = { g_qh + gbase, g_kh + gbase, g_vh + gbase };
#pragma unroll
        for (int arr = 0; arr < 3; arr++)
            for (int i = tid; i < 1372; i += 512) {
                int row = i >> 2, ch = i & 3;
                cp_async16(smb + arr * ABUF + row * 80 + ch * 16,
                           gsrc[arr] + row * HDs + ch * 8);
            }
        for (int i = tid; i < 492; i += 512) {
            int arr = i / 164, j = i - arr * 164;
            int r = 343 + (j >> 2), ch = j & 3;
            *(uint4*)(sm2 + arr * ABUF + r * 80 + ch * 16) = make_uint4(0, 0, 0, 0);
        }
        cp_commit();
        cp_wait0();
        __syncthreads();
    }

    const int wm = wid & 3;
    const int wn = wid >> 2;
    const int nbase = wn * 96;

    const int arow = (lane & 7) + ((lane >> 3) & 1) * 8;
    const int acolo = ((lane >> 4) & 1) * 8;
    const int brow = (lane & 7) + ((lane >> 4) & 1) * 8;
    const int bcolo = ((lane >> 3) & 1) * 8;

    const float invscale = 1.0f / fmaxf(scalep[0], 0.01f);
    const float* bias0 = g_bias + (size_t)h * (Ls * LPAD);
    const uint32_t* mrowb = g_maskb + (size_t)bb * (344 * MW) + wn * 3;
    const int r0 = wm * 16 + (lane >> 2);
    const int r1 = r0 + 8;
    const int ncol = (lane & 3) * 2;
    const int lane16 = lane & 15;
    const int halfr = lane >> 4;

    for (int qt = 0; qt < 6; qt++) {
        const int q0 = qt * 64;
        const int qrow0 = q0 + r0, qrow1 = q0 + r1;
        const bool rv0 = qrow0 < Ls, rv1 = qrow1 < Ls;

        // ---- mask words for this quarter's 96 cols (3 per row) ----
        uint32_t mw0[3] = {0, 0, 0}, mw1[3] = {0, 0, 0};
        if (rv0) {
            const uint32_t* p = mrowb + (size_t)qrow0 * MW;
            mw0[0] = p[0]; mw0[1] = p[1]; mw0[2] = p[2];
        }
        if (rv1) {
            const uint32_t* p = mrowb + (size_t)qrow1 * MW;
            mw1[0] = p[0]; mw1[1] = p[1]; mw1[2] = p[2];
        }

        // ---- Q fragments ----
        uint32_t qh[2][4];
#pragma unroll
        for (int kk = 0; kk < 2; kk++) {
            uint32_t ro = (uint32_t)((q0 + wm * 16 + arow) * ASTR + kk * 16 + acolo) * 2;
            ldsm_x4(qh[kk][0], qh[kk][1], qh[kk][2], qh[kk][3], smb + OFF_QH + ro);
        }

        // ---- fused phase 1: per g, LDG bias early; mma; epilogue ----
        float c[12][4];
        float mx0 = -FLT_MAX, mx1 = -FLT_MAX;
#pragma unroll
        for (int g = 0; g < 6; g++) {
            float2 bT[2][2];
#pragma unroll
            for (int nt = 0; nt < 2; nt++) {
                int col = nbase + g * 16 + nt * 8 + ncol;
                bool cv = col < Ls;
                bT[nt][0] = make_float2(0.f, 0.f); bT[nt][1] = make_float2(0.f, 0.f);
                if (rv0 && cv)
                    bT[nt][0] = *(const float2*)(bias0 + (size_t)qrow0 * LPAD + col);
                if (rv1 && cv)
                    bT[nt][1] = *(const float2*)(bias0 + (size_t)qrow1 * LPAD + col);
            }

            uint32_t bh[2][4];
#pragma unroll
            for (int kk = 0; kk < 2; kk++) {
                uint32_t rb = (uint32_t)((nbase + g * 16 + brow) * ASTR + kk * 16 + bcolo) * 2;
                ldsm_x4(bh[kk][0], bh[kk][1], bh[kk][2], bh[kk][3], smb + OFF_KH + rb);
            }
            float cg[2][4];
#pragma unroll
            for (int nt = 0; nt < 2; nt++)
#pragma unroll
                for (int e = 0; e < 4; e++) cg[nt][e] = 0.0f;
#pragma unroll
            for (int kk = 0; kk < 2; kk++)
#pragma unroll
                for (int nt = 0; nt < 2; nt++)
                    mma16816(cg[nt], qh[kk], bh[kk][nt * 2], bh[kk][nt * 2 + 1]);
#pragma unroll
            for (int nt = 0; nt < 2; nt++) {
                const int t = g * 2 + nt;
                const int base = g * 16 + nt * 8;         // 0..88, 8-aligned
                const int wI = base >> 5;                 // compile-time 0..2
                int col = nbase + base + ncol;
                bool cv0 = col < Ls, cv1 = (col + 1) < Ls;
                uint32_t mb0 = (mw0[wI] >> ((base & 31) + ncol)) & 3u;
                uint32_t mb1 = (mw1[wI] >> ((base & 31) + ncol)) & 3u;
                c[t][0] = (rv0 && cv0) ? ((mb0 & 1u) ? -100000.0f
                          : fmaf(cg[nt][0], invscale, bT[nt][0].x)) : -1e9f;
                c[t][1] = (rv0 && cv1) ? ((mb0 & 2u) ? -100000.0f
                          : fmaf(cg[nt][1], invscale, bT[nt][0].y)) : -1e9f;
                c[t][2] = (rv1 && cv0) ? ((mb1 & 1u) ? -100000.0f
                          : fmaf(cg[nt][2], invscale, bT[nt][1].x)) : -1e9f;
                c[t][3] = (rv1 && cv1) ? ((mb1 & 2u) ? -100000.0f
                          : fmaf(cg[nt][3], invscale, bT[nt][1].y)) : -1e9f;
                mx0 = fmaxf(mx0, fmaxf(c[t][0], c[t][1]));
                mx1 = fmaxf(mx1, fmaxf(c[t][2], c[t][3]));
            }
        }

        // ---- single-sync softmax; normalization deferred to post-PV ----
        mx0 = fmaxf(mx0, __shfl_xor_sync(0xffffffffu, mx0, 1));
        mx0 = fmaxf(mx0, __shfl_xor_sync(0xffffffffu, mx0, 2));
        mx1 = fmaxf(mx1, __shfl_xor_sync(0xffffffffu, mx1, 1));
        mx1 = fmaxf(mx1, __shfl_xor_sync(0xffffffffu, mx1, 2));

        float s0 = 0.0f, s1 = 0.0f;
#pragma unroll
        for (int t = 0; t < 12; t++) {
            float e0 = fexp(c[t][0] - mx0); c[t][0] = e0; s0 += e0;
            float e1 = fexp(c[t][1] - mx0); c[t][1] = e1; s0 += e1;
            float e2 = fexp(c[t][2] - mx1); c[t][2] = e2; s1 += e2;
            float e3 = fexp(c[t][3] - mx1); c[t][3] = e3; s1 += e3;
        }
        s0 += __shfl_xor_sync(0xffffffffu, s0, 1);
        s0 += __shfl_xor_sync(0xffffffffu, s0, 2);
        s1 += __shfl_xor_sync(0xffffffffu, s1, 1);
        s1 += __shfl_xor_sync(0xffffffffu, s1, 2);
        if ((lane & 3) == 0) {
            redmax[wn * 64 + r0] = mx0; redsum[wn * 64 + r0] = s0;
            redmax[wn * 64 + r1] = mx1; redsum[wn * 64 + r1] = s1;
        }
        __syncthreads();
        float f0, f1;
        {
            float gm0 = -FLT_MAX, gm1 = -FLT_MAX;
#pragma unroll
            for (int qd = 0; qd < 4; qd++) {
                gm0 = fmaxf(gm0, redmax[qd * 64 + r0]);
                gm1 = fmaxf(gm1, redmax[qd * 64 + r1]);
            }
            float S0 = 0.0f, S1 = 0.0f;
#pragma unroll
            for (int qd = 0; qd < 4; qd++) {
                S0 += redsum[qd * 64 + r0] * fexp(redmax[qd * 64 + r0] - gm0);
                S1 += redsum[qd * 64 + r1] * fexp(redmax[qd * 64 + r1] - gm1);
            }
            f0 = fexp(mx0 - gm0) / S0;
            f1 = fexp(mx1 - gm1) / S1;
        }

        // ---- phase 3: O = P * V, then scale by f ----
        float oc[4][4];
#pragma unroll
        for (int nt = 0; nt < 4; nt++)
#pragma unroll
            for (int e = 0; e < 4; e++) oc[nt][e] = 0.0f;

#pragma unroll
        for (int kt = 0; kt < 6; kt++) {
            uint32_t ph[4];
#pragma unroll
            for (int half = 0; half < 2; half++) {
                const float* cc = c[2 * kt + half];
                ph[half * 2 + 0] = packh(cc[0], cc[1]);
                ph[half * 2 + 1] = packh(cc[2], cc[3]);
            }
            const int krow = nbase + kt * 16;
            uint32_t vh[2][4];
#pragma unroll
            for (int g = 0; g < 2; g++) {
                uint32_t ad = (uint32_t)((krow + arow) * ASTR + g * 16 + acolo) * 2;
                ldsm_x4_t(vh[g][0], vh[g][1], vh[g][2], vh[g][3], smb + OFF_VH + ad);
            }
#pragma unroll
            for (int nt = 0; nt < 4; nt++) {
                const int g = nt >> 1, i2 = (nt & 1) * 2;
                mma16816(oc[nt], ph, vh[g][i2], vh[g][i2 + 1]);
            }
        }
#pragma unroll
        for (int nt = 0; nt < 4; nt++) {
            oc[nt][0] *= f0; oc[nt][1] *= f0;
            oc[nt][2] *= f1; oc[nt][3] *= f1;
        }

        // ---- all quarters write slabs; distributed reduce + fp16 store ----
        {
            float* dst = ored + (size_t)wn * (64 * ORSTR);
#pragma unroll
            for (int nt = 0; nt < 4; nt++) {
                *(float2*)(dst + r0 * ORSTR + nt * 8 + ncol) = make_float2(oc[nt][0], oc[nt][1]);
                *(float2*)(dst + r1 * ORSTR + nt * 8 + ncol) = make_float2(oc[nt][2], oc[nt][3]);
            }
        }
        __syncthreads();
#pragma unroll
        for (int p = 0; p < 2; p++) {
            int row = wid * 4 + p * 2 + halfr;
            int qrow = q0 + row;
            if (qrow < Ls) {
                int col = lane16 * 2;
                float s0o = 0.0f, s1o = 0.0f;
#pragma unroll
                for (int qd = 0; qd < 4; qd++) {
                    float2 v = *(float2*)(ored + qd * (64 * ORSTR) + row * ORSTR + col);
                    s0o += v.x; s1o += v.y;
                }
                size_t ad = (size_t)(bb * Ls + qrow) * Es + h * HDs + col;
                *(uint32_t*)(g_a + ad) = packh(s0o, s1o);
            }
        }
    }
}

// ============================================================
// launch
// ============================================================
extern "C" void kernel_launch(void* const* d_in, const int* in_sizes, int n_in,
                              void* d_out, int out_size)
{
    (void)in_sizes; (void)n_in; (void)out_size;
    const float* query   = (const float*)d_in[0];
    const float* key     = (const float*)d_in[1];
    const float* value   = (const float*)d_in[2];
    const float* indices = (const float*)d_in[3];
    const void*  mask    = d_in[4];
    const float* Wq      = (const float*)d_in[5];
    const float* bq      = (const float*)d_in[6];
    const float* Wk      = (const float*)d_in[7];
    const float* bk      = (const float*)d_in[8];
    const float* Wv      = (const float*)d_in[9];
    const float* Ww      = (const float*)d_in[10];
    const float* bw      = (const float*)d_in[11];
    const float* scale   = (const float*)d_in[12];
    const float* W1      = (const float*)d_in[13];
    const float* b1      = (const float*)d_in[14];
    const float* W2      = (const float*)d_in[15];
    const float* b2      = (const float*)d_in[16];
    float* out = (float*)d_out;

    cudaFuncSetAttribute(qkv_gemm_kernel, cudaFuncAttributeMaxDynamicSharedMemorySize,
                         TG_SMEM);
    cudaFuncSetAttribute(out_gemm_kernel, cudaFuncAttributeMaxDynamicSharedMemorySize,
                         TG_SMEM);
    cudaFuncSetAttribute(attn3_kernel, cudaFuncAttributeMaxDynamicSharedMemorySize,
                         ATT3_SMEM);

    const int n4 = ROWSs * Es / 4;
    const int splitg = (n4 + 255) / 256;

    wsplit_all_kernel<<<dim3(8, 8, 4), 256>>>(Wq, Wk, Wv, Ww);
    split3_kernel<<<dim3(splitg, 3), 256>>>((const float4*)query, (const float4*)key,
                                            (const float4*)value, n4);
    detect_mask_kernel<<<1, 256>>>((const unsigned int*)mask);
    // Q/K/V projections (+fused norm for Q,K) in ONE launch  (ncu slot)
    qkv_gemm_kernel<<<dim3(ROWSs / 128, Es / 128, 3), 256, TG_SMEM>>>(bq, bk);
    mask_prep_kernel<<<(BBs * Ls * MW + 255) / 256, 256>>>(mask);
    bias_lut_kernel<<<(NCLS + 7) / 8, 256>>>(W1, b1, W2, b2);
    bias_gather_kernel<<<(LLs + 255) / 256, 256>>>(indices);
    attn3_kernel<<<dim3(Hs, BBs), 512, ATT3_SMEM>>>(scale);
    out_gemm_kernel<<<dim3(ROWSs / 128, Es / 128), 256, TG_SMEM>>>(bw, out);
}

// round 15
// speedup vs baseline: 6.5753x; 1.1350x over previous
#include <cuda_runtime.h>
#include <cuda_fp16.h>
#include <math.h>
#include <float.h>
#include <stdint.h>

// Problem dims
#define BBs   128
#define Ls    343
#define Es    256
#define Hs    8
#define HDs   32
#define HIDs  512
#define LLs   (Ls * Ls)       // 117649
#define ROWSs (BBs * Ls)      // 43904
#define LPAD  344
#define NCLS  2197
#define MW    12
#define MASKG ((BBs * Ls * MW + 255) / 256)   // 2058

// -------- scratch (device globals; no allocation allowed) --------
__device__ float g_bias[Hs * Ls * LPAD];
__device__ __align__(16) float g_blut[NCLS * 8];
__device__ uint32_t g_maskb[BBs * 344 * MW];
__device__ __half g_xq[ROWSs * Es], g_xk[ROWSs * Es], g_xv[ROWSs * Es];
__device__ __half g_a[ROWSs * Es];
__device__ __half g_w4[4 * Es * Es];
__device__ __half g_qh[BBs * Hs * Ls * HDs];
__device__ __half g_kh[BBs * Hs * Ls * HDs];
__device__ __half g_vh[BBs * Hs * Ls * HDs];

// ============================================================
// PTX helpers
// ============================================================
__device__ __forceinline__ uint32_t smem_u32(const void* p) {
    uint32_t a;
    asm("{ .reg .u64 t; cvta.to.shared.u64 t, %1; cvt.u32.u64 %0, t; }" : "=r"(a) : "l"(p));
    return a;
}
__device__ __forceinline__ void ldsm_x4(uint32_t& r0, uint32_t& r1, uint32_t& r2,
                                        uint32_t& r3, uint32_t addr) {
    asm volatile("ldmatrix.sync.aligned.m8n8.x4.shared.b16 {%0,%1,%2,%3}, [%4];"
                 : "=r"(r0), "=r"(r1), "=r"(r2), "=r"(r3) : "r"(addr));
}
__device__ __forceinline__ void ldsm_x4_t(uint32_t& r0, uint32_t& r1, uint32_t& r2,
                                          uint32_t& r3, uint32_t addr) {
    asm volatile("ldmatrix.sync.aligned.m8n8.x4.trans.shared.b16 {%0,%1,%2,%3}, [%4];"
                 : "=r"(r0), "=r"(r1), "=r"(r2), "=r"(r3) : "r"(addr));
}
__device__ __forceinline__ void mma16816(float* c, const uint32_t* a,
                                         uint32_t b0, uint32_t b1) {
    asm volatile(
        "mma.sync.aligned.m16n8k16.row.col.f32.f16.f16.f32 "
        "{%0,%1,%2,%3}, {%4,%5,%6,%7}, {%8,%9}, {%0,%1,%2,%3};"
        : "+f"(c[0]), "+f"(c[1]), "+f"(c[2]), "+f"(c[3])
        : "r"(a[0]), "r"(a[1]), "r"(a[2]), "r"(a[3]), "r"(b0), "r"(b1));
}
__device__ __forceinline__ void cp_async16(uint32_t dst, const void* src) {
    asm volatile("cp.async.cg.shared.global [%0], [%1], 16;" :: "r"(dst), "l"(src));
}
__device__ __forceinline__ void cp_commit() { asm volatile("cp.async.commit_group;"); }
__device__ __forceinline__ void cp_wait1() { asm volatile("cp.async.wait_group 1;"); }
__device__ __forceinline__ void cp_wait0() { asm volatile("cp.async.wait_group 0;"); }

__device__ __forceinline__ uint32_t packh(float a, float b) {
    __half2 t = __floats2half2_rn(a, b);
    return *(uint32_t*)&t;
}

// Fast exp on FMA/ALU pipes only (no MUFU). rel err ~2.4e-6.
__device__ __forceinline__ float fexp(float x) {
    float y = fmaxf(x * 1.4426950408889634f, -126.0f);
    float yr = __fadd_rn(y, 12582912.0f);
    float n  = __fsub_rn(yr, 12582912.0f);
    float f  = __fsub_rn(y, n);
    float p  = 1.3333558e-3f;
    p = fmaf(p, f, 9.6181291e-3f);
    p = fmaf(p, f, 5.5504109e-2f);
    p = fmaf(p, f, 2.4022651e-1f);
    p = fmaf(p, f, 6.9314718e-1f);
    p = fmaf(p, f, 1.0f);
    return __int_as_float(__float_as_int(p) + (__float_as_int(yr) << 23));
}

// ============================================================
// Launch 1: inputs->fp16 (y=0..2) + weight transpose->fp16 (y=3)
// ============================================================
__global__ __launch_bounds__(256) void prep_kernel(
    const float4* __restrict__ q, const float4* __restrict__ k,
    const float4* __restrict__ v, int n4,
    const float* __restrict__ Wq, const float* __restrict__ Wk,
    const float* __restrict__ Wv, const float* __restrict__ Ww)
{
    __shared__ float t[32][33];
    if (blockIdx.y < 3) {
        const int z = blockIdx.y;
        const float4* in = (z == 0) ? q : (z == 1) ? k : v;
        __half* dst = (z == 0) ? g_xq : (z == 1) ? g_xk : g_xv;
        int i = blockIdx.x * 256 + threadIdx.x;
        if (i >= n4) return;
        float4 val = in[i];
        uint2 o = make_uint2(packh(val.x, val.y), packh(val.z, val.w));
        *(uint2*)(dst + (size_t)i * 4) = o;
    } else {
        if (blockIdx.x >= 256) return;
        int b = blockIdx.x;
        int z = b >> 6, rem = b & 63;
        int bn = (rem & 7) * 32, bk = (rem >> 3) * 32;
        const float* W = (z == 0) ? Wq : (z == 1) ? Wk : (z == 2) ? Wv : Ww;
        __half* ht = g_w4 + (size_t)z * Es * Es;
        int lx = threadIdx.x & 31, ly = threadIdx.x >> 5;
        for (int yy = ly; yy < 32; yy += 8)
            t[yy][lx] = W[(size_t)(bk + yy) * Es + bn + lx];
        __syncthreads();
        for (int yy = ly; yy < 32; yy += 8)
            ht[(size_t)(bn + yy) * Es + bk + lx] = __float2half_rn(t[lx][yy]);
    }
}

// ============================================================
// Launch 2: mask bit-pack (self-detected dtype) + CPB LUT
// ============================================================
__global__ __launch_bounds__(256) void mask_lut_kernel(
    const void* __restrict__ maskp,
    const float* __restrict__ W1, const float* __restrict__ b1,
    const float* __restrict__ W2, const float* __restrict__ b2)
{
    if (blockIdx.x < MASKG) {
        // self-detect dtype (deterministic; same result in every block)
        __shared__ int s_float, s_multi;
        if (threadIdx.x == 0) { s_float = 0; s_multi = 0; }
        __syncthreads();
        const unsigned int* m = (const unsigned int*)maskp;
        for (int i = threadIdx.x; i < 4096; i += 256) {
            unsigned int w = m[i];
            if (w == 0x3F800000u) atomicOr(&s_float, 1);
            else if (w != 0u && (w & 0xFFFFFF00u) != 0u) atomicOr(&s_multi, 1);
        }
        __syncthreads();
        const int mode = s_float ? 2 : (s_multi ? 0 : 1);

        int idx = blockIdx.x * 256 + threadIdx.x;
        if (idx >= BBs * Ls * MW) return;
        int w = idx % MW;
        int tt = idx / MW;
        int row = tt % Ls;
        int bb = tt / Ls;
        const size_t rbase = (size_t)bb * LLs + (size_t)row * Ls;
        uint32_t bits = 0;
        int c0 = w * 32;
        int cend = min(32, Ls - c0);
        if (mode == 0) {
            const uint8_t* p = (const uint8_t*)maskp + rbase + c0;
            for (int b = 0; b < cend; b++) if (p[b]) bits |= (1u << b);
        } else if (mode == 1) {
            const int* p = (const int*)maskp + rbase + c0;
            for (int b = 0; b < cend; b++) if (p[b]) bits |= (1u << b);
        } else {
            const float* p = (const float*)maskp + rbase + c0;
            for (int b = 0; b < cend; b++) if (p[b] != 0.0f) bits |= (1u << b);
        }
        g_maskb[((size_t)bb * 344 + row) * MW + w] = bits;
    } else {
        int wid = threadIdx.x >> 5, lane = threadIdx.x & 31;
        int cls = (blockIdx.x - MASKG) * 8 + wid;
        if (cls >= NCLS) return;
        int d0 = cls % 13 - 6;
        int d1 = (cls / 13) % 13 - 6;
        int d2 = cls / 169 - 6;
        float x0 = copysignf(log2f(1.0f + fabsf((float)d0)) * (1.0f / 3.0f), (float)d0);
        float x1 = copysignf(log2f(1.0f + fabsf((float)d1)) * (1.0f / 3.0f), (float)d1);
        float x2 = copysignf(log2f(1.0f + fabsf((float)d2)) * (1.0f / 3.0f), (float)d2);
        float acc[8];
#pragma unroll
        for (int h = 0; h < 8; h++) acc[h] = 0.0f;
        for (int t = lane; t < HIDs; t += 32) {
            float hv = fmaxf(fmaf(x0, W1[t], fmaf(x1, W1[HIDs + t],
                            fmaf(x2, W1[2 * HIDs + t], b1[t]))), 0.0f);
#pragma unroll
            for (int h = 0; h < 8; h++) acc[h] = fmaf(hv, W2[t * 8 + h], acc[h]);
        }
#pragma unroll
        for (int h = 0; h < 8; h++) {
#pragma unroll
            for (int o = 16; o > 0; o >>= 1)
                acc[h] += __shfl_xor_sync(0xffffffffu, acc[h], o);
        }
        if (lane == 0) {
#pragma unroll
            for (int h = 0; h < 8; h++) {
                float z = acc[h] + b2[h];
                g_blut[cls * 8 + h] = 16.0f / (1.0f + fexp(-z));
            }
        }
    }
}

// ============================================================
// Shared fp16 GEMM body
// ============================================================
#define TGS 72
#define TGBUF 18432
#define TGSTAGE (2 * TGBUF)
#define TG_SMEM (3 * TGSTAGE)

__device__ __forceinline__ void tgemm_body(
    char* dsm,
    const __half* __restrict__ A, const __half* __restrict__ W,
    const float* __restrict__ bias, float* __restrict__ C, int remap,
    __half* __restrict__ Oh, int donorm)
{
    const int tid = threadIdx.x;
    const int wid = tid >> 5;
    const int lane = tid & 31;
    const int m0 = blockIdx.x * 128;
    const int n0 = blockIdx.y * 128;
    const int wm = wid & 1;
    const int wn = wid >> 1;
    const uint32_t smb = smem_u32(dsm);

    float c[4][4][4];
#pragma unroll
    for (int i = 0; i < 4; i++)
#pragma unroll
        for (int j = 0; j < 4; j++)
#pragma unroll
            for (int k = 0; k < 4; k++) c[i][j][k] = 0.0f;

    auto prefetch = [&](int i) {
        const int s = i % 3;
        const int k0 = i * 64;
        const uint32_t bA = smb + s * TGSTAGE;
        const uint32_t bB = bA + TGBUF;
#pragma unroll
        for (int j = 0; j < 4; j++) {
            int x = tid + j * 256;
            int r = x >> 3, cc = x & 7;
            uint32_t off = (uint32_t)(r * TGS + cc * 8) * 2;
            cp_async16(bA + off, A + (size_t)(m0 + r) * Es + k0 + cc * 8);
            cp_async16(bB + off, W + (size_t)(n0 + r) * Es + k0 + cc * 8);
        }
    };

    prefetch(0); cp_commit();
    prefetch(1); cp_commit();

    const int arow = (lane & 7) + ((lane >> 3) & 1) * 8;
    const int acolo = ((lane >> 4) & 1) * 8;
    const int brow = (lane & 7) + ((lane >> 4) & 1) * 8;
    const int bcolo = ((lane >> 3) & 1) * 8;

    for (int i = 0; i < 4; i++) {
        if (i < 3) cp_wait1(); else cp_wait0();
        __syncthreads();
        if (i < 2) { prefetch(i + 2); cp_commit(); }

        const uint32_t bA = smb + (i % 3) * TGSTAGE;
        const uint32_t bB = bA + TGBUF;
#pragma unroll
        for (int ks = 0; ks < 4; ks++) {
            const int k0 = ks * 16;
            uint32_t a[4][4], b[2][4];
#pragma unroll
            for (int mt = 0; mt < 4; mt++)
                ldsm_x4(a[mt][0], a[mt][1], a[mt][2], a[mt][3],
                        bA + (uint32_t)((wm * 64 + mt * 16 + arow) * TGS + k0 + acolo) * 2);
#pragma unroll
            for (int g = 0; g < 2; g++)
                ldsm_x4(b[g][0], b[g][1], b[g][2], b[g][3],
                        bB + (uint32_t)((wn * 32 + g * 16 + brow) * TGS + k0 + bcolo) * 2);
#pragma unroll
            for (int mt = 0; mt < 4; mt++)
#pragma unroll
                for (int nt = 0; nt < 4; nt++)
                    mma16816(c[mt][nt], a[mt], b[nt >> 1][(nt & 1) * 2],
                             b[nt >> 1][(nt & 1) * 2 + 1]);
        }
    }

    const int tq = lane >> 2;
    const int tr = lane & 3;
#pragma unroll
    for (int mt = 0; mt < 4; mt++) {
        const int m = m0 + wm * 64 + mt * 16 + tq;
        float v0x[4], v0y[4], v1x[4], v1y[4];
#pragma unroll
        for (int nt = 0; nt < 4; nt++) {
            const int n = n0 + wn * 32 + nt * 8 + tr * 2;
            float bx = 0.0f, by = 0.0f;
            if (bias) { float2 bv = *(const float2*)(bias + n); bx = bv.x; by = bv.y; }
            v0x[nt] = c[mt][nt][0] + bx; v0y[nt] = c[mt][nt][1] + by;
            v1x[nt] = c[mt][nt][2] + bx; v1y[nt] = c[mt][nt][3] + by;
        }
        if (donorm) {
            float ss0 = 0.0f, ss1 = 0.0f;
#pragma unroll
            for (int nt = 0; nt < 4; nt++) {
                ss0 = fmaf(v0x[nt], v0x[nt], fmaf(v0y[nt], v0y[nt], ss0));
                ss1 = fmaf(v1x[nt], v1x[nt], fmaf(v1y[nt], v1y[nt], ss1));
            }
            ss0 += __shfl_xor_sync(0xffffffffu, ss0, 1);
            ss0 += __shfl_xor_sync(0xffffffffu, ss0, 2);
            ss1 += __shfl_xor_sync(0xffffffffu, ss1, 1);
            ss1 += __shfl_xor_sync(0xffffffffu, ss1, 2);
            float i0 = 1.0f / fmaxf(sqrtf(ss0), 1e-12f);
            float i1 = 1.0f / fmaxf(sqrtf(ss1), 1e-12f);
#pragma unroll
            for (int nt = 0; nt < 4; nt++) {
                v0x[nt] *= i0; v0y[nt] *= i0;
                v1x[nt] *= i1; v1y[nt] *= i1;
            }
        }
#pragma unroll
        for (int nt = 0; nt < 4; nt++) {
            const int n = n0 + wn * 32 + nt * 8 + tr * 2;
            size_t a0, a1;
            if (remap) {
                const int hh = n >> 5, hd = n & 31;
                int bbw = m / Ls, l = m - bbw * Ls;
                a0 = ((size_t)(bbw * Hs + hh) * Ls + l) * HDs + hd;
                int m2 = m + 8;
                int bbw2 = m2 / Ls, l2 = m2 - bbw2 * Ls;
                a1 = ((size_t)(bbw2 * Hs + hh) * Ls + l2) * HDs + hd;
            } else {
                a0 = (size_t)m * Es + n;
                a1 = (size_t)(m + 8) * Es + n;
            }
            if (Oh) {
                *(uint32_t*)(Oh + a0) = packh(v0x[nt], v0y[nt]);
                *(uint32_t*)(Oh + a1) = packh(v1x[nt], v1y[nt]);
            } else {
                *(float2*)(C + a0) = make_float2(v0x[nt], v0y[nt]);
                *(float2*)(C + a1) = make_float2(v1x[nt], v1y[nt]);
            }
        }
    }
}

// Launch 3: Q/K/V projections (z=0..2) + bias gather (z=3)
__global__ __launch_bounds__(256, 2) void qkv_gemm_kernel(
    const float* __restrict__ bq, const float* __restrict__ bk,
    const float* __restrict__ indices)
{
    extern __shared__ char dsm[];
    const int z = blockIdx.z;
    if (z == 3) {
        int p = (blockIdx.y * gridDim.x + blockIdx.x) * 256 + threadIdx.x;
        if (p >= LLs) return;
        int i = p / Ls, j = p - i * Ls;
        int q0 = __float2int_rn(indices[p * 3 + 0]) + 6;
        int q1 = __float2int_rn(indices[p * 3 + 1]) + 6;
        int q2 = __float2int_rn(indices[p * 3 + 2]) + 6;
        int cls = q0 + 13 * q1 + 169 * q2;
        float4 v0 = *(const float4*)(g_blut + cls * 8);
        float4 v1 = *(const float4*)(g_blut + cls * 8 + 4);
        float vals[8] = { v0.x, v0.y, v0.z, v0.w, v1.x, v1.y, v1.z, v1.w };
#pragma unroll
        for (int h = 0; h < 8; h++)
            g_bias[(size_t)h * (Ls * LPAD) + i * LPAD + j] = vals[h];
        return;
    }
    const __half* A  = (z == 0) ? g_xq : (z == 1) ? g_xk : g_xv;
    const __half* W  = g_w4 + (size_t)z * Es * Es;
    const float* bias = (z == 0) ? bq : (z == 1) ? bk : nullptr;
    __half* Oh = (z == 0) ? g_qh : (z == 1) ? g_kh : g_vh;
    tgemm_body(dsm, A, W, bias, nullptr, 1, Oh, z < 2);
}

// Launch 5: output projection -> fp32 d_out
__global__ __launch_bounds__(256, 2) void out_gemm_kernel(
    const float* __restrict__ bw, float* __restrict__ out)
{
    extern __shared__ char dsm[];
    tgemm_body(dsm, g_a, g_w4 + 3 * (size_t)Es * Es, bw, out, 0, nullptr, 0);
}

// ============================================================
// Launch 4 (PROFILED): persistent fp16 attention per (head, window).
// 256 threads / 8 warps; 110.6 KB SMEM -> 2 CTAs/SM.
// 11 q-tiles of 32 rows; warp grid 2m x 4n (96-key quarters).
// ============================================================
#define ASTR 40
#define ABUF 30720
#define OFF_QH (0 * ABUF)
#define OFF_KH (1 * ABUF)
#define OFF_VH (2 * ABUF)
#define OFF_RMAX (3 * ABUF)            // 92160; [4][32] float
#define OFF_RSUM (OFF_RMAX + 512)
#define OFF_ORED (OFF_RSUM + 512)      // [4][32][ORSTR] float
#define ORSTR 34
#define ATT3_SMEM (OFF_ORED + 4 * 32 * ORSTR * 4)   // 110592

__global__ __launch_bounds__(256, 2) void attn3_kernel(const float* __restrict__ scalep)
{
    extern __shared__ char sm2[];
    float* redmax = (float*)(sm2 + OFF_RMAX);
    float* redsum = (float*)(sm2 + OFF_RSUM);
    float* ored   = (float*)(sm2 + OFF_ORED);
    const uint32_t smb = smem_u32(sm2);

    const int tid = threadIdx.x;
    const int wid = tid >> 5;
    const int lane = tid & 31;
    const int h = blockIdx.x;
    const int bb = blockIdx.y;
    const size_t gbase = (size_t)(bb * Hs + h) * (Ls * HDs);

    // ---- fill Q,K,V once ----
    {
        const __half* gsrc[3] = { g_qh + gbase, g_kh + gbase, g_vh + gbase };
#pragma unroll
        for (int arr = 0; arr < 3; arr++)
            for (int i = tid; i < 1372; i += 256) {
                int row = i >> 2, ch = i & 3;
                cp_async16(smb + arr * ABUF + row * 80 + ch * 16,
                           gsrc[arr] + row * HDs + ch * 8);
            }
        for (int i = tid; i < 492; i += 256) {
            int arr = i / 164, j = i - arr * 164;
            int r = 343 + (j >> 2), ch = j & 3;
            *(uint4*)(sm2 + arr * ABUF + r * 80 + ch * 16) = make_uint4(0, 0, 0, 0);
        }
        cp_commit();
        cp_wait0();
        __syncthreads();
    }

    const int wm = wid & 1;
    const int wn = wid >> 1;
    const int nbase = wn * 96;

    const int arow = (lane & 7) + ((lane >> 3) & 1) * 8;
    const int acolo = ((lane >> 4) & 1) * 8;
    const int brow = (lane & 7) + ((lane >> 4) & 1) * 8;
    const int bcolo = ((lane >> 3) & 1) * 8;

    const float invscale = 1.0f / fmaxf(scalep[0], 0.01f);
    const float* bias0 = g_bias + (size_t)h * (Ls * LPAD);
    const uint32_t* mrowb = g_maskb + (size_t)bb * (344 * MW) + wn * 3;
    const int r0 = wm * 16 + (lane >> 2);
    const int r1 = r0 + 8;
    const int ncol = (lane & 3) * 2;
    const int lane16 = lane & 15;
    const int halfr = lane >> 4;

    for (int qt = 0; qt < 11; qt++) {
        const int q0 = qt * 32;
        const int qrow0 = q0 + r0, qrow1 = q0 + r1;
        const bool rv0 = qrow0 < Ls, rv1 = qrow1 < Ls;

        // ---- mask words (3 per row for this 96-col quarter) ----
        uint32_t mw0[3] = {0, 0, 0}, mw1[3] = {0, 0, 0};
        if (rv0) {
            const uint32_t* p = mrowb + (size_t)qrow0 * MW;
            mw0[0] = p[0]; mw0[1] = p[1]; mw0[2] = p[2];
        }
        if (rv1) {
            const uint32_t* p = mrowb + (size_t)qrow1 * MW;
            mw1[0] = p[0]; mw1[1] = p[1]; mw1[2] = p[2];
        }

        // ---- Q fragments ----
        uint32_t qh[2][4];
#pragma unroll
        for (int kk = 0; kk < 2; kk++) {
            uint32_t ro = (uint32_t)((q0 + wm * 16 + arow) * ASTR + kk * 16 + acolo) * 2;
            ldsm_x4(qh[kk][0], qh[kk][1], qh[kk][2], qh[kk][3], smb + OFF_QH + ro);
        }

        // ---- fused phase 1 ----
        float c[12][4];
        float mx0 = -FLT_MAX, mx1 = -FLT_MAX;
#pragma unroll
        for (int g = 0; g < 6; g++) {
            float2 bT[2][2];
#pragma unroll
            for (int nt = 0; nt < 2; nt++) {
                int col = nbase + g * 16 + nt * 8 + ncol;
                bool cv = col < Ls;
                bT[nt][0] = make_float2(0.f, 0.f); bT[nt][1] = make_float2(0.f, 0.f);
                if (rv0 && cv)
                    bT[nt][0] = *(const float2*)(bias0 + (size_t)qrow0 * LPAD + col);
                if (rv1 && cv)
                    bT[nt][1] = *(const float2*)(bias0 + (size_t)qrow1 * LPAD + col);
            }

            uint32_t bh[2][4];
#pragma unroll
            for (int kk = 0; kk < 2; kk++) {
                uint32_t rb = (uint32_t)((nbase + g * 16 + brow) * ASTR + kk * 16 + bcolo) * 2;
                ldsm_x4(bh[kk][0], bh[kk][1], bh[kk][2], bh[kk][3], smb + OFF_KH + rb);
            }
            float cg[2][4];
#pragma unroll
            for (int nt = 0; nt < 2; nt++)
#pragma unroll
                for (int e = 0; e < 4; e++) cg[nt][e] = 0.0f;
#pragma unroll
            for (int kk = 0; kk < 2; kk++)
#pragma unroll
                for (int nt = 0; nt < 2; nt++)
                    mma16816(cg[nt], qh[kk], bh[kk][nt * 2], bh[kk][nt * 2 + 1]);
#pragma unroll
            for (int nt = 0; nt < 2; nt++) {
                const int t = g * 2 + nt;
                const int base = g * 16 + nt * 8;
                const int wI = base >> 5;
                int col = nbase + base + ncol;
                bool cv0 = col < Ls, cv1 = (col + 1) < Ls;
                uint32_t mb0 = (mw0[wI] >> ((base & 31) + ncol)) & 3u;
                uint32_t mb1 = (mw1[wI] >> ((base & 31) + ncol)) & 3u;
                c[t][0] = (rv0 && cv0) ? ((mb0 & 1u) ? -100000.0f
                          : fmaf(cg[nt][0], invscale, bT[nt][0].x)) : -1e9f;
                c[t][1] = (rv0 && cv1) ? ((mb0 & 2u) ? -100000.0f
                          : fmaf(cg[nt][1], invscale, bT[nt][0].y)) : -1e9f;
                c[t][2] = (rv1 && cv0) ? ((mb1 & 1u) ? -100000.0f
                          : fmaf(cg[nt][2], invscale, bT[nt][1].x)) : -1e9f;
                c[t][3] = (rv1 && cv1) ? ((mb1 & 2u) ? -100000.0f
                          : fmaf(cg[nt][3], invscale, bT[nt][1].y)) : -1e9f;
                mx0 = fmaxf(mx0, fmaxf(c[t][0], c[t][1]));
                mx1 = fmaxf(mx1, fmaxf(c[t][2], c[t][3]));
            }
        }

        // ---- single-sync softmax; normalization deferred to post-PV ----
        mx0 = fmaxf(mx0, __shfl_xor_sync(0xffffffffu, mx0, 1));
        mx0 = fmaxf(mx0, __shfl_xor_sync(0xffffffffu, mx0, 2));
        mx1 = fmaxf(mx1, __shfl_xor_sync(0xffffffffu, mx1, 1));
        mx1 = fmaxf(mx1, __shfl_xor_sync(0xffffffffu, mx1, 2));

        float s0 = 0.0f, s1 = 0.0f;
#pragma unroll
        for (int t = 0; t < 12; t++) {
            float e0 = fexp(c[t][0] - mx0); c[t][0] = e0; s0 += e0;
            float e1 = fexp(c[t][1] - mx0); c[t][1] = e1; s0 += e1;
            float e2 = fexp(c[t][2] - mx1); c[t][2] = e2; s1 += e2;
            float e3 = fexp(c[t][3] - mx1); c[t][3] = e3; s1 += e3;
        }
        s0 += __shfl_xor_sync(0xffffffffu, s0, 1);
        s0 += __shfl_xor_sync(0xffffffffu, s0, 2);
        s1 += __shfl_xor_sync(0xffffffffu, s1, 1);
        s1 += __shfl_xor_sync(0xffffffffu, s1, 2);
        if ((lane & 3) == 0) {
            redmax[wn * 32 + r0] = mx0; redsum[wn * 32 + r0] = s0;
            redmax[wn * 32 + r1] = mx1; redsum[wn * 32 + r1] = s1;
        }
        __syncthreads();
        float f0, f1;
        {
            float gm0 = -FLT_MAX, gm1 = -FLT_MAX;
#pragma unroll
            for (int qd = 0; qd < 4; qd++) {
                gm0 = fmaxf(gm0, redmax[qd * 32 + r0]);
                gm1 = fmaxf(gm1, redmax[qd * 32 + r1]);
            }
            float S0 = 0.0f, S1 = 0.0f;
#pragma unroll
            for (int qd = 0; qd < 4; qd++) {
                S0 += redsum[qd * 32 + r0] * fexp(redmax[qd * 32 + r0] - gm0);
                S1 += redsum[qd * 32 + r1] * fexp(redmax[qd * 32 + r1] - gm1);
            }
            f0 = fexp(mx0 - gm0) / S0;
            f1 = fexp(mx1 - gm1) / S1;
        }

        // ---- phase 3: O = P * V, then scale by f ----
        float oc[4][4];
#pragma unroll
        for (int nt = 0; nt < 4; nt++)
#pragma unroll
            for (int e = 0; e < 4; e++) oc[nt][e] = 0.0f;

#pragma unroll
        for (int kt = 0; kt < 6; kt++) {
            uint32_t ph[4];
#pragma unroll
            for (int half = 0; half < 2; half++) {
                const float* cc = c[2 * kt + half];
                ph[half * 2 + 0] = packh(cc[0], cc[1]);
                ph[half * 2 + 1] = packh(cc[2], cc[3]);
            }
            const int krow = nbase + kt * 16;
            uint32_t vh[2][4];
#pragma unroll
            for (int g = 0; g < 2; g++) {
                uint32_t ad = (uint32_t)((krow + arow) * ASTR + g * 16 + acolo) * 2;
                ldsm_x4_t(vh[g][0], vh[g][1], vh[g][2], vh[g][3], smb + OFF_VH + ad);
            }
#pragma unroll
            for (int nt = 0; nt < 4; nt++) {
                const int g = nt >> 1, i2 = (nt & 1) * 2;
                mma16816(oc[nt], ph, vh[g][i2], vh[g][i2 + 1]);
            }
        }
#pragma unroll
        for (int nt = 0; nt < 4; nt++) {
            oc[nt][0] *= f0; oc[nt][1] *= f0;
            oc[nt][2] *= f1; oc[nt][3] *= f1;
        }

        // ---- 4 slabs + distributed reduce + fp16 store ----
        {
            float* dst = ored + (size_t)wn * (32 * ORSTR);
#pragma unroll
            for (int nt = 0; nt < 4; nt++) {
                *(float2*)(dst + r0 * ORSTR + nt * 8 + ncol) = make_float2(oc[nt][0], oc[nt][1]);
                *(float2*)(dst + r1 * ORSTR + nt * 8 + ncol) = make_float2(oc[nt][2], oc[nt][3]);
            }
        }
        __syncthreads();
#pragma unroll
        for (int p = 0; p < 2; p++) {
            int row = wid * 4 + p * 2 + halfr;     // 0..31
            int qrow = q0 + row;
            if (qrow < Ls) {
                int col = lane16 * 2;
                float s0o = 0.0f, s1o = 0.0f;
#pragma unroll
                for (int qd = 0; qd < 4; qd++) {
                    float2 v = *(float2*)(ored + qd * (32 * ORSTR) + row * ORSTR + col);
                    s0o += v.x; s1o += v.y;
                }
                size_t ad = (size_t)(bb * Ls + qrow) * Es + h * HDs + col;
                *(uint32_t*)(g_a + ad) = packh(s0o, s1o);
            }
        }
        __syncthreads();   // ored reused next q-tile
    }
}

// ============================================================
// launch
// ============================================================
extern "C" void kernel_launch(void* const* d_in, const int* in_sizes, int n_in,
                              void* d_out, int out_size)
{
    (void)in_sizes; (void)n_in; (void)out_size;
    const float* query   = (const float*)d_in[0];
    const float* key     = (const float*)d_in[1];
    const float* value   = (const float*)d_in[2];
    const float* indices = (const float*)d_in[3];
    const void*  mask    = d_in[4];
    const float* Wq      = (const float*)d_in[5];
    const float* bq      = (const float*)d_in[6];
    const float* Wk      = (const float*)d_in[7];
    const float* bk      = (const float*)d_in[8];
    const float* Wv      = (const float*)d_in[9];
    const float* Ww      = (const float*)d_in[10];
    const float* bw      = (const float*)d_in[11];
    const float* scale   = (const float*)d_in[12];
    const float* W1      = (const float*)d_in[13];
    const float* b1      = (const float*)d_in[14];
    const float* W2      = (const float*)d_in[15];
    const float* b2      = (const float*)d_in[16];
    float* out = (float*)d_out;

    cudaFuncSetAttribute(qkv_gemm_kernel, cudaFuncAttributeMaxDynamicSharedMemorySize,
                         TG_SMEM);
    cudaFuncSetAttribute(out_gemm_kernel, cudaFuncAttributeMaxDynamicSharedMemorySize,
                         TG_SMEM);
    cudaFuncSetAttribute(attn3_kernel, cudaFuncAttributeMaxDynamicSharedMemorySize,
                         ATT3_SMEM);

    const int n4 = ROWSs * Es / 4;
    const int splitg = (n4 + 255) / 256;
    const int lutg = (NCLS + 7) / 8;

    // L1: input rounding + weight transposes
    prep_kernel<<<dim3(splitg, 4), 256>>>((const float4*)query, (const float4*)key,
                                          (const float4*)value, n4, Wq, Wk, Wv, Ww);
    // L2: mask bit-pack (self-detect) + CPB LUT
    mask_lut_kernel<<<MASKG + lutg, 256>>>(mask, W1, b1, W2, b2);
    // L3: Q/K/V projections + bias gather
    qkv_gemm_kernel<<<dim3(ROWSs / 128, Es / 128, 4), 256, TG_SMEM>>>(bq, bk, indices);
    // L4: attention  (ncu-captured slot)
    attn3_kernel<<<dim3(Hs, BBs), 256, ATT3_SMEM>>>(scale);
    // L5: output projection
    out_gemm_kernel<<<dim3(ROWSs / 128, Es / 128), 256, TG_SMEM>>>(bw, out);
}